// round 4
// baseline (speedup 1.0000x reference)
#include <cuda_runtime.h>
#include <math.h>
#include <stdint.h>

// ---------------- problem constants ----------------
#define BATCH   32768
#define KCODES  4096
#define DLAT    64
#define HIDDEN  1024

// output layout (f32, reference return order, flattened+concat)
#define P_OFF    0
#define P_SIZE   (BATCH*40)
#define CP_OFF   (P_OFF + P_SIZE)
#define CP_SIZE  (BATCH*48)
#define W_OFF    (CP_OFF + CP_SIZE)
#define WA_SIZE  (BATCH*2)
#define A_OFF    (W_OFF + WA_SIZE)
#define LOSS_OFF (A_OFF + WA_SIZE)
#define IDX_OFF  (LOSS_OFF + 1)
#define PERP_OFF (IDX_OFF + BATCH)

#define SPAD 4

// ---------------- scratch (__device__ globals; no allocation allowed) ----------------
__device__ float2 g_x2 [BATCH*784];      // split x
__device__ float2 g_W12[784*256];
__device__ float2 g_W22[256*256];
__device__ float2 g_emb2[KCODES*DLAT];
__device__ float2 g_h12[BATCH*256];      // split h1
__device__ float  g_h2 [BATCH*256];
__device__ float  g_z  [BATCH*DLAT];
__device__ float2 g_z2 [BATCH*DLAT];
__device__ float  g_zq [BATCH*DLAT];
__device__ float  g_d1 [BATCH*HIDDEN];
__device__ float  g_d2 [BATCH*HIDDEN];
__device__ float  g_ho [BATCH*128];      // head out, stride 128
__device__ int    g_idx[BATCH];
__device__ float  g_counts[KCODES];
__device__ float  g_loss;
__device__ float  g_enorm[KCODES];
__device__ float  g_hw [HIDDEN*128];     // padded head weights
__device__ float  g_hb [128];

// ---------------- activations ----------------
#define ACT_NONE 0
#define ACT_LEAKY 1
#define ACT_SELU 2
#define ACT_HEAD 3

__device__ __forceinline__ float sigmoidf_(float x){ return 1.0f/(1.0f+expf(-x)); }

template<int ACT>
__device__ __forceinline__ float apply_act(float v, int col){
    if (ACT == ACT_LEAKY) return v > 0.0f ? v : 0.2f*v;
    if (ACT == ACT_SELU){
        const float a = 1.6732632423543772f, s = 1.0507009873554805f;
        return v > 0.0f ? s*v : s*a*(expf(v)-1.0f);
    }
    if (ACT == ACT_HEAD){
        if (col < 40) return tanhf(v)*12.0f + 14.0f;
        if (col < 42) return sigmoidf_(v)*2.0f + 1.0f;
        return sigmoidf_(v);
    }
    return v;
}

// ---------------- TF32 split helpers ----------------
__device__ __forceinline__ uint32_t tf32_of(float x){
    uint32_t r; asm("cvt.rna.tf32.f32 %0, %1;" : "=r"(r) : "f"(x)); return r;
}
__device__ __forceinline__ float2 split2(float x){
    uint32_t h = tf32_of(x);
    float hf = __uint_as_float(h);
    float lof = __uint_as_float(tf32_of(x - hf));
    return make_float2(hf, lof);
}

// D += A*B, m16n8k8 tf32
__device__ __forceinline__ void mma8(float* c, const uint32_t* a, const uint32_t* b){
    asm volatile(
        "mma.sync.aligned.m16n8k8.row.col.f32.tf32.tf32.f32 "
        "{%0,%1,%2,%3}, {%4,%5,%6,%7}, {%8,%9}, {%0,%1,%2,%3};\n"
        : "+f"(c[0]), "+f"(c[1]), "+f"(c[2]), "+f"(c[3])
        : "r"(a[0]), "r"(a[1]), "r"(a[2]), "r"(a[3]), "r"(b[0]), "r"(b[1]));
}

// ---------------- cp.async helpers ----------------
__device__ __forceinline__ void cpasync16(void* dst_smem, const void* src){
    uint32_t s = (uint32_t)__cvta_generic_to_shared(dst_smem);
    asm volatile("cp.async.cg.shared.global [%0], [%1], 16;\n" :: "r"(s), "l"(src));
}
__device__ __forceinline__ void cpasync_commit(){ asm volatile("cp.async.commit_group;\n"); }
template<int NN>
__device__ __forceinline__ void cpasync_wait(){ asm volatile("cp.async.wait_group %0;\n" :: "n"(NN)); }

// ---------------- elementwise split: float -> (tf32 hi, tf32 lo) ----------------
__global__ void split_arr(const float* __restrict__ src, float2* __restrict__ dst, int n4){
    int i = blockIdx.x * 256 + threadIdx.x;
    if (i >= n4) return;
    float4 v = ((const float4*)src)[i];
    float2 s0 = split2(v.x), s1 = split2(v.y), s2 = split2(v.z), s3 = split2(v.w);
    float4* d = (float4*)(dst + (size_t)i*4);
    d[0] = make_float4(s0.x, s0.y, s1.x, s1.y);
    d[1] = make_float4(s2.x, s2.y, s3.x, s3.y);
}

// ============================================================================
// split-3x GEMM on PRE-SPLIT inputs (encoder): C = act(A2[M,K] @ B2[K,N] + bias)
// 128x128 tile, BK=16, 8 warps (2Mx4N), warp tile 64x32.
// OUT_MODE: 0 = plain C, 1 = split C2 (for chaining to next split GEMM)
// ============================================================================
template<int ACT, int OUT_MODE>
__global__ void __launch_bounds__(256, 2) mma_gemm_pre(
    const float2* __restrict__ A2, const float2* __restrict__ B2,
    const float* __restrict__ bias, float* __restrict__ C, float2* __restrict__ C2,
    int M, int N, int K)
{
    __shared__ float2 As[16][128+SPAD];   // [k][m] = (hi, lo)
    __shared__ float2 Bs[16][128+SPAD];   // [k][n] = (hi, lo)

    const int tid  = threadIdx.x;
    const int lane = tid & 31, warp = tid >> 5;
    const int wm = (warp & 1) * 64, wn = (warp >> 1) * 32;
    const int bm = blockIdx.y * 128, bn = blockIdx.x * 128;
    const int g = lane >> 2, tg = lane & 3;

    float acc[4][4][4];
    #pragma unroll
    for (int i = 0; i < 4; i++)
        #pragma unroll
        for (int j = 0; j < 4; j++)
            #pragma unroll
            for (int q = 0; q < 4; q++) acc[i][j][q] = 0.0f;

    const int ar = tid >> 1, ac = (tid & 1) * 8;
    const int br = tid >> 4, bc = (tid & 15) * 4;
    const float2* Ap = A2 + (size_t)(bm + ar) * K + ac;
    const float2* Bp = B2 + (size_t)br * N + bn + bc;

    for (int k0 = 0; k0 < K; k0 += 16){
        {
            const float4* ap = (const float4*)(Ap + k0);   // 8 float2 = 4 float4
            #pragma unroll
            for (int q = 0; q < 4; q++){
                float4 v = ap[q];
                As[ac+q*2+0][ar] = make_float2(v.x, v.y);
                As[ac+q*2+1][ar] = make_float2(v.z, v.w);
            }
            const float4* bp0 = (const float4*)(Bp + (size_t)k0 * N);
            const float4* bp1 = (const float4*)(Bp + (size_t)k0 * N + 64);
            #pragma unroll
            for (int q = 0; q < 2; q++){
                float4 v = bp0[q];
                Bs[br][bc+q*2+0] = make_float2(v.x, v.y);
                Bs[br][bc+q*2+1] = make_float2(v.z, v.w);
                float4 w = bp1[q];
                Bs[br][bc+64+q*2+0] = make_float2(w.x, w.y);
                Bs[br][bc+64+q*2+1] = make_float2(w.z, w.w);
            }
        }
        __syncthreads();

        #pragma unroll
        for (int ks = 0; ks < 16; ks += 8){
            uint32_t ah[4][4], al[4][4];
            #pragma unroll
            for (int mt = 0; mt < 4; mt++){
                int m = wm + mt*16 + g;
                float2 v0 = As[ks+tg][m];
                float2 v1 = As[ks+tg][m+8];
                float2 v2 = As[ks+4+tg][m];
                float2 v3 = As[ks+4+tg][m+8];
                ah[mt][0] = __float_as_uint(v0.x);
                ah[mt][1] = __float_as_uint(v1.x);
                ah[mt][2] = __float_as_uint(v2.x);
                ah[mt][3] = __float_as_uint(v3.x);
                al[mt][0] = __float_as_uint(v0.y);
                al[mt][1] = __float_as_uint(v1.y);
                al[mt][2] = __float_as_uint(v2.y);
                al[mt][3] = __float_as_uint(v3.y);
            }
            #pragma unroll
            for (int nt = 0; nt < 4; nt++){
                int n = wn + nt*8 + g;
                float2 w0 = Bs[ks+tg][n];
                float2 w1 = Bs[ks+4+tg][n];
                uint32_t bh[2] = { __float_as_uint(w0.x), __float_as_uint(w1.x) };
                uint32_t bl[2] = { __float_as_uint(w0.y), __float_as_uint(w1.y) };
                #pragma unroll
                for (int mt = 0; mt < 4; mt++) mma8(acc[mt][nt], ah[mt], bh);
                #pragma unroll
                for (int mt = 0; mt < 4; mt++) mma8(acc[mt][nt], al[mt], bh);
                #pragma unroll
                for (int mt = 0; mt < 4; mt++) mma8(acc[mt][nt], ah[mt], bl);
            }
        }
        __syncthreads();
    }

    // epilogue
    #pragma unroll
    for (int mt = 0; mt < 4; mt++){
        #pragma unroll
        for (int nt = 0; nt < 4; nt++){
            int row = bm + wm + mt*16 + g;
            int col = bn + wn + nt*8 + 2*tg;
            float bs0 = bias[col], bs1 = bias[col+1];
            float v00 = apply_act<ACT>(acc[mt][nt][0] + bs0, col);
            float v01 = apply_act<ACT>(acc[mt][nt][1] + bs1, col+1);
            float v10 = apply_act<ACT>(acc[mt][nt][2] + bs0, col);
            float v11 = apply_act<ACT>(acc[mt][nt][3] + bs1, col+1);
            if (OUT_MODE == 0){
                *(float2*)&C[(size_t)row*N + col]     = make_float2(v00, v01);
                *(float2*)&C[(size_t)(row+8)*N + col] = make_float2(v10, v11);
            } else {
                float2 s00 = split2(v00), s01 = split2(v01);
                float2 s10 = split2(v10), s11 = split2(v11);
                *(float4*)&C2[(size_t)row*N + col]     = make_float4(s00.x, s00.y, s01.x, s01.y);
                *(float4*)&C2[(size_t)(row+8)*N + col] = make_float4(s10.x, s10.y, s11.x, s11.y);
            }
        }
    }
}

// ============================================================================
// 1x-TF32 WIDE GEMM (decoder): 128x256 block tile, warp tile 64x64,
// 3-stage cp.async, 1 CTA/SM.
// ============================================================================
#define WAST 20
#define WBST 264
#define WA_ELEMS (3*128*WAST)
template<int ACT>
__global__ void __launch_bounds__(256, 1) mma_1x_wide(
    const float* __restrict__ A, const float* __restrict__ W,
    const float* __restrict__ bias, float* __restrict__ C,
    int M, int N, int K)
{
    extern __shared__ float dsm[];
    float* Asp = dsm;                 // [3][128][WAST]
    float* Bsp = dsm + WA_ELEMS;      // [3][16][WBST]
    #define AS(s,m,k) Asp[(s)*128*WAST + (m)*WAST + (k)]
    #define BS(s,k,n) Bsp[(s)*16*WBST + (k)*WBST + (n)]

    const int tid  = threadIdx.x;
    const int lane = tid & 31, warp = tid >> 5;
    const int wm = (warp & 1) * 64, wn = (warp >> 1) * 64;
    const int bm = blockIdx.y * 128, bn = blockIdx.x * 256;
    const int g = lane >> 2, tg = lane & 3;

    float acc[4][8][4];
    #pragma unroll
    for (int i = 0; i < 4; i++)
        #pragma unroll
        for (int j = 0; j < 8; j++)
            #pragma unroll
            for (int q = 0; q < 4; q++) acc[i][j][q] = 0.0f;

    const int ar = tid >> 1, ac = (tid & 1) * 8;
    const int br = tid >> 4, bc = (tid & 15) * 16;
    const float* Ap = A + (size_t)(bm + ar) * K + ac;
    const float* Bp = W + (size_t)br * N + bn + bc;

    const int ntiles = K >> 4;

    #define WCOPY(kt, s) do { \
        const float* ap_ = Ap + (size_t)(kt) * 16; \
        cpasync16(&AS(s, ar, ac),   ap_); \
        cpasync16(&AS(s, ar, ac+4), ap_ + 4); \
        const float* bp_ = Bp + (size_t)(kt) * 16 * N; \
        cpasync16(&BS(s, br, bc),    bp_); \
        cpasync16(&BS(s, br, bc+4),  bp_ + 4); \
        cpasync16(&BS(s, br, bc+8),  bp_ + 8); \
        cpasync16(&BS(s, br, bc+12), bp_ + 12); \
        cpasync_commit(); \
    } while (0)

    WCOPY(0, 0);
    if (ntiles > 1) WCOPY(1, 1);

    for (int i = 0; i < ntiles; i++){
        if (i + 1 < ntiles) cpasync_wait<1>(); else cpasync_wait<0>();
        __syncthreads();
        int s = i % 3;
        if (i + 2 < ntiles) WCOPY(i + 2, (i + 2) % 3);

        #pragma unroll
        for (int ks = 0; ks < 16; ks += 8){
            uint32_t a[4][4];
            #pragma unroll
            for (int mt = 0; mt < 4; mt++){
                int m = wm + mt*16 + g;
                a[mt][0] = __float_as_uint(AS(s, m,   ks+tg));
                a[mt][1] = __float_as_uint(AS(s, m+8, ks+tg));
                a[mt][2] = __float_as_uint(AS(s, m,   ks+tg+4));
                a[mt][3] = __float_as_uint(AS(s, m+8, ks+tg+4));
            }
            uint32_t b[8][2];
            #pragma unroll
            for (int nt = 0; nt < 8; nt++){
                int n = wn + nt*8 + g;
                b[nt][0] = __float_as_uint(BS(s, ks+tg,   n));
                b[nt][1] = __float_as_uint(BS(s, ks+tg+4, n));
            }
            #pragma unroll
            for (int nt = 0; nt < 8; nt++)
                #pragma unroll
                for (int mt = 0; mt < 4; mt++)
                    mma8(acc[mt][nt], a[mt], b[nt]);
        }
    }
    #undef WCOPY
    #undef AS
    #undef BS

    // epilogue
    #pragma unroll
    for (int mt = 0; mt < 4; mt++){
        #pragma unroll
        for (int nt = 0; nt < 8; nt++){
            int row = bm + wm + mt*16 + g;
            int col = bn + wn + nt*8 + 2*tg;
            float bs0 = bias[col], bs1 = bias[col+1];
            float2 o0, o1;
            o0.x = apply_act<ACT>(acc[mt][nt][0] + bs0, col);
            o0.y = apply_act<ACT>(acc[mt][nt][1] + bs1, col+1);
            o1.x = apply_act<ACT>(acc[mt][nt][2] + bs0, col);
            o1.y = apply_act<ACT>(acc[mt][nt][3] + bs1, col+1);
            *(float2*)&C[(size_t)row*N + col]     = o0;
            *(float2*)&C[(size_t)(row+8)*N + col] = o1;
        }
    }
}

// ============================================================================
// 1x-TF32 GEMM 128x128 (head, N=128 padded): proven R3 kernel
// ============================================================================
#define AST 20
#define BST 136
template<int ACT>
__global__ void __launch_bounds__(256, 2) mma_gemm_1x(
    const float* __restrict__ A, const float* __restrict__ W,
    const float* __restrict__ bias, float* __restrict__ C,
    int M, int N, int K)
{
    __shared__ float As[2][128][AST];
    __shared__ float Bs[2][16][BST];

    const int tid  = threadIdx.x;
    const int lane = tid & 31, warp = tid >> 5;
    const int wm = (warp & 1) * 64, wn = (warp >> 1) * 32;
    const int bm = blockIdx.y * 128, bn = blockIdx.x * 128;
    const int g = lane >> 2, tg = lane & 3;

    float acc[4][4][4];
    #pragma unroll
    for (int i = 0; i < 4; i++)
        #pragma unroll
        for (int j = 0; j < 4; j++)
            #pragma unroll
            for (int q = 0; q < 4; q++) acc[i][j][q] = 0.0f;

    const int ar = tid >> 1, ac = (tid & 1) * 8;
    const int br = tid >> 4, bc = (tid & 15) * 8;
    const float* Ap = A + (size_t)(bm + ar) * K + ac;
    const float* Bp = W + (size_t)br * N + bn + bc;

    const int ntiles = K >> 4;

    #define COPY_TILE(kt, buf) do { \
        const float* ap = Ap + (size_t)(kt) * 16; \
        cpasync16(&As[buf][ar][ac],   ap); \
        cpasync16(&As[buf][ar][ac+4], ap + 4); \
        const float* bp = Bp + (size_t)(kt) * 16 * N; \
        cpasync16(&Bs[buf][br][bc],   bp); \
        cpasync16(&Bs[buf][br][bc+4], bp + 4); \
        cpasync_commit(); \
    } while (0)

    COPY_TILE(0, 0);

    for (int i = 0; i < ntiles; i++){
        int buf = i & 1;
        if (i + 1 < ntiles){
            COPY_TILE(i + 1, buf ^ 1);
            cpasync_wait<1>();
        } else {
            cpasync_wait<0>();
        }
        __syncthreads();

        #pragma unroll
        for (int ks = 0; ks < 16; ks += 8){
            uint32_t a[4][4];
            #pragma unroll
            for (int mt = 0; mt < 4; mt++){
                int m = wm + mt*16 + g;
                a[mt][0] = __float_as_uint(As[buf][m  ][ks+tg]);
                a[mt][1] = __float_as_uint(As[buf][m+8][ks+tg]);
                a[mt][2] = __float_as_uint(As[buf][m  ][ks+tg+4]);
                a[mt][3] = __float_as_uint(As[buf][m+8][ks+tg+4]);
            }
            #pragma unroll
            for (int nt = 0; nt < 4; nt++){
                int n = wn + nt*8 + g;
                uint32_t b[2] = { __float_as_uint(Bs[buf][ks+tg  ][n]),
                                  __float_as_uint(Bs[buf][ks+tg+4][n]) };
                #pragma unroll
                for (int mt = 0; mt < 4; mt++) mma8(acc[mt][nt], a[mt], b);
            }
        }
        __syncthreads();
    }
    #undef COPY_TILE

    #pragma unroll
    for (int mt = 0; mt < 4; mt++){
        #pragma unroll
        for (int nt = 0; nt < 4; nt++){
            int row = bm + wm + mt*16 + g;
            int col = bn + wn + nt*8 + 2*tg;
            float bs0 = bias[col], bs1 = bias[col+1];
            float2 o0, o1;
            o0.x = apply_act<ACT>(acc[mt][nt][0] + bs0, col);
            o0.y = apply_act<ACT>(acc[mt][nt][1] + bs1, col+1);
            o1.x = apply_act<ACT>(acc[mt][nt][2] + bs0, col);
            o1.y = apply_act<ACT>(acc[mt][nt][3] + bs1, col+1);
            *(float2*)&C[(size_t)row*N + col]     = o0;
            *(float2*)&C[(size_t)(row+8)*N + col] = o1;
        }
    }
}

// ---------------- small-N SGEMM (z projection): fp32, writes z and split z2 ----------------
template<int ACT>
__global__ void __launch_bounds__(256) sgemm_smallN(
    const float* __restrict__ A, const float* __restrict__ W,
    const float* __restrict__ bias, float* __restrict__ C, float2* __restrict__ C2,
    int M, int N, int K)
{
    __shared__ float As[16][64];
    __shared__ float Bs[16][64];
    const int tid = threadIdx.x;
    const int bm = blockIdx.x * 64;
    const int arow = tid >> 2,  acol = (tid & 3) * 4;
    const int bkr  = tid >> 4,  bcol = (tid & 15) * 4;
    const int ty = tid >> 4, tx = tid & 15;

    float acc[4][4];
    #pragma unroll
    for (int i = 0; i < 4; i++)
        #pragma unroll
        for (int j = 0; j < 4; j++) acc[i][j] = 0.0f;

    for (int k0 = 0; k0 < K; k0 += 16){
        float4 av = *(const float4*)(A + (size_t)(bm + arow) * K + k0 + acol);
        As[acol+0][arow] = av.x;
        As[acol+1][arow] = av.y;
        As[acol+2][arow] = av.z;
        As[acol+3][arow] = av.w;
        float4 bv = make_float4(0.f,0.f,0.f,0.f);
        if (bcol < N) bv = *(const float4*)(W + (size_t)(k0 + bkr) * N + bcol);
        *(float4*)&Bs[bkr][bcol] = bv;
        __syncthreads();
        #pragma unroll
        for (int kk = 0; kk < 16; kk++){
            float a[4], b[4];
            *(float4*)a = *(const float4*)&As[kk][ty*4];
            *(float4*)b = *(const float4*)&Bs[kk][tx*4];
            #pragma unroll
            for (int i = 0; i < 4; i++)
                #pragma unroll
                for (int j = 0; j < 4; j++)
                    acc[i][j] = fmaf(a[i], b[j], acc[i][j]);
        }
        __syncthreads();
    }

    if (tx*4 < N){
        float bsv[4];
        #pragma unroll
        for (int j = 0; j < 4; j++) bsv[j] = bias[tx*4 + j];
        #pragma unroll
        for (int i = 0; i < 4; i++){
            float4 v;
            v.x = apply_act<ACT>(acc[i][0] + bsv[0], tx*4+0);
            v.y = apply_act<ACT>(acc[i][1] + bsv[1], tx*4+1);
            v.z = apply_act<ACT>(acc[i][2] + bsv[2], tx*4+2);
            v.w = apply_act<ACT>(acc[i][3] + bsv[3], tx*4+3);
            *(float4*)(C + (size_t)(bm + ty*4 + i) * N + tx*4) = v;
            float2 s0 = split2(v.x), s1 = split2(v.y), s2 = split2(v.z), s3 = split2(v.w);
            float4* d = (float4*)(C2 + (size_t)(bm + ty*4 + i) * N + tx*4);
            d[0] = make_float4(s0.x, s0.y, s1.x, s1.y);
            d[1] = make_float4(s2.x, s2.y, s3.x, s3.y);
        }
    }
}

// ---------------- codebook norms ----------------
__global__ void enorm_kernel(const float* __restrict__ emb, float* __restrict__ enorm){
    int k = blockIdx.x * 256 + threadIdx.x;
    if (k >= KCODES) return;
    const float4* e = (const float4*)(emb + (size_t)k * DLAT);
    float s = 0.0f;
    #pragma unroll
    for (int q = 0; q < 16; q++){
        float4 v = e[q];
        s += v.x*v.x + v.y*v.y + v.z*v.z + v.w*v.w;
    }
    enorm[k] = s;
}

// ---------------- VQ argmin via tensor cores on PRE-SPLIT data ----------------
__global__ void __launch_bounds__(256) vq_argmin_mma(
    const float2* __restrict__ z2, const float2* __restrict__ emb2,
    const float* __restrict__ enorm, int* __restrict__ idx_out)
{
    extern __shared__ float2 sm2[];
    float2 (*Zs)[128+SPAD] = (float2 (*)[128+SPAD])sm2;                   // [64][132]
    float2 (*Es)[128+SPAD] = (float2 (*)[128+SPAD])(sm2 + 64*(128+SPAD)); // [64][132]
    float* en = (float*)(sm2 + 2*64*(128+SPAD));                          // [128]

    const int tid  = threadIdx.x;
    const int lane = tid & 31, warp = tid >> 5;
    const int wm = (warp & 1) * 64, wn = (warp >> 1) * 32;
    const int bm = blockIdx.x * 128;
    const int g = lane >> 2, tg = lane & 3;

    const int zr = tid >> 1, zc = (tid & 1) * 32;
    {
        const float4* Zp = (const float4*)(z2 + (size_t)(bm + zr) * DLAT + zc);
        #pragma unroll
        for (int q = 0; q < 16; q++){
            float4 v = Zp[q];
            Zs[zc + q*2 + 0][zr] = make_float2(v.x, v.y);
            Zs[zc + q*2 + 1][zr] = make_float2(v.z, v.w);
        }
    }

    float mv[8]; int mi[8];
    #pragma unroll
    for (int s = 0; s < 8; s++){ mv[s] = INFINITY; mi[s] = 0; }

    for (int c0 = 0; c0 < KCODES; c0 += 128){
        __syncthreads();
        {
            const float4* Ep = (const float4*)(emb2 + (size_t)(c0 + zr) * DLAT + zc);
            #pragma unroll
            for (int q = 0; q < 16; q++){
                float4 v = Ep[q];
                Es[zc + q*2 + 0][zr] = make_float2(v.x, v.y);
                Es[zc + q*2 + 1][zr] = make_float2(v.z, v.w);
            }
        }
        if (tid < 128) en[tid] = enorm[c0 + tid];
        __syncthreads();

        float acc[4][4][4];
        #pragma unroll
        for (int i = 0; i < 4; i++)
            #pragma unroll
            for (int j = 0; j < 4; j++)
                #pragma unroll
                for (int q = 0; q < 4; q++) acc[i][j][q] = 0.0f;

        #pragma unroll
        for (int ks = 0; ks < DLAT; ks += 8){
            uint32_t ah[4][4], al[4][4];
            #pragma unroll
            for (int mt = 0; mt < 4; mt++){
                int m = wm + mt*16 + g;
                float2 v0 = Zs[ks+tg][m];
                float2 v1 = Zs[ks+tg][m+8];
                float2 v2 = Zs[ks+4+tg][m];
                float2 v3 = Zs[ks+4+tg][m+8];
                ah[mt][0] = __float_as_uint(v0.x);
                ah[mt][1] = __float_as_uint(v1.x);
                ah[mt][2] = __float_as_uint(v2.x);
                ah[mt][3] = __float_as_uint(v3.x);
                al[mt][0] = __float_as_uint(v0.y);
                al[mt][1] = __float_as_uint(v1.y);
                al[mt][2] = __float_as_uint(v2.y);
                al[mt][3] = __float_as_uint(v3.y);
            }
            #pragma unroll
            for (int nt = 0; nt < 4; nt++){
                int n = wn + nt*8 + g;
                float2 w0 = Es[ks+tg][n];
                float2 w1 = Es[ks+4+tg][n];
                uint32_t bh[2] = { __float_as_uint(w0.x), __float_as_uint(w1.x) };
                uint32_t bl[2] = { __float_as_uint(w0.y), __float_as_uint(w1.y) };
                #pragma unroll
                for (int mt = 0; mt < 4; mt++) mma8(acc[mt][nt], ah[mt], bh);
                #pragma unroll
                for (int mt = 0; mt < 4; mt++) mma8(acc[mt][nt], al[mt], bh);
                #pragma unroll
                for (int mt = 0; mt < 4; mt++) mma8(acc[mt][nt], ah[mt], bl);
            }
        }

        // running argmin (ascending code order within thread; strict < keeps first min)
        #pragma unroll
        for (int mt = 0; mt < 4; mt++){
            #pragma unroll
            for (int nt = 0; nt < 4; nt++){
                int nc = wn + nt*8 + 2*tg;
                float e0 = en[nc], e1 = en[nc+1];
                int code = c0 + nc;
                float d00 = e0 - 2.0f*acc[mt][nt][0];
                float d01 = e1 - 2.0f*acc[mt][nt][1];
                float d10 = e0 - 2.0f*acc[mt][nt][2];
                float d11 = e1 - 2.0f*acc[mt][nt][3];
                int s0 = mt*2, s1 = mt*2 + 1;
                if (d00 < mv[s0]){ mv[s0] = d00; mi[s0] = code;   }
                if (d01 < mv[s0]){ mv[s0] = d01; mi[s0] = code+1; }
                if (d10 < mv[s1]){ mv[s1] = d10; mi[s1] = code;   }
                if (d11 < mv[s1]){ mv[s1] = d11; mi[s1] = code+1; }
            }
        }
    }

    __syncthreads();
    float* rv = (float*)Es;           // 16 candidates x 128 rows
    int*   ri = ((int*)Es) + 16*128;
    int cand = (warp >> 1) * 4 + tg;  // 0..15
    #pragma unroll
    for (int s = 0; s < 8; s++){
        int r = wm + (s >> 1)*16 + g + (s & 1)*8;
        rv[cand*128 + r] = mv[s];
        ri[cand*128 + r] = mi[s];
    }
    __syncthreads();
    if (tid < 128){
        float bv = INFINITY; int bi = 0x7fffffff;
        #pragma unroll
        for (int t = 0; t < 16; t++){
            float v = rv[t*128 + tid];
            int c = ri[t*128 + tid];
            if (v < bv || (v == bv && c < bi)){ bv = v; bi = c; }
        }
        idx_out[bm + tid] = bi;
    }
}

// ---------------- gather z_q, idx-as-float, counts, commit-loss partial sums ----------------
__global__ void vq_post(const float* __restrict__ z, const float* __restrict__ emb,
                        const int* __restrict__ idx, float* __restrict__ zq,
                        float* __restrict__ counts, float* __restrict__ loss,
                        float* __restrict__ out_idx)
{
    int b = blockIdx.x * 256 + threadIdx.x;
    int k = idx[b];
    const float4* e  = (const float4*)(emb + (size_t)k * DLAT);
    const float4* zz = (const float4*)(z   + (size_t)b * DLAT);
    float4*       zo = (float4*)(zq + (size_t)b * DLAT);
    float s = 0.0f;
    #pragma unroll
    for (int q = 0; q < 16; q++){
        float4 ev = e[q], zv = zz[q];
        float dx = ev.x - zv.x, dy = ev.y - zv.y, dz = ev.z - zv.z, dw = ev.w - zv.w;
        s += dx*dx + dy*dy + dz*dz + dw*dw;
        zo[q] = ev;
    }
    out_idx[b] = (float)k;
    atomicAdd(&counts[k], 1.0f);

    __shared__ float red[256];
    red[threadIdx.x] = s;
    __syncthreads();
    for (int off = 128; off > 0; off >>= 1){
        if (threadIdx.x < off) red[threadIdx.x] += red[threadIdx.x + off];
        __syncthreads();
    }
    if (threadIdx.x == 0) atomicAdd(loss, red[0]);
}

// ---------------- perplexity + vq_loss scalars ----------------
__global__ void finalize_kernel(const float* __restrict__ counts, const float* __restrict__ loss,
                                float* __restrict__ out)
{
    __shared__ float red[256];
    float s = 0.0f;
    for (int k = threadIdx.x; k < KCODES; k += 256){
        float p = counts[k] * (1.0f / (float)BATCH);
        s += p * logf(p + 1e-10f);
    }
    red[threadIdx.x] = s;
    __syncthreads();
    for (int off = 128; off > 0; off >>= 1){
        if (threadIdx.x < off) red[threadIdx.x] += red[threadIdx.x + off];
        __syncthreads();
    }
    if (threadIdx.x == 0){
        out[PERP_OFF] = expf(-red[0]);
        out[LOSS_OFF] = loss[0] * (0.25f / ((float)BATCH * (float)DLAT));
    }
}

// ---------------- zero counts + loss ----------------
__global__ void zero_kernel(float* __restrict__ counts, float* __restrict__ loss){
    int i = blockIdx.x * 256 + threadIdx.x;
    if (i < KCODES) counts[i] = 0.0f;
    if (i == KCODES) loss[0] = 0.0f;
}

// ---------------- concat head weights [pW|wW|aW|0pad] -> [1024,128], biases -> [128] ----------------
__global__ void concat_head(const float* __restrict__ pW, const float* __restrict__ pb,
                            const float* __restrict__ wW, const float* __restrict__ wb,
                            const float* __restrict__ aW, const float* __restrict__ ab,
                            float* __restrict__ hw, float* __restrict__ hb)
{
    int i = blockIdx.x * 256 + threadIdx.x;
    int total = HIDDEN * 128;
    if (i < total){
        int k = i >> 7, col = i & 127;
        float v = 0.0f;
        if (col < 40)      v = pW[k*40 + col];
        else if (col < 42) v = wW[k*2 + (col-40)];
        else if (col < 44) v = aW[k*2 + (col-42)];
        hw[i] = v;
    }
    if (i < 128){
        float v = 0.0f;
        if (i < 40)      v = pb[i];
        else if (i < 42) v = wb[i-40];
        else if (i < 44) v = ab[i-42];
        hb[i] = v;
    }
}

// ---------------- pack outputs: points / control_points / widths / alphas ----------------
__global__ void pack_kernel(const float* __restrict__ ho, float* __restrict__ out){
    int gid = blockIdx.x * 256 + threadIdx.x;
    int b = gid / 92, e = gid % 92;
    if (b >= BATCH) return;
    const float* h = ho + (size_t)b * 128;
    if (e < 40){
        out[P_OFF + (size_t)b*40 + e] = h[e];
    } else if (e < 88){
        int e2 = e - 40;
        int c  = e2 & 1;
        int j  = (e2 >> 1) & 3;
        int sg = (e2 >> 3) % 3;
        int p  = e2 / 24;
        out[CP_OFF + (size_t)b*48 + e2] = h[p*20 + (3*sg + j)*2 + c];
    } else if (e < 90){
        int p = e - 88;
        out[W_OFF + (size_t)b*2 + p] = h[40 + p];
    } else {
        int p = e - 90;
        out[A_OFF + (size_t)b*2 + p] = h[42 + p];
    }
}

// ---------------- launch ----------------
extern "C" void kernel_launch(void* const* d_in, const int* in_sizes, int n_in,
                              void* d_out, int out_size)
{
    (void)in_sizes; (void)n_in; (void)out_size;
    const float* x   = (const float*)d_in[0];
    const float* W1  = (const float*)d_in[1];
    const float* b1  = (const float*)d_in[2];
    const float* W2  = (const float*)d_in[3];
    const float* b2  = (const float*)d_in[4];
    const float* W3  = (const float*)d_in[5];
    const float* b3  = (const float*)d_in[6];
    const float* emb = (const float*)d_in[7];
    const float* dW1 = (const float*)d_in[8];
    const float* db1 = (const float*)d_in[9];
    const float* dW2 = (const float*)d_in[10];
    const float* db2 = (const float*)d_in[11];
    const float* pW  = (const float*)d_in[12];
    const float* pb  = (const float*)d_in[13];
    const float* wW  = (const float*)d_in[14];
    const float* wb  = (const float*)d_in[15];
    const float* aW  = (const float*)d_in[16];
    const float* ab  = (const float*)d_in[17];
    float* out = (float*)d_out;

    float2 *x2, *W12, *W22, *emb2, *h12, *z2;
    float *h2, *z, *zq, *d1, *d2, *ho, *counts, *loss, *enorm, *hw, *hb;
    int* idx;
    cudaGetSymbolAddress((void**)&x2,  g_x2);
    cudaGetSymbolAddress((void**)&W12, g_W12);
    cudaGetSymbolAddress((void**)&W22, g_W22);
    cudaGetSymbolAddress((void**)&emb2, g_emb2);
    cudaGetSymbolAddress((void**)&h12, g_h12);
    cudaGetSymbolAddress((void**)&z2,  g_z2);
    cudaGetSymbolAddress((void**)&h2,  g_h2);
    cudaGetSymbolAddress((void**)&z,   g_z);
    cudaGetSymbolAddress((void**)&zq,  g_zq);
    cudaGetSymbolAddress((void**)&d1,  g_d1);
    cudaGetSymbolAddress((void**)&d2,  g_d2);
    cudaGetSymbolAddress((void**)&ho,  g_ho);
    cudaGetSymbolAddress((void**)&idx, g_idx);
    cudaGetSymbolAddress((void**)&counts, g_counts);
    cudaGetSymbolAddress((void**)&loss, g_loss);
    cudaGetSymbolAddress((void**)&enorm, g_enorm);
    cudaGetSymbolAddress((void**)&hw,  g_hw);
    cudaGetSymbolAddress((void**)&hb,  g_hb);

    const int VQ_SMEM = (int)(2*64*(128+SPAD)*sizeof(float2) + 128*sizeof(float));
    cudaFuncSetAttribute(vq_argmin_mma, cudaFuncAttributeMaxDynamicSharedMemorySize, VQ_SMEM);
    const int WIDE_SMEM = (int)((WA_ELEMS + 3*16*WBST) * sizeof(float));
    cudaFuncSetAttribute(mma_1x_wide<ACT_SELU>, cudaFuncAttributeMaxDynamicSharedMemorySize, WIDE_SMEM);

    // init + pre-split inputs
    zero_kernel<<<(KCODES + 1 + 255)/256, 256>>>(counts, loss);
    concat_head<<<(HIDDEN*128 + 255)/256, 256>>>(pW, pb, wW, wb, aW, ab, hw, hb);
    enorm_kernel<<<(KCODES + 255)/256, 256>>>(emb, enorm);
    split_arr<<<(BATCH*784/4 + 255)/256, 256>>>(x,   x2,  BATCH*784/4);
    split_arr<<<(784*256/4   + 255)/256, 256>>>(W1,  W12, 784*256/4);
    split_arr<<<(256*256/4   + 255)/256, 256>>>(W2,  W22, 256*256/4);
    split_arr<<<(KCODES*DLAT/4 + 255)/256, 256>>>(emb, emb2, KCODES*DLAT/4);

    // encoder (split-3x tensor cores, pre-split inputs)
    mma_gemm_pre<ACT_LEAKY, 1><<<dim3(2, BATCH/128), 256>>>(x2,  W12, b1, nullptr, h12, BATCH, 256, 784);
    mma_gemm_pre<ACT_LEAKY, 0><<<dim3(2, BATCH/128), 256>>>(h12, W22, b2, h2, nullptr, BATCH, 256, 256);
    sgemm_smallN<ACT_NONE><<<BATCH/64, 256>>>(h2, W3, b3, z, z2, BATCH, DLAT, 256);

    // VQ (split-3x, pre-split, fused argmin)
    vq_argmin_mma<<<BATCH/128, 256, VQ_SMEM>>>(z2, emb2, enorm, idx);
    vq_post<<<BATCH/256, 256>>>(z, emb, idx, zq, counts, loss, out + IDX_OFF);
    finalize_kernel<<<1, 256>>>(counts, loss, out);

    // decoder (1x TF32, wide 128x256 tiles, 3-stage cp.async)
    mma_1x_wide<ACT_SELU><<<dim3(HIDDEN/256, BATCH/128), 256, WIDE_SMEM>>>(zq, dW1, db1, d1, BATCH, HIDDEN, DLAT);
    mma_1x_wide<ACT_SELU><<<dim3(HIDDEN/256, BATCH/128), 256, WIDE_SMEM>>>(d1, dW2, db2, d2, BATCH, HIDDEN, HIDDEN);

    // head (1x TF32, N padded to 128)
    mma_gemm_1x<ACT_HEAD><<<dim3(1, BATCH/128), 256>>>(d2, hw, hb, ho, BATCH, 128, HIDDEN);

    // pack outputs
    pack_kernel<<<(BATCH*92 + 255)/256, 256>>>(ho, out);
}

// round 5
// speedup vs baseline: 1.1830x; 1.1830x over previous
#include <cuda_runtime.h>
#include <math.h>
#include <stdint.h>

// ---------------- problem constants ----------------
#define BATCH   32768
#define KCODES  4096
#define DLAT    64
#define HIDDEN  1024

// output layout (f32, reference return order, flattened+concat)
#define P_OFF    0
#define P_SIZE   (BATCH*40)
#define CP_OFF   (P_OFF + P_SIZE)
#define CP_SIZE  (BATCH*48)
#define W_OFF    (CP_OFF + CP_SIZE)
#define WA_SIZE  (BATCH*2)
#define A_OFF    (W_OFF + WA_SIZE)
#define LOSS_OFF (A_OFF + WA_SIZE)
#define IDX_OFF  (LOSS_OFF + 1)
#define PERP_OFF (IDX_OFF + BATCH)

#define SPAD 4

// ---------------- scratch (__device__ globals; no allocation allowed) ----------------
__device__ float g_h1[BATCH*256];
__device__ float g_h2[BATCH*256];
__device__ float g_z [BATCH*DLAT];
__device__ float g_zq[BATCH*DLAT];
__device__ float g_d1[BATCH*HIDDEN];
__device__ float g_d2[BATCH*HIDDEN];
__device__ float g_ho[BATCH*128];        // head out, stride 128 (padded)
__device__ int   g_idx[BATCH];
__device__ float g_counts[KCODES];
__device__ float g_loss;
__device__ float g_enorm[KCODES];
__device__ float g_hw[HIDDEN*128];       // padded head weights [1024,128]
__device__ float g_hb[128];

// ---------------- activations ----------------
#define ACT_NONE 0
#define ACT_LEAKY 1
#define ACT_SELU 2
#define ACT_HEAD 3

__device__ __forceinline__ float sigmoidf_(float x){ return 1.0f/(1.0f+expf(-x)); }

template<int ACT>
__device__ __forceinline__ float apply_act(float v, int col){
    if (ACT == ACT_LEAKY) return v > 0.0f ? v : 0.2f*v;
    if (ACT == ACT_SELU){
        const float a = 1.6732632423543772f, s = 1.0507009873554805f;
        return v > 0.0f ? s*v : s*a*(expf(v)-1.0f);
    }
    if (ACT == ACT_HEAD){
        if (col < 40) return tanhf(v)*12.0f + 14.0f;
        if (col < 42) return sigmoidf_(v)*2.0f + 1.0f;
        return sigmoidf_(v);
    }
    return v;
}

// ---------------- TF32 split helpers ----------------
__device__ __forceinline__ uint32_t tf32_of(float x){
    uint32_t r; asm("cvt.rna.tf32.f32 %0, %1;" : "=r"(r) : "f"(x)); return r;
}
// returns (hi, lo) both already valid tf32 bit patterns stored as floats
__device__ __forceinline__ float2 split2(float x){
    uint32_t h = tf32_of(x);
    float hf = __uint_as_float(h);
    float lof = __uint_as_float(tf32_of(x - hf));
    return make_float2(hf, lof);
}

// D += A*B, m16n8k8 tf32
__device__ __forceinline__ void mma8(float* c, const uint32_t* a, const uint32_t* b){
    asm volatile(
        "mma.sync.aligned.m16n8k8.row.col.f32.tf32.tf32.f32 "
        "{%0,%1,%2,%3}, {%4,%5,%6,%7}, {%8,%9}, {%0,%1,%2,%3};\n"
        : "+f"(c[0]), "+f"(c[1]), "+f"(c[2]), "+f"(c[3])
        : "r"(a[0]), "r"(a[1]), "r"(a[2]), "r"(a[3]), "r"(b[0]), "r"(b[1]));
}

// ---------------- cp.async helpers ----------------
__device__ __forceinline__ void cpasync16(void* dst_smem, const void* src){
    uint32_t s = (uint32_t)__cvta_generic_to_shared(dst_smem);
    asm volatile("cp.async.cg.shared.global [%0], [%1], 16;\n" :: "r"(s), "l"(src));
}
__device__ __forceinline__ void cpasync_commit(){ asm volatile("cp.async.commit_group;\n"); }
template<int NN>
__device__ __forceinline__ void cpasync_wait(){ asm volatile("cp.async.wait_group %0;\n" :: "n"(NN)); }

// ============================================================================
// 1x-TF32 GEMM (decoder + head): C = act(A[M,K] @ W[K,N] + bias)
// 128x128 tile, BK=16, 8 warps (2Mx4N), cp.async double-buffered.
// ============================================================================
#define AST 20
#define BST 136
template<int ACT>
__global__ void __launch_bounds__(256, 2) mma_gemm_1x(
    const float* __restrict__ A, const float* __restrict__ W,
    const float* __restrict__ bias, float* __restrict__ C,
    int M, int N, int K)
{
    __shared__ float As[2][128][AST];
    __shared__ float Bs[2][16][BST];

    const int tid  = threadIdx.x;
    const int lane = tid & 31, warp = tid >> 5;
    const int wm = (warp & 1) * 64, wn = (warp >> 1) * 32;
    const int bm = blockIdx.y * 128, bn = blockIdx.x * 128;
    const int g = lane >> 2, tg = lane & 3;

    float acc[4][4][4];
    #pragma unroll
    for (int i = 0; i < 4; i++)
        #pragma unroll
        for (int j = 0; j < 4; j++)
            #pragma unroll
            for (int q = 0; q < 4; q++) acc[i][j][q] = 0.0f;

    const int ar = tid >> 1, ac = (tid & 1) * 8;
    const int br = tid >> 4, bc = (tid & 15) * 8;
    const float* Ap = A + (size_t)(bm + ar) * K + ac;
    const float* Bp = W + (size_t)br * N + bn + bc;

    const int ntiles = K >> 4;

    #define COPY_TILE(kt, buf) do { \
        const float* ap = Ap + (size_t)(kt) * 16; \
        cpasync16(&As[buf][ar][ac],   ap); \
        cpasync16(&As[buf][ar][ac+4], ap + 4); \
        const float* bp = Bp + (size_t)(kt) * 16 * N; \
        cpasync16(&Bs[buf][br][bc],   bp); \
        cpasync16(&Bs[buf][br][bc+4], bp + 4); \
        cpasync_commit(); \
    } while (0)

    COPY_TILE(0, 0);

    for (int i = 0; i < ntiles; i++){
        int buf = i & 1;
        if (i + 1 < ntiles){
            COPY_TILE(i + 1, buf ^ 1);
            cpasync_wait<1>();
        } else {
            cpasync_wait<0>();
        }
        __syncthreads();

        #pragma unroll
        for (int ks = 0; ks < 16; ks += 8){
            uint32_t a[4][4];
            #pragma unroll
            for (int mt = 0; mt < 4; mt++){
                int m = wm + mt*16 + g;
                a[mt][0] = __float_as_uint(As[buf][m  ][ks+tg]);
                a[mt][1] = __float_as_uint(As[buf][m+8][ks+tg]);
                a[mt][2] = __float_as_uint(As[buf][m  ][ks+tg+4]);
                a[mt][3] = __float_as_uint(As[buf][m+8][ks+tg+4]);
            }
            #pragma unroll
            for (int nt = 0; nt < 4; nt++){
                int n = wn + nt*8 + g;
                uint32_t b[2] = { __float_as_uint(Bs[buf][ks+tg  ][n]),
                                  __float_as_uint(Bs[buf][ks+tg+4][n]) };
                #pragma unroll
                for (int mt = 0; mt < 4; mt++) mma8(acc[mt][nt], a[mt], b);
            }
        }
        __syncthreads();
    }
    #undef COPY_TILE

    // epilogue: bias + activation, 64-bit stores
    #pragma unroll
    for (int mt = 0; mt < 4; mt++){
        #pragma unroll
        for (int nt = 0; nt < 4; nt++){
            int row = bm + wm + mt*16 + g;
            int col = bn + wn + nt*8 + 2*tg;
            float bs0 = bias[col], bs1 = bias[col+1];
            float2 o0, o1;
            o0.x = apply_act<ACT>(acc[mt][nt][0] + bs0, col);
            o0.y = apply_act<ACT>(acc[mt][nt][1] + bs1, col+1);
            o1.x = apply_act<ACT>(acc[mt][nt][2] + bs0, col);
            o1.y = apply_act<ACT>(acc[mt][nt][3] + bs1, col+1);
            *(float2*)&C[(size_t)row*N + col]     = o0;
            *(float2*)&C[(size_t)(row+8)*N + col] = o1;
        }
    }
}

// ---------------- tensor-core GEMM (split-TF32, 3 mma products; encoder) ----------------
template<int ACT>
__global__ void __launch_bounds__(256, 2) mma_gemm(
    const float* __restrict__ A, const float* __restrict__ W,
    const float* __restrict__ bias, float* __restrict__ C,
    int M, int N, int K)
{
    __shared__ float2 As[16][128+SPAD];   // [k][m] = (hi, lo)
    __shared__ float2 Bs[16][128+SPAD];   // [k][n] = (hi, lo)

    const int tid  = threadIdx.x;
    const int lane = tid & 31, warp = tid >> 5;
    const int wm = (warp & 1) * 64, wn = (warp >> 1) * 32;
    const int bm = blockIdx.y * 128, bn = blockIdx.x * 128;
    const int g = lane >> 2, tg = lane & 3;

    float acc[4][4][4];
    #pragma unroll
    for (int i = 0; i < 4; i++)
        #pragma unroll
        for (int j = 0; j < 4; j++)
            #pragma unroll
            for (int q = 0; q < 4; q++) acc[i][j][q] = 0.0f;

    const int ar = tid >> 1, ac = (tid & 1) * 8;
    const int br = tid >> 4, bc = (tid & 15) * 4;
    const float* Ap = A + (size_t)(bm + ar) * K + ac;
    const float* Bp = W + (size_t)br * N + bn + bc;

    for (int k0 = 0; k0 < K; k0 += 16){
        float4 av0 = *(const float4*)(Ap + k0);
        float4 av1 = *(const float4*)(Ap + k0 + 4);
        As[ac+0][ar] = split2(av0.x);
        As[ac+1][ar] = split2(av0.y);
        As[ac+2][ar] = split2(av0.z);
        As[ac+3][ar] = split2(av0.w);
        As[ac+4][ar] = split2(av1.x);
        As[ac+5][ar] = split2(av1.y);
        As[ac+6][ar] = split2(av1.z);
        As[ac+7][ar] = split2(av1.w);
        float4 bv0 = *(const float4*)(Bp + (size_t)k0 * N);
        float4 bv1 = *(const float4*)(Bp + (size_t)k0 * N + 64);
        Bs[br][bc+0] = split2(bv0.x);
        Bs[br][bc+1] = split2(bv0.y);
        Bs[br][bc+2] = split2(bv0.z);
        Bs[br][bc+3] = split2(bv0.w);
        Bs[br][bc+64+0] = split2(bv1.x);
        Bs[br][bc+64+1] = split2(bv1.y);
        Bs[br][bc+64+2] = split2(bv1.z);
        Bs[br][bc+64+3] = split2(bv1.w);
        __syncthreads();

        #pragma unroll
        for (int ks = 0; ks < 16; ks += 8){
            uint32_t ah[4][4], al[4][4];
            #pragma unroll
            for (int mt = 0; mt < 4; mt++){
                int m = wm + mt*16 + g;
                float2 v0 = As[ks+tg][m];
                float2 v1 = As[ks+tg][m+8];
                float2 v2 = As[ks+4+tg][m];
                float2 v3 = As[ks+4+tg][m+8];
                ah[mt][0] = __float_as_uint(v0.x);
                ah[mt][1] = __float_as_uint(v1.x);
                ah[mt][2] = __float_as_uint(v2.x);
                ah[mt][3] = __float_as_uint(v3.x);
                al[mt][0] = __float_as_uint(v0.y);
                al[mt][1] = __float_as_uint(v1.y);
                al[mt][2] = __float_as_uint(v2.y);
                al[mt][3] = __float_as_uint(v3.y);
            }
            #pragma unroll
            for (int nt = 0; nt < 4; nt++){
                int n = wn + nt*8 + g;
                float2 w0 = Bs[ks+tg][n];
                float2 w1 = Bs[ks+4+tg][n];
                uint32_t bh[2] = { __float_as_uint(w0.x), __float_as_uint(w1.x) };
                uint32_t bl[2] = { __float_as_uint(w0.y), __float_as_uint(w1.y) };
                #pragma unroll
                for (int mt = 0; mt < 4; mt++) mma8(acc[mt][nt], ah[mt], bh);
                #pragma unroll
                for (int mt = 0; mt < 4; mt++) mma8(acc[mt][nt], al[mt], bh);
                #pragma unroll
                for (int mt = 0; mt < 4; mt++) mma8(acc[mt][nt], ah[mt], bl);
            }
        }
        __syncthreads();
    }

    // epilogue: bias + activation, 64-bit stores
    #pragma unroll
    for (int mt = 0; mt < 4; mt++){
        #pragma unroll
        for (int nt = 0; nt < 4; nt++){
            int row = bm + wm + mt*16 + g;
            int col = bn + wn + nt*8 + 2*tg;
            float bs0 = bias[col], bs1 = bias[col+1];
            float2 o0, o1;
            o0.x = apply_act<ACT>(acc[mt][nt][0] + bs0, col);
            o0.y = apply_act<ACT>(acc[mt][nt][1] + bs1, col+1);
            o1.x = apply_act<ACT>(acc[mt][nt][2] + bs0, col);
            o1.y = apply_act<ACT>(acc[mt][nt][3] + bs1, col+1);
            *(float2*)&C[(size_t)row*N + col]     = o0;
            *(float2*)&C[(size_t)(row+8)*N + col] = o1;
        }
    }
}

// ---------------- small-N SGEMM: 64 rows x N(<=64) cols, BK=16, 4x4 microtile ----------------
template<int ACT>
__global__ void __launch_bounds__(256) sgemm_smallN(
    const float* __restrict__ A, const float* __restrict__ W,
    const float* __restrict__ bias, float* __restrict__ C,
    int M, int N, int K)
{
    __shared__ float As[16][64];
    __shared__ float Bs[16][64];
    const int tid = threadIdx.x;
    const int bm = blockIdx.x * 64;
    const int arow = tid >> 2,  acol = (tid & 3) * 4;
    const int bkr  = tid >> 4,  bcol = (tid & 15) * 4;
    const int ty = tid >> 4, tx = tid & 15;

    float acc[4][4];
    #pragma unroll
    for (int i = 0; i < 4; i++)
        #pragma unroll
        for (int j = 0; j < 4; j++) acc[i][j] = 0.0f;

    for (int k0 = 0; k0 < K; k0 += 16){
        float4 av = *(const float4*)(A + (size_t)(bm + arow) * K + k0 + acol);
        As[acol+0][arow] = av.x;
        As[acol+1][arow] = av.y;
        As[acol+2][arow] = av.z;
        As[acol+3][arow] = av.w;
        float4 bv = make_float4(0.f,0.f,0.f,0.f);
        if (bcol < N) bv = *(const float4*)(W + (size_t)(k0 + bkr) * N + bcol);
        *(float4*)&Bs[bkr][bcol] = bv;
        __syncthreads();
        #pragma unroll
        for (int kk = 0; kk < 16; kk++){
            float a[4], b[4];
            *(float4*)a = *(const float4*)&As[kk][ty*4];
            *(float4*)b = *(const float4*)&Bs[kk][tx*4];
            #pragma unroll
            for (int i = 0; i < 4; i++)
                #pragma unroll
                for (int j = 0; j < 4; j++)
                    acc[i][j] = fmaf(a[i], b[j], acc[i][j]);
        }
        __syncthreads();
    }

    if (tx*4 < N){
        float bsv[4];
        #pragma unroll
        for (int j = 0; j < 4; j++) bsv[j] = bias[tx*4 + j];
        #pragma unroll
        for (int i = 0; i < 4; i++){
            float4 v;
            v.x = apply_act<ACT>(acc[i][0] + bsv[0], tx*4+0);
            v.y = apply_act<ACT>(acc[i][1] + bsv[1], tx*4+1);
            v.z = apply_act<ACT>(acc[i][2] + bsv[2], tx*4+2);
            v.w = apply_act<ACT>(acc[i][3] + bsv[3], tx*4+3);
            *(float4*)(C + (size_t)(bm + ty*4 + i) * N + tx*4) = v;
        }
    }
}

// ---------------- codebook norms ----------------
__global__ void enorm_kernel(const float* __restrict__ emb, float* __restrict__ enorm){
    int k = blockIdx.x * 256 + threadIdx.x;
    if (k >= KCODES) return;
    const float4* e = (const float4*)(emb + (size_t)k * DLAT);
    float s = 0.0f;
    #pragma unroll
    for (int q = 0; q < 16; q++){
        float4 v = e[q];
        s += v.x*v.x + v.y*v.y + v.z*v.z + v.w*v.w;
    }
    enorm[k] = s;
}

// ---------------- VQ argmin via tensor cores: 128 rows x 4096 codes, K=64 ----------------
__global__ void __launch_bounds__(256) vq_argmin_mma(
    const float* __restrict__ z, const float* __restrict__ emb,
    const float* __restrict__ enorm, int* __restrict__ idx_out)
{
    extern __shared__ float2 sm2[];
    float2 (*Zs)[128+SPAD] = (float2 (*)[128+SPAD])sm2;                   // [64][132]
    float2 (*Es)[128+SPAD] = (float2 (*)[128+SPAD])(sm2 + 64*(128+SPAD)); // [64][132]
    float* en = (float*)(sm2 + 2*64*(128+SPAD));                          // [128]

    const int tid  = threadIdx.x;
    const int lane = tid & 31, warp = tid >> 5;
    const int wm = (warp & 1) * 64, wn = (warp >> 1) * 32;
    const int bm = blockIdx.x * 128;
    const int g = lane >> 2, tg = lane & 3;

    // load z tile: [k][m] split form
    const int zr = tid >> 1, zc = (tid & 1) * 32;
    {
        const float* Zp = z + (size_t)(bm + zr) * DLAT + zc;
        #pragma unroll
        for (int q = 0; q < 8; q++){
            float4 v = *(const float4*)(Zp + q*4);
            Zs[zc+q*4+0][zr] = split2(v.x);
            Zs[zc+q*4+1][zr] = split2(v.y);
            Zs[zc+q*4+2][zr] = split2(v.z);
            Zs[zc+q*4+3][zr] = split2(v.w);
        }
    }

    float mv[8]; int mi[8];
    #pragma unroll
    for (int s = 0; s < 8; s++){ mv[s] = INFINITY; mi[s] = 0; }

    for (int c0 = 0; c0 < KCODES; c0 += 128){
        __syncthreads();
        {
            const float* Ep = emb + (size_t)(c0 + zr) * DLAT + zc;
            #pragma unroll
            for (int q = 0; q < 8; q++){
                float4 v = *(const float4*)(Ep + q*4);
                Es[zc+q*4+0][zr] = split2(v.x);
                Es[zc+q*4+1][zr] = split2(v.y);
                Es[zc+q*4+2][zr] = split2(v.z);
                Es[zc+q*4+3][zr] = split2(v.w);
            }
        }
        if (tid < 128) en[tid] = enorm[c0 + tid];
        __syncthreads();

        float acc[4][4][4];
        #pragma unroll
        for (int i = 0; i < 4; i++)
            #pragma unroll
            for (int j = 0; j < 4; j++)
                #pragma unroll
                for (int q = 0; q < 4; q++) acc[i][j][q] = 0.0f;

        #pragma unroll
        for (int ks = 0; ks < DLAT; ks += 8){
            uint32_t ah[4][4], al[4][4];
            #pragma unroll
            for (int mt = 0; mt < 4; mt++){
                int m = wm + mt*16 + g;
                float2 v0 = Zs[ks+tg][m];
                float2 v1 = Zs[ks+tg][m+8];
                float2 v2 = Zs[ks+4+tg][m];
                float2 v3 = Zs[ks+4+tg][m+8];
                ah[mt][0] = __float_as_uint(v0.x);
                ah[mt][1] = __float_as_uint(v1.x);
                ah[mt][2] = __float_as_uint(v2.x);
                ah[mt][3] = __float_as_uint(v3.x);
                al[mt][0] = __float_as_uint(v0.y);
                al[mt][1] = __float_as_uint(v1.y);
                al[mt][2] = __float_as_uint(v2.y);
                al[mt][3] = __float_as_uint(v3.y);
            }
            #pragma unroll
            for (int nt = 0; nt < 4; nt++){
                int n = wn + nt*8 + g;
                float2 w0 = Es[ks+tg][n];
                float2 w1 = Es[ks+4+tg][n];
                uint32_t bh[2] = { __float_as_uint(w0.x), __float_as_uint(w1.x) };
                uint32_t bl[2] = { __float_as_uint(w0.y), __float_as_uint(w1.y) };
                #pragma unroll
                for (int mt = 0; mt < 4; mt++) mma8(acc[mt][nt], ah[mt], bh);
                #pragma unroll
                for (int mt = 0; mt < 4; mt++) mma8(acc[mt][nt], al[mt], bh);
                #pragma unroll
                for (int mt = 0; mt < 4; mt++) mma8(acc[mt][nt], ah[mt], bl);
            }
        }

        // running argmin (ascending code order within thread; strict < keeps first min)
        #pragma unroll
        for (int mt = 0; mt < 4; mt++){
            #pragma unroll
            for (int nt = 0; nt < 4; nt++){
                int nc = wn + nt*8 + 2*tg;
                float e0 = en[nc], e1 = en[nc+1];
                int code = c0 + nc;
                float d00 = e0 - 2.0f*acc[mt][nt][0];
                float d01 = e1 - 2.0f*acc[mt][nt][1];
                float d10 = e0 - 2.0f*acc[mt][nt][2];
                float d11 = e1 - 2.0f*acc[mt][nt][3];
                int s0 = mt*2, s1 = mt*2 + 1;
                if (d00 < mv[s0]){ mv[s0] = d00; mi[s0] = code;   }
                if (d01 < mv[s0]){ mv[s0] = d01; mi[s0] = code+1; }
                if (d10 < mv[s1]){ mv[s1] = d10; mi[s1] = code;   }
                if (d11 < mv[s1]){ mv[s1] = d11; mi[s1] = code+1; }
            }
        }
    }

    __syncthreads();
    float* rv = (float*)Es;           // 16 candidates x 128 rows
    int*   ri = ((int*)Es) + 16*128;
    int cand = (warp >> 1) * 4 + tg;  // 0..15
    #pragma unroll
    for (int s = 0; s < 8; s++){
        int r = wm + (s >> 1)*16 + g + (s & 1)*8;
        rv[cand*128 + r] = mv[s];
        ri[cand*128 + r] = mi[s];
    }
    __syncthreads();
    if (tid < 128){
        float bv = INFINITY; int bi = 0x7fffffff;
        #pragma unroll
        for (int t = 0; t < 16; t++){
            float v = rv[t*128 + tid];
            int c = ri[t*128 + tid];
            if (v < bv || (v == bv && c < bi)){ bv = v; bi = c; }
        }
        idx_out[bm + tid] = bi;
    }
}

// ---------------- gather z_q, idx-as-float, counts, commit-loss partial sums ----------------
__global__ void vq_post(const float* __restrict__ z, const float* __restrict__ emb,
                        const int* __restrict__ idx, float* __restrict__ zq,
                        float* __restrict__ counts, float* __restrict__ loss,
                        float* __restrict__ out_idx)
{
    int b = blockIdx.x * 256 + threadIdx.x;
    int k = idx[b];
    const float4* e  = (const float4*)(emb + (size_t)k * DLAT);
    const float4* zz = (const float4*)(z   + (size_t)b * DLAT);
    float4*       zo = (float4*)(zq + (size_t)b * DLAT);
    float s = 0.0f;
    #pragma unroll
    for (int q = 0; q < 16; q++){
        float4 ev = e[q], zv = zz[q];
        float dx = ev.x - zv.x, dy = ev.y - zv.y, dz = ev.z - zv.z, dw = ev.w - zv.w;
        s += dx*dx + dy*dy + dz*dz + dw*dw;
        zo[q] = ev;
    }
    out_idx[b] = (float)k;
    atomicAdd(&counts[k], 1.0f);

    __shared__ float red[256];
    red[threadIdx.x] = s;
    __syncthreads();
    for (int off = 128; off > 0; off >>= 1){
        if (threadIdx.x < off) red[threadIdx.x] += red[threadIdx.x + off];
        __syncthreads();
    }
    if (threadIdx.x == 0) atomicAdd(loss, red[0]);
}

// ---------------- perplexity + vq_loss scalars ----------------
__global__ void finalize_kernel(const float* __restrict__ counts, const float* __restrict__ loss,
                                float* __restrict__ out)
{
    __shared__ float red[256];
    float s = 0.0f;
    for (int k = threadIdx.x; k < KCODES; k += 256){
        float p = counts[k] * (1.0f / (float)BATCH);
        s += p * logf(p + 1e-10f);
    }
    red[threadIdx.x] = s;
    __syncthreads();
    for (int off = 128; off > 0; off >>= 1){
        if (threadIdx.x < off) red[threadIdx.x] += red[threadIdx.x + off];
        __syncthreads();
    }
    if (threadIdx.x == 0){
        out[PERP_OFF] = expf(-red[0]);
        out[LOSS_OFF] = loss[0] * (0.25f / ((float)BATCH * (float)DLAT));
    }
}

// ---------------- zero counts + loss ----------------
__global__ void zero_kernel(float* __restrict__ counts, float* __restrict__ loss){
    int i = blockIdx.x * 256 + threadIdx.x;
    if (i < KCODES) counts[i] = 0.0f;
    if (i == KCODES) loss[0] = 0.0f;
}

// ---------------- concat head weights [pW|wW|aW|0pad] -> [1024,128], biases -> [128] ----------------
__global__ void concat_head(const float* __restrict__ pW, const float* __restrict__ pb,
                            const float* __restrict__ wW, const float* __restrict__ wb,
                            const float* __restrict__ aW, const float* __restrict__ ab,
                            float* __restrict__ hw, float* __restrict__ hb)
{
    int i = blockIdx.x * 256 + threadIdx.x;
    int total = HIDDEN * 128;
    if (i < total){
        int k = i >> 7, col = i & 127;
        float v = 0.0f;
        if (col < 40)      v = pW[k*40 + col];
        else if (col < 42) v = wW[k*2 + (col-40)];
        else if (col < 44) v = aW[k*2 + (col-42)];
        hw[i] = v;
    }
    if (i < 128){
        float v = 0.0f;
        if (i < 40)      v = pb[i];
        else if (i < 42) v = wb[i-40];
        else if (i < 44) v = ab[i-42];
        hb[i] = v;
    }
}

// ---------------- pack outputs: points / control_points / widths / alphas ----------------
__global__ void pack_kernel(const float* __restrict__ ho, float* __restrict__ out){
    int gid = blockIdx.x * 256 + threadIdx.x;
    int b = gid / 92, e = gid % 92;
    if (b >= BATCH) return;
    const float* h = ho + (size_t)b * 128;
    if (e < 40){
        out[P_OFF + (size_t)b*40 + e] = h[e];
    } else if (e < 88){
        int e2 = e - 40;
        int c  = e2 & 1;
        int j  = (e2 >> 1) & 3;
        int sg = (e2 >> 3) % 3;
        int p  = e2 / 24;
        out[CP_OFF + (size_t)b*48 + e2] = h[p*20 + (3*sg + j)*2 + c];
    } else if (e < 90){
        int p = e - 88;
        out[W_OFF + (size_t)b*2 + p] = h[40 + p];
    } else {
        int p = e - 90;
        out[A_OFF + (size_t)b*2 + p] = h[42 + p];
    }
}

// ---------------- launch ----------------
extern "C" void kernel_launch(void* const* d_in, const int* in_sizes, int n_in,
                              void* d_out, int out_size)
{
    (void)in_sizes; (void)n_in; (void)out_size;
    const float* x   = (const float*)d_in[0];
    const float* W1  = (const float*)d_in[1];
    const float* b1  = (const float*)d_in[2];
    const float* W2  = (const float*)d_in[3];
    const float* b2  = (const float*)d_in[4];
    const float* W3  = (const float*)d_in[5];
    const float* b3  = (const float*)d_in[6];
    const float* emb = (const float*)d_in[7];
    const float* dW1 = (const float*)d_in[8];
    const float* db1 = (const float*)d_in[9];
    const float* dW2 = (const float*)d_in[10];
    const float* db2 = (const float*)d_in[11];
    const float* pW  = (const float*)d_in[12];
    const float* pb  = (const float*)d_in[13];
    const float* wW  = (const float*)d_in[14];
    const float* wb  = (const float*)d_in[15];
    const float* aW  = (const float*)d_in[16];
    const float* ab  = (const float*)d_in[17];
    float* out = (float*)d_out;

    float *h1, *h2, *z, *zq, *d1, *d2, *ho, *counts, *loss, *enorm, *hw, *hb;
    int* idx;
    cudaGetSymbolAddress((void**)&h1, g_h1);
    cudaGetSymbolAddress((void**)&h2, g_h2);
    cudaGetSymbolAddress((void**)&z,  g_z);
    cudaGetSymbolAddress((void**)&zq, g_zq);
    cudaGetSymbolAddress((void**)&d1, g_d1);
    cudaGetSymbolAddress((void**)&d2, g_d2);
    cudaGetSymbolAddress((void**)&ho, g_ho);
    cudaGetSymbolAddress((void**)&idx, g_idx);
    cudaGetSymbolAddress((void**)&counts, g_counts);
    cudaGetSymbolAddress((void**)&loss, g_loss);
    cudaGetSymbolAddress((void**)&enorm, g_enorm);
    cudaGetSymbolAddress((void**)&hw, g_hw);
    cudaGetSymbolAddress((void**)&hb, g_hb);

    const int VQ_SMEM = (int)(2*64*(128+SPAD)*sizeof(float2) + 128*sizeof(float));
    cudaFuncSetAttribute(vq_argmin_mma, cudaFuncAttributeMaxDynamicSharedMemorySize, VQ_SMEM);

    // init scalars/counts + head-weight concat + codebook norms
    zero_kernel<<<(KCODES + 1 + 255)/256, 256>>>(counts, loss);
    concat_head<<<(HIDDEN*128 + 255)/256, 256>>>(pW, pb, wW, wb, aW, ab, hw, hb);
    enorm_kernel<<<(KCODES + 255)/256, 256>>>(emb, enorm);

    // encoder (tensor cores, split-TF32 for argmin safety)
    mma_gemm<ACT_LEAKY><<<dim3(256/128, BATCH/128), 256>>>(x,  W1, b1, h1, BATCH, 256, 784);
    mma_gemm<ACT_LEAKY><<<dim3(256/128, BATCH/128), 256>>>(h1, W2, b2, h2, BATCH, 256, 256);
    sgemm_smallN<ACT_NONE><<<BATCH/64, 256>>>(h2, W3, b3, z, BATCH, DLAT, 256);

    // VQ (tensor cores, split-TF32, fused argmin)
    vq_argmin_mma<<<BATCH/128, 256, VQ_SMEM>>>(z, emb, enorm, idx);
    vq_post<<<BATCH/256, 256>>>(z, emb, idx, zq, counts, loss, out + IDX_OFF);
    finalize_kernel<<<1, 256>>>(counts, loss, out);

    // decoder (tensor cores, 1x TF32 + cp.async pipeline)
    mma_gemm_1x<ACT_SELU><<<dim3(HIDDEN/128, BATCH/128), 256>>>(zq, dW1, db1, d1, BATCH, HIDDEN, DLAT);
    mma_gemm_1x<ACT_SELU><<<dim3(HIDDEN/128, BATCH/128), 256>>>(d1, dW2, db2, d2, BATCH, HIDDEN, HIDDEN);

    // head (1x TF32, N padded to 128)
    mma_gemm_1x<ACT_HEAD><<<dim3(1, BATCH/128), 256>>>(d2, hw, hb, ho, BATCH, 128, HIDDEN);

    // pack outputs
    pack_kernel<<<(BATCH*92 + 255)/256, 256>>>(ho, out);
}

// round 6
// speedup vs baseline: 1.2010x; 1.0152x over previous
#include <cuda_runtime.h>
#include <math.h>
#include <stdint.h>

// ---------------- problem constants ----------------
#define BATCH   32768
#define KCODES  4096
#define DLAT    64
#define HIDDEN  1024

// output layout (f32, reference return order, flattened+concat)
#define P_OFF    0
#define P_SIZE   (BATCH*40)
#define CP_OFF   (P_OFF + P_SIZE)
#define CP_SIZE  (BATCH*48)
#define W_OFF    (CP_OFF + CP_SIZE)
#define WA_SIZE  (BATCH*2)
#define A_OFF    (W_OFF + WA_SIZE)
#define LOSS_OFF (A_OFF + WA_SIZE)
#define IDX_OFF  (LOSS_OFF + 1)
#define PERP_OFF (IDX_OFF + BATCH)

#define SPAD 4
#define ESTRIDE (128+SPAD)

// ---------------- scratch (__device__ globals; no allocation allowed) ----------------
__device__ float  g_h1[BATCH*256];
__device__ float  g_h2[BATCH*256];
__device__ float  g_z [BATCH*DLAT];
__device__ float  g_zq[BATCH*DLAT];
__device__ float  g_d1[BATCH*HIDDEN];
__device__ float  g_d2[BATCH*HIDDEN];
__device__ float  g_ho[BATCH*128];        // head out, stride 128 (padded)
__device__ int    g_idx[BATCH];
__device__ float  g_counts[KCODES];
__device__ float  g_loss;
__device__ float  g_enorm[KCODES];
__device__ float  g_hw[HIDDEN*128];       // padded head weights [1024,128]
__device__ float  g_hb[128];
__device__ float2 g_W12[784*256];         // pre-split W1
__device__ float2 g_W22[256*256];         // pre-split W2
__device__ float2 g_embT[DLAT*KCODES];    // pre-split transposed codebook [d][k]

// ---------------- activations ----------------
#define ACT_NONE 0
#define ACT_LEAKY 1
#define ACT_SELU 2
#define ACT_HEAD 3

__device__ __forceinline__ float sigmoidf_(float x){ return 1.0f/(1.0f+expf(-x)); }

template<int ACT>
__device__ __forceinline__ float apply_act(float v, int col){
    if (ACT == ACT_LEAKY) return v > 0.0f ? v : 0.2f*v;
    if (ACT == ACT_SELU){
        const float a = 1.6732632423543772f, s = 1.0507009873554805f;
        return v > 0.0f ? s*v : s*a*(expf(v)-1.0f);
    }
    if (ACT == ACT_HEAD){
        if (col < 40) return tanhf(v)*12.0f + 14.0f;
        if (col < 42) return sigmoidf_(v)*2.0f + 1.0f;
        return sigmoidf_(v);
    }
    return v;
}

// ---------------- TF32 split helpers ----------------
__device__ __forceinline__ uint32_t tf32_of(float x){
    uint32_t r; asm("cvt.rna.tf32.f32 %0, %1;" : "=r"(r) : "f"(x)); return r;
}
__device__ __forceinline__ float2 split2(float x){
    uint32_t h = tf32_of(x);
    float hf = __uint_as_float(h);
    float lof = __uint_as_float(tf32_of(x - hf));
    return make_float2(hf, lof);
}

// D += A*B, m16n8k8 tf32
__device__ __forceinline__ void mma8(float* c, const uint32_t* a, const uint32_t* b){
    asm volatile(
        "mma.sync.aligned.m16n8k8.row.col.f32.tf32.tf32.f32 "
        "{%0,%1,%2,%3}, {%4,%5,%6,%7}, {%8,%9}, {%0,%1,%2,%3};\n"
        : "+f"(c[0]), "+f"(c[1]), "+f"(c[2]), "+f"(c[3])
        : "r"(a[0]), "r"(a[1]), "r"(a[2]), "r"(a[3]), "r"(b[0]), "r"(b[1]));
}

// ---------------- cp.async helpers ----------------
__device__ __forceinline__ void cpasync16(void* dst_smem, const void* src){
    uint32_t s = (uint32_t)__cvta_generic_to_shared(dst_smem);
    asm volatile("cp.async.cg.shared.global [%0], [%1], 16;\n" :: "r"(s), "l"(src));
}
__device__ __forceinline__ void cpasync_commit(){ asm volatile("cp.async.commit_group;\n"); }
template<int NN>
__device__ __forceinline__ void cpasync_wait(){ asm volatile("cp.async.wait_group %0;\n" :: "n"(NN)); }

// ---------------- elementwise split kernels ----------------
__global__ void split_arr(const float* __restrict__ src, float2* __restrict__ dst, int n4){
    int i = blockIdx.x * 256 + threadIdx.x;
    if (i >= n4) return;
    float4 v = ((const float4*)src)[i];
    float2 s0 = split2(v.x), s1 = split2(v.y), s2 = split2(v.z), s3 = split2(v.w);
    float4* d = (float4*)(dst + (size_t)i*4);
    d[0] = make_float4(s0.x, s0.y, s1.x, s1.y);
    d[1] = make_float4(s2.x, s2.y, s3.x, s3.y);
}

// emb [K][D] -> embT [D][K] split
__global__ void split_emb_T(const float* __restrict__ emb, float2* __restrict__ embT){
    int i = blockIdx.x * 256 + threadIdx.x;   // i = k*64 + d (coalesced read)
    if (i >= KCODES*DLAT) return;
    int k = i >> 6, d = i & 63;
    embT[(size_t)d*KCODES + k] = split2(emb[i]);
}

// ============================================================================
// 1x-TF32 GEMM (decoder + head): C = act(A[M,K] @ W[K,N] + bias)
// 128x128 tile, BK=16, 8 warps (2Mx4N), cp.async double-buffered.
// ============================================================================
#define AST 20
#define BST 136
template<int ACT>
__global__ void __launch_bounds__(256, 2) mma_gemm_1x(
    const float* __restrict__ A, const float* __restrict__ W,
    const float* __restrict__ bias, float* __restrict__ C,
    int M, int N, int K)
{
    __shared__ float As[2][128][AST];
    __shared__ float Bs[2][16][BST];

    const int tid  = threadIdx.x;
    const int lane = tid & 31, warp = tid >> 5;
    const int wm = (warp & 1) * 64, wn = (warp >> 1) * 32;
    const int bm = blockIdx.y * 128, bn = blockIdx.x * 128;
    const int g = lane >> 2, tg = lane & 3;

    float acc[4][4][4];
    #pragma unroll
    for (int i = 0; i < 4; i++)
        #pragma unroll
        for (int j = 0; j < 4; j++)
            #pragma unroll
            for (int q = 0; q < 4; q++) acc[i][j][q] = 0.0f;

    const int ar = tid >> 1, ac = (tid & 1) * 8;
    const int br = tid >> 4, bc = (tid & 15) * 8;
    const float* Ap = A + (size_t)(bm + ar) * K + ac;
    const float* Bp = W + (size_t)br * N + bn + bc;

    const int ntiles = K >> 4;

    #define COPY_TILE(kt, buf) do { \
        const float* ap = Ap + (size_t)(kt) * 16; \
        cpasync16(&As[buf][ar][ac],   ap); \
        cpasync16(&As[buf][ar][ac+4], ap + 4); \
        const float* bp = Bp + (size_t)(kt) * 16 * N; \
        cpasync16(&Bs[buf][br][bc],   bp); \
        cpasync16(&Bs[buf][br][bc+4], bp + 4); \
        cpasync_commit(); \
    } while (0)

    COPY_TILE(0, 0);

    for (int i = 0; i < ntiles; i++){
        int buf = i & 1;
        if (i + 1 < ntiles){
            COPY_TILE(i + 1, buf ^ 1);
            cpasync_wait<1>();
        } else {
            cpasync_wait<0>();
        }
        __syncthreads();

        #pragma unroll
        for (int ks = 0; ks < 16; ks += 8){
            uint32_t a[4][4];
            #pragma unroll
            for (int mt = 0; mt < 4; mt++){
                int m = wm + mt*16 + g;
                a[mt][0] = __float_as_uint(As[buf][m  ][ks+tg]);
                a[mt][1] = __float_as_uint(As[buf][m+8][ks+tg]);
                a[mt][2] = __float_as_uint(As[buf][m  ][ks+tg+4]);
                a[mt][3] = __float_as_uint(As[buf][m+8][ks+tg+4]);
            }
            #pragma unroll
            for (int nt = 0; nt < 4; nt++){
                int n = wn + nt*8 + g;
                uint32_t b[2] = { __float_as_uint(Bs[buf][ks+tg  ][n]),
                                  __float_as_uint(Bs[buf][ks+tg+4][n]) };
                #pragma unroll
                for (int mt = 0; mt < 4; mt++) mma8(acc[mt][nt], a[mt], b);
            }
        }
        __syncthreads();
    }
    #undef COPY_TILE

    // epilogue: bias + activation, 64-bit stores
    #pragma unroll
    for (int mt = 0; mt < 4; mt++){
        #pragma unroll
        for (int nt = 0; nt < 4; nt++){
            int row = bm + wm + mt*16 + g;
            int col = bn + wn + nt*8 + 2*tg;
            float bs0 = bias[col], bs1 = bias[col+1];
            float2 o0, o1;
            o0.x = apply_act<ACT>(acc[mt][nt][0] + bs0, col);
            o0.y = apply_act<ACT>(acc[mt][nt][1] + bs1, col+1);
            o1.x = apply_act<ACT>(acc[mt][nt][2] + bs0, col);
            o1.y = apply_act<ACT>(acc[mt][nt][3] + bs1, col+1);
            *(float2*)&C[(size_t)row*N + col]     = o0;
            *(float2*)&C[(size_t)(row+8)*N + col] = o1;
        }
    }
}

// ============================================================================
// split-3x GEMM, A split on-the-fly, B PRE-SPLIT (encoder)
// ============================================================================
template<int ACT>
__global__ void __launch_bounds__(256, 2) mma_gemm_sb(
    const float* __restrict__ A, const float2* __restrict__ B2,
    const float* __restrict__ bias, float* __restrict__ C,
    int M, int N, int K)
{
    __shared__ float2 As[16][128+SPAD];   // [k][m] = (hi, lo)
    __shared__ float2 Bs[16][128+SPAD];   // [k][n] = (hi, lo)

    const int tid  = threadIdx.x;
    const int lane = tid & 31, warp = tid >> 5;
    const int wm = (warp & 1) * 64, wn = (warp >> 1) * 32;
    const int bm = blockIdx.y * 128, bn = blockIdx.x * 128;
    const int g = lane >> 2, tg = lane & 3;

    float acc[4][4][4];
    #pragma unroll
    for (int i = 0; i < 4; i++)
        #pragma unroll
        for (int j = 0; j < 4; j++)
            #pragma unroll
            for (int q = 0; q < 4; q++) acc[i][j][q] = 0.0f;

    const int ar = tid >> 1, ac = (tid & 1) * 8;
    const int br = tid >> 4, bcf2 = (tid & 15) * 8;   // 8 float2 per thread per B row
    const float* Ap = A + (size_t)(bm + ar) * K + ac;

    for (int k0 = 0; k0 < K; k0 += 16){
        float4 av0 = *(const float4*)(Ap + k0);
        float4 av1 = *(const float4*)(Ap + k0 + 4);
        As[ac+0][ar] = split2(av0.x);
        As[ac+1][ar] = split2(av0.y);
        As[ac+2][ar] = split2(av0.z);
        As[ac+3][ar] = split2(av0.w);
        As[ac+4][ar] = split2(av1.x);
        As[ac+5][ar] = split2(av1.y);
        As[ac+6][ar] = split2(av1.z);
        As[ac+7][ar] = split2(av1.w);
        {
            const float4* bp = (const float4*)(B2 + (size_t)(k0 + br) * N + bn) + (tid & 15) * 4;
            float4 b0 = bp[0], b1 = bp[1], b2 = bp[2], b3 = bp[3];
            *(float4*)&Bs[br][bcf2+0] = b0;
            *(float4*)&Bs[br][bcf2+2] = b1;
            *(float4*)&Bs[br][bcf2+4] = b2;
            *(float4*)&Bs[br][bcf2+6] = b3;
        }
        __syncthreads();

        #pragma unroll
        for (int ks = 0; ks < 16; ks += 8){
            uint32_t ah[4][4], al[4][4];
            #pragma unroll
            for (int mt = 0; mt < 4; mt++){
                int m = wm + mt*16 + g;
                float2 v0 = As[ks+tg][m];
                float2 v1 = As[ks+tg][m+8];
                float2 v2 = As[ks+4+tg][m];
                float2 v3 = As[ks+4+tg][m+8];
                ah[mt][0] = __float_as_uint(v0.x);
                ah[mt][1] = __float_as_uint(v1.x);
                ah[mt][2] = __float_as_uint(v2.x);
                ah[mt][3] = __float_as_uint(v3.x);
                al[mt][0] = __float_as_uint(v0.y);
                al[mt][1] = __float_as_uint(v1.y);
                al[mt][2] = __float_as_uint(v2.y);
                al[mt][3] = __float_as_uint(v3.y);
            }
            #pragma unroll
            for (int nt = 0; nt < 4; nt++){
                int n = wn + nt*8 + g;
                float2 w0 = Bs[ks+tg][n];
                float2 w1 = Bs[ks+4+tg][n];
                uint32_t bh[2] = { __float_as_uint(w0.x), __float_as_uint(w1.x) };
                uint32_t bl[2] = { __float_as_uint(w0.y), __float_as_uint(w1.y) };
                #pragma unroll
                for (int mt = 0; mt < 4; mt++) mma8(acc[mt][nt], ah[mt], bh);
                #pragma unroll
                for (int mt = 0; mt < 4; mt++) mma8(acc[mt][nt], al[mt], bh);
                #pragma unroll
                for (int mt = 0; mt < 4; mt++) mma8(acc[mt][nt], ah[mt], bl);
            }
        }
        __syncthreads();
    }

    // epilogue: bias + activation, 64-bit stores
    #pragma unroll
    for (int mt = 0; mt < 4; mt++){
        #pragma unroll
        for (int nt = 0; nt < 4; nt++){
            int row = bm + wm + mt*16 + g;
            int col = bn + wn + nt*8 + 2*tg;
            float bs0 = bias[col], bs1 = bias[col+1];
            float2 o0, o1;
            o0.x = apply_act<ACT>(acc[mt][nt][0] + bs0, col);
            o0.y = apply_act<ACT>(acc[mt][nt][1] + bs1, col+1);
            o1.x = apply_act<ACT>(acc[mt][nt][2] + bs0, col);
            o1.y = apply_act<ACT>(acc[mt][nt][3] + bs1, col+1);
            *(float2*)&C[(size_t)row*N + col]     = o0;
            *(float2*)&C[(size_t)(row+8)*N + col] = o1;
        }
    }
}

// ---------------- small-N SGEMM: 64 rows x N(<=64) cols, BK=16, 4x4 microtile ----------------
template<int ACT>
__global__ void __launch_bounds__(256) sgemm_smallN(
    const float* __restrict__ A, const float* __restrict__ W,
    const float* __restrict__ bias, float* __restrict__ C,
    int M, int N, int K)
{
    __shared__ float As[16][64];
    __shared__ float Bs[16][64];
    const int tid = threadIdx.x;
    const int bm = blockIdx.x * 64;
    const int arow = tid >> 2,  acol = (tid & 3) * 4;
    const int bkr  = tid >> 4,  bcol = (tid & 15) * 4;
    const int ty = tid >> 4, tx = tid & 15;

    float acc[4][4];
    #pragma unroll
    for (int i = 0; i < 4; i++)
        #pragma unroll
        for (int j = 0; j < 4; j++) acc[i][j] = 0.0f;

    for (int k0 = 0; k0 < K; k0 += 16){
        float4 av = *(const float4*)(A + (size_t)(bm + arow) * K + k0 + acol);
        As[acol+0][arow] = av.x;
        As[acol+1][arow] = av.y;
        As[acol+2][arow] = av.z;
        As[acol+3][arow] = av.w;
        float4 bv = make_float4(0.f,0.f,0.f,0.f);
        if (bcol < N) bv = *(const float4*)(W + (size_t)(k0 + bkr) * N + bcol);
        *(float4*)&Bs[bkr][bcol] = bv;
        __syncthreads();
        #pragma unroll
        for (int kk = 0; kk < 16; kk++){
            float a[4], b[4];
            *(float4*)a = *(const float4*)&As[kk][ty*4];
            *(float4*)b = *(const float4*)&Bs[kk][tx*4];
            #pragma unroll
            for (int i = 0; i < 4; i++)
                #pragma unroll
                for (int j = 0; j < 4; j++)
                    acc[i][j] = fmaf(a[i], b[j], acc[i][j]);
        }
        __syncthreads();
    }

    if (tx*4 < N){
        float bsv[4];
        #pragma unroll
        for (int j = 0; j < 4; j++) bsv[j] = bias[tx*4 + j];
        #pragma unroll
        for (int i = 0; i < 4; i++){
            float4 v;
            v.x = apply_act<ACT>(acc[i][0] + bsv[0], tx*4+0);
            v.y = apply_act<ACT>(acc[i][1] + bsv[1], tx*4+1);
            v.z = apply_act<ACT>(acc[i][2] + bsv[2], tx*4+2);
            v.w = apply_act<ACT>(acc[i][3] + bsv[3], tx*4+3);
            *(float4*)(C + (size_t)(bm + ty*4 + i) * N + tx*4) = v;
        }
    }
}

// ---------------- codebook norms ----------------
__global__ void enorm_kernel(const float* __restrict__ emb, float* __restrict__ enorm){
    int k = blockIdx.x * 256 + threadIdx.x;
    if (k >= KCODES) return;
    const float4* e = (const float4*)(emb + (size_t)k * DLAT);
    float s = 0.0f;
    #pragma unroll
    for (int q = 0; q < 16; q++){
        float4 v = e[q];
        s += v.x*v.x + v.y*v.y + v.z*v.z + v.w*v.w;
    }
    enorm[k] = s;
}

// ---------------- VQ argmin v2: pre-split transposed codebook + cp.async ----------------
// smem: Zs [64][132] f2, Es [2][64][132] f2 (double-buffered)
__global__ void __launch_bounds__(256) vq_argmin_mma(
    const float* __restrict__ z, const float2* __restrict__ embT,
    const float* __restrict__ enorm, int* __restrict__ idx_out)
{
    extern __shared__ float2 sm2[];
    float2 (*Zs)[ESTRIDE] = (float2 (*)[ESTRIDE])sm2;
    float2* EsBase = sm2 + 64*ESTRIDE;
    #define ES(buf,k,n) EsBase[(buf)*64*ESTRIDE + (k)*ESTRIDE + (n)]

    const int tid  = threadIdx.x;
    const int lane = tid & 31, warp = tid >> 5;
    const int wm = (warp & 1) * 64, wn = (warp >> 1) * 32;
    const int bm = blockIdx.x * 128;
    const int g = lane >> 2, tg = lane & 3;

    // load z tile: [k][m] split form (once per block)
    const int zr = tid >> 1, zc = (tid & 1) * 32;
    {
        const float* Zp = z + (size_t)(bm + zr) * DLAT + zc;
        #pragma unroll
        for (int q = 0; q < 8; q++){
            float4 v = *(const float4*)(Zp + q*4);
            Zs[zc+q*4+0][zr] = split2(v.x);
            Zs[zc+q*4+1][zr] = split2(v.y);
            Zs[zc+q*4+2][zr] = split2(v.z);
            Zs[zc+q*4+3][zr] = split2(v.w);
        }
    }

    // chunk copy: 64 rows x 128 float2 = 4096 16B-units; 16 per thread
    #define COPY_ES(c0_, buf_) do { \
        _Pragma("unroll") \
        for (int j = 0; j < 16; j++){ \
            int unit = j*256 + tid; \
            int k_ = unit >> 6, u_ = unit & 63; \
            cpasync16(&ES(buf_, k_, u_*2), embT + (size_t)k_*KCODES + (c0_) + u_*2); \
        } \
        cpasync_commit(); \
    } while (0)

    float mv[8]; int mi[8];
    #pragma unroll
    for (int s = 0; s < 8; s++){ mv[s] = INFINITY; mi[s] = 0; }

    COPY_ES(0, 0);

    for (int ch = 0; ch < KCODES/128; ch++){
        int c0 = ch * 128;
        int buf = ch & 1;
        if (ch + 1 < KCODES/128){
            COPY_ES(c0 + 128, buf ^ 1);
            cpasync_wait<1>();
        } else {
            cpasync_wait<0>();
        }
        __syncthreads();

        float acc[4][4][4];
        #pragma unroll
        for (int i = 0; i < 4; i++)
            #pragma unroll
            for (int j = 0; j < 4; j++)
                #pragma unroll
                for (int q = 0; q < 4; q++) acc[i][j][q] = 0.0f;

        #pragma unroll
        for (int ks = 0; ks < DLAT; ks += 8){
            uint32_t ah[4][4], al[4][4];
            #pragma unroll
            for (int mt = 0; mt < 4; mt++){
                int m = wm + mt*16 + g;
                float2 v0 = Zs[ks+tg][m];
                float2 v1 = Zs[ks+tg][m+8];
                float2 v2 = Zs[ks+4+tg][m];
                float2 v3 = Zs[ks+4+tg][m+8];
                ah[mt][0] = __float_as_uint(v0.x);
                ah[mt][1] = __float_as_uint(v1.x);
                ah[mt][2] = __float_as_uint(v2.x);
                ah[mt][3] = __float_as_uint(v3.x);
                al[mt][0] = __float_as_uint(v0.y);
                al[mt][1] = __float_as_uint(v1.y);
                al[mt][2] = __float_as_uint(v2.y);
                al[mt][3] = __float_as_uint(v3.y);
            }
            #pragma unroll
            for (int nt = 0; nt < 4; nt++){
                int n = wn + nt*8 + g;
                float2 w0 = ES(buf, ks+tg,   n);
                float2 w1 = ES(buf, ks+4+tg, n);
                uint32_t bh[2] = { __float_as_uint(w0.x), __float_as_uint(w1.x) };
                uint32_t bl[2] = { __float_as_uint(w0.y), __float_as_uint(w1.y) };
                #pragma unroll
                for (int mt = 0; mt < 4; mt++) mma8(acc[mt][nt], ah[mt], bh);
                #pragma unroll
                for (int mt = 0; mt < 4; mt++) mma8(acc[mt][nt], al[mt], bh);
                #pragma unroll
                for (int mt = 0; mt < 4; mt++) mma8(acc[mt][nt], ah[mt], bl);
            }
        }

        // running argmin (ascending code order within thread; strict < keeps first min)
        #pragma unroll
        for (int nt = 0; nt < 4; nt++){
            int nc = wn + nt*8 + 2*tg;
            float e0 = __ldg(enorm + c0 + nc);
            float e1 = __ldg(enorm + c0 + nc + 1);
            int code = c0 + nc;
            #pragma unroll
            for (int mt = 0; mt < 4; mt++){
                float d00 = e0 - 2.0f*acc[mt][nt][0];
                float d01 = e1 - 2.0f*acc[mt][nt][1];
                float d10 = e0 - 2.0f*acc[mt][nt][2];
                float d11 = e1 - 2.0f*acc[mt][nt][3];
                int s0 = mt*2, s1 = mt*2 + 1;
                if (d00 < mv[s0]){ mv[s0] = d00; mi[s0] = code;   }
                if (d01 < mv[s0]){ mv[s0] = d01; mi[s0] = code+1; }
                if (d10 < mv[s1]){ mv[s1] = d10; mi[s1] = code;   }
                if (d11 < mv[s1]){ mv[s1] = d11; mi[s1] = code+1; }
            }
        }
        __syncthreads();
    }
    #undef COPY_ES

    float* rv = (float*)EsBase;           // 16 candidates x 128 rows
    int*   ri = ((int*)EsBase) + 16*128;
    int cand = (warp >> 1) * 4 + tg;      // 0..15
    #pragma unroll
    for (int s = 0; s < 8; s++){
        int r = wm + (s >> 1)*16 + g + (s & 1)*8;
        rv[cand*128 + r] = mv[s];
        ri[cand*128 + r] = mi[s];
    }
    __syncthreads();
    if (tid < 128){
        float bv = INFINITY; int bi = 0x7fffffff;
        #pragma unroll
        for (int t = 0; t < 16; t++){
            float v = rv[t*128 + tid];
            int c = ri[t*128 + tid];
            if (v < bv || (v == bv && c < bi)){ bv = v; bi = c; }
        }
        idx_out[bm + tid] = bi;
    }
    #undef ES
}

// ---------------- gather z_q, idx-as-float, counts, commit-loss partial sums ----------------
__global__ void vq_post(const float* __restrict__ z, const float* __restrict__ emb,
                        const int* __restrict__ idx, float* __restrict__ zq,
                        float* __restrict__ counts, float* __restrict__ loss,
                        float* __restrict__ out_idx)
{
    int b = blockIdx.x * 256 + threadIdx.x;
    int k = idx[b];
    const float4* e  = (const float4*)(emb + (size_t)k * DLAT);
    const float4* zz = (const float4*)(z   + (size_t)b * DLAT);
    float4*       zo = (float4*)(zq + (size_t)b * DLAT);
    float s = 0.0f;
    #pragma unroll
    for (int q = 0; q < 16; q++){
        float4 ev = e[q], zv = zz[q];
        float dx = ev.x - zv.x, dy = ev.y - zv.y, dz = ev.z - zv.z, dw = ev.w - zv.w;
        s += dx*dx + dy*dy + dz*dz + dw*dw;
        zo[q] = ev;
    }
    out_idx[b] = (float)k;
    atomicAdd(&counts[k], 1.0f);

    __shared__ float red[256];
    red[threadIdx.x] = s;
    __syncthreads();
    for (int off = 128; off > 0; off >>= 1){
        if (threadIdx.x < off) red[threadIdx.x] += red[threadIdx.x + off];
        __syncthreads();
    }
    if (threadIdx.x == 0) atomicAdd(loss, red[0]);
}

// ---------------- perplexity + vq_loss scalars ----------------
__global__ void finalize_kernel(const float* __restrict__ counts, const float* __restrict__ loss,
                                float* __restrict__ out)
{
    __shared__ float red[256];
    float s = 0.0f;
    for (int k = threadIdx.x; k < KCODES; k += 256){
        float p = counts[k] * (1.0f / (float)BATCH);
        s += p * logf(p + 1e-10f);
    }
    red[threadIdx.x] = s;
    __syncthreads();
    for (int off = 128; off > 0; off >>= 1){
        if (threadIdx.x < off) red[threadIdx.x] += red[threadIdx.x + off];
        __syncthreads();
    }
    if (threadIdx.x == 0){
        out[PERP_OFF] = expf(-red[0]);
        out[LOSS_OFF] = loss[0] * (0.25f / ((float)BATCH * (float)DLAT));
    }
}

// ---------------- zero counts + loss ----------------
__global__ void zero_kernel(float* __restrict__ counts, float* __restrict__ loss){
    int i = blockIdx.x * 256 + threadIdx.x;
    if (i < KCODES) counts[i] = 0.0f;
    if (i == KCODES) loss[0] = 0.0f;
}

// ---------------- concat head weights [pW|wW|aW|0pad] -> [1024,128], biases -> [128] ----------------
__global__ void concat_head(const float* __restrict__ pW, const float* __restrict__ pb,
                            const float* __restrict__ wW, const float* __restrict__ wb,
                            const float* __restrict__ aW, const float* __restrict__ ab,
                            float* __restrict__ hw, float* __restrict__ hb)
{
    int i = blockIdx.x * 256 + threadIdx.x;
    int total = HIDDEN * 128;
    if (i < total){
        int k = i >> 7, col = i & 127;
        float v = 0.0f;
        if (col < 40)      v = pW[k*40 + col];
        else if (col < 42) v = wW[k*2 + (col-40)];
        else if (col < 44) v = aW[k*2 + (col-42)];
        hw[i] = v;
    }
    if (i < 128){
        float v = 0.0f;
        if (i < 40)      v = pb[i];
        else if (i < 42) v = wb[i-40];
        else if (i < 44) v = ab[i-42];
        hb[i] = v;
    }
}

// ---------------- pack outputs: points / control_points / widths / alphas ----------------
__global__ void pack_kernel(const float* __restrict__ ho, float* __restrict__ out){
    int gid = blockIdx.x * 256 + threadIdx.x;
    int b = gid / 92, e = gid % 92;
    if (b >= BATCH) return;
    const float* h = ho + (size_t)b * 128;
    if (e < 40){
        out[P_OFF + (size_t)b*40 + e] = h[e];
    } else if (e < 88){
        int e2 = e - 40;
        int c  = e2 & 1;
        int j  = (e2 >> 1) & 3;
        int sg = (e2 >> 3) % 3;
        int p  = e2 / 24;
        out[CP_OFF + (size_t)b*48 + e2] = h[p*20 + (3*sg + j)*2 + c];
    } else if (e < 90){
        int p = e - 88;
        out[W_OFF + (size_t)b*2 + p] = h[40 + p];
    } else {
        int p = e - 90;
        out[A_OFF + (size_t)b*2 + p] = h[42 + p];
    }
}

// ---------------- launch ----------------
extern "C" void kernel_launch(void* const* d_in, const int* in_sizes, int n_in,
                              void* d_out, int out_size)
{
    (void)in_sizes; (void)n_in; (void)out_size;
    const float* x   = (const float*)d_in[0];
    const float* W1  = (const float*)d_in[1];
    const float* b1  = (const float*)d_in[2];
    const float* W2  = (const float*)d_in[3];
    const float* b2  = (const float*)d_in[4];
    const float* W3  = (const float*)d_in[5];
    const float* b3  = (const float*)d_in[6];
    const float* emb = (const float*)d_in[7];
    const float* dW1 = (const float*)d_in[8];
    const float* db1 = (const float*)d_in[9];
    const float* dW2 = (const float*)d_in[10];
    const float* db2 = (const float*)d_in[11];
    const float* pW  = (const float*)d_in[12];
    const float* pb  = (const float*)d_in[13];
    const float* wW  = (const float*)d_in[14];
    const float* wb  = (const float*)d_in[15];
    const float* aW  = (const float*)d_in[16];
    const float* ab  = (const float*)d_in[17];
    float* out = (float*)d_out;

    float *h1, *h2, *z, *zq, *d1, *d2, *ho, *counts, *loss, *enorm, *hw, *hb;
    float2 *W12, *W22, *embT;
    int* idx;
    cudaGetSymbolAddress((void**)&h1, g_h1);
    cudaGetSymbolAddress((void**)&h2, g_h2);
    cudaGetSymbolAddress((void**)&z,  g_z);
    cudaGetSymbolAddress((void**)&zq, g_zq);
    cudaGetSymbolAddress((void**)&d1, g_d1);
    cudaGetSymbolAddress((void**)&d2, g_d2);
    cudaGetSymbolAddress((void**)&ho, g_ho);
    cudaGetSymbolAddress((void**)&idx, g_idx);
    cudaGetSymbolAddress((void**)&counts, g_counts);
    cudaGetSymbolAddress((void**)&loss, g_loss);
    cudaGetSymbolAddress((void**)&enorm, g_enorm);
    cudaGetSymbolAddress((void**)&hw, g_hw);
    cudaGetSymbolAddress((void**)&hb, g_hb);
    cudaGetSymbolAddress((void**)&W12, g_W12);
    cudaGetSymbolAddress((void**)&W22, g_W22);
    cudaGetSymbolAddress((void**)&embT, g_embT);

    const int VQ_SMEM = (int)(3*64*ESTRIDE*sizeof(float2));   // Zs + 2x Es = 202752 B
    cudaFuncSetAttribute(vq_argmin_mma, cudaFuncAttributeMaxDynamicSharedMemorySize, VQ_SMEM);

    // init scalars/counts + head-weight concat + codebook norms + pre-splits
    zero_kernel<<<(KCODES + 1 + 255)/256, 256>>>(counts, loss);
    concat_head<<<(HIDDEN*128 + 255)/256, 256>>>(pW, pb, wW, wb, aW, ab, hw, hb);
    enorm_kernel<<<(KCODES + 255)/256, 256>>>(emb, enorm);
    split_arr<<<(784*256/4 + 255)/256, 256>>>(W1, W12, 784*256/4);
    split_arr<<<(256*256/4 + 255)/256, 256>>>(W2, W22, 256*256/4);
    split_emb_T<<<(KCODES*DLAT + 255)/256, 256>>>(emb, embT);

    // encoder (split-3x tensor cores, B pre-split)
    mma_gemm_sb<ACT_LEAKY><<<dim3(2, BATCH/128), 256>>>(x,  W12, b1, h1, BATCH, 256, 784);
    mma_gemm_sb<ACT_LEAKY><<<dim3(2, BATCH/128), 256>>>(h1, W22, b2, h2, BATCH, 256, 256);
    sgemm_smallN<ACT_NONE><<<BATCH/64, 256>>>(h2, W3, b3, z, BATCH, DLAT, 256);

    // VQ (split-3x, pre-split transposed codebook, cp.async double-buffered)
    vq_argmin_mma<<<BATCH/128, 256, VQ_SMEM>>>(z, embT, enorm, idx);
    vq_post<<<BATCH/256, 256>>>(z, emb, idx, zq, counts, loss, out + IDX_OFF);
    finalize_kernel<<<1, 256>>>(counts, loss, out);

    // decoder (tensor cores, 1x TF32 + cp.async pipeline)
    mma_gemm_1x<ACT_SELU><<<dim3(HIDDEN/128, BATCH/128), 256>>>(zq, dW1, db1, d1, BATCH, HIDDEN, DLAT);
    mma_gemm_1x<ACT_SELU><<<dim3(HIDDEN/128, BATCH/128), 256>>>(d1, dW2, db2, d2, BATCH, HIDDEN, HIDDEN);

    // head (1x TF32, N padded to 128)
    mma_gemm_1x<ACT_HEAD><<<dim3(1, BATCH/128), 256>>>(d2, hw, hb, ho, BATCH, 128, HIDDEN);

    // pack outputs
    pack_kernel<<<(BATCH*92 + 255)/256, 256>>>(ho, out);
}

// round 7
// speedup vs baseline: 1.2653x; 1.0536x over previous
#include <cuda_runtime.h>
#include <math.h>
#include <stdint.h>

// ---------------- problem constants ----------------
#define BATCH   32768
#define KCODES  4096
#define DLAT    64
#define HIDDEN  1024

// output layout (f32, reference return order, flattened+concat)
#define P_OFF    0
#define P_SIZE   (BATCH*40)
#define CP_OFF   (P_OFF + P_SIZE)
#define CP_SIZE  (BATCH*48)
#define W_OFF    (CP_OFF + CP_SIZE)
#define WA_SIZE  (BATCH*2)
#define A_OFF    (W_OFF + WA_SIZE)
#define LOSS_OFF (A_OFF + WA_SIZE)
#define IDX_OFF  (LOSS_OFF + 1)
#define PERP_OFF (IDX_OFF + BATCH)

#define SPAD 4
#define ESTRIDE (128+SPAD)

// ---------------- scratch (__device__ globals; no allocation allowed) ----------------
__device__ float  g_h1[BATCH*256];
__device__ float  g_h2[BATCH*256];
__device__ float  g_z [BATCH*DLAT];
__device__ float  g_zq[BATCH*DLAT];
__device__ float  g_d1[BATCH*HIDDEN];
__device__ float  g_d2[BATCH*HIDDEN];
__device__ float  g_ho[BATCH*128];        // head out, stride 128 (padded)
__device__ int    g_idx[BATCH];
__device__ float  g_counts[KCODES];
__device__ float  g_loss;
__device__ float  g_enorm[KCODES];
__device__ float  g_hw[HIDDEN*128];       // padded head weights [1024,128]
__device__ float  g_hb[128];
__device__ float2 g_W12[784*256];         // pre-split W1
__device__ float2 g_W22[256*256];         // pre-split W2
__device__ float2 g_embT[DLAT*KCODES];    // pre-split transposed codebook [d][k]

// ---------------- activations ----------------
#define ACT_NONE 0
#define ACT_LEAKY 1
#define ACT_SELU 2
#define ACT_HEAD 3

__device__ __forceinline__ float sigmoidf_(float x){ return 1.0f/(1.0f+expf(-x)); }

template<int ACT>
__device__ __forceinline__ float apply_act(float v, int col){
    if (ACT == ACT_LEAKY) return v > 0.0f ? v : 0.2f*v;
    if (ACT == ACT_SELU){
        const float a = 1.6732632423543772f, s = 1.0507009873554805f;
        return v > 0.0f ? s*v : s*a*(expf(v)-1.0f);
    }
    if (ACT == ACT_HEAD){
        if (col < 40) return tanhf(v)*12.0f + 14.0f;
        if (col < 42) return sigmoidf_(v)*2.0f + 1.0f;
        return sigmoidf_(v);
    }
    return v;
}

// ---------------- TF32 split helpers ----------------
__device__ __forceinline__ uint32_t tf32_of(float x){
    uint32_t r; asm("cvt.rna.tf32.f32 %0, %1;" : "=r"(r) : "f"(x)); return r;
}
__device__ __forceinline__ float2 split2(float x){
    uint32_t h = tf32_of(x);
    float hf = __uint_as_float(h);
    float lof = __uint_as_float(tf32_of(x - hf));
    return make_float2(hf, lof);
}
// in-register split to uint32 pair
__device__ __forceinline__ void split_u(float x, uint32_t& hi, uint32_t& lo){
    hi = tf32_of(x);
    lo = tf32_of(x - __uint_as_float(hi));
}

// D += A*B, m16n8k8 tf32
__device__ __forceinline__ void mma8(float* c, const uint32_t* a, const uint32_t* b){
    asm volatile(
        "mma.sync.aligned.m16n8k8.row.col.f32.tf32.tf32.f32 "
        "{%0,%1,%2,%3}, {%4,%5,%6,%7}, {%8,%9}, {%0,%1,%2,%3};\n"
        : "+f"(c[0]), "+f"(c[1]), "+f"(c[2]), "+f"(c[3])
        : "r"(a[0]), "r"(a[1]), "r"(a[2]), "r"(a[3]), "r"(b[0]), "r"(b[1]));
}

// ---------------- cp.async helpers ----------------
__device__ __forceinline__ void cpasync16(void* dst_smem, const void* src){
    uint32_t s = (uint32_t)__cvta_generic_to_shared(dst_smem);
    asm volatile("cp.async.cg.shared.global [%0], [%1], 16;\n" :: "r"(s), "l"(src));
}
__device__ __forceinline__ void cpasync_commit(){ asm volatile("cp.async.commit_group;\n"); }
template<int NN>
__device__ __forceinline__ void cpasync_wait(){ asm volatile("cp.async.wait_group %0;\n" :: "n"(NN)); }

// ---------------- elementwise split kernels ----------------
__global__ void split_arr(const float* __restrict__ src, float2* __restrict__ dst, int n4){
    int i = blockIdx.x * 256 + threadIdx.x;
    if (i >= n4) return;
    float4 v = ((const float4*)src)[i];
    float2 s0 = split2(v.x), s1 = split2(v.y), s2 = split2(v.z), s3 = split2(v.w);
    float4* d = (float4*)(dst + (size_t)i*4);
    d[0] = make_float4(s0.x, s0.y, s1.x, s1.y);
    d[1] = make_float4(s2.x, s2.y, s3.x, s3.y);
}

// emb [K][D] -> embT [D][K] split
__global__ void split_emb_T(const float* __restrict__ emb, float2* __restrict__ embT){
    int i = blockIdx.x * 256 + threadIdx.x;   // i = k*64 + d (coalesced read)
    if (i >= KCODES*DLAT) return;
    int k = i >> 6, d = i & 63;
    embT[(size_t)d*KCODES + k] = split2(emb[i]);
}

// ============================================================================
// 1x-TF32 GEMM (decoder + head): C = act(A[M,K] @ W[K,N] + bias)
// 128x128 tile, BK=16, 8 warps (2Mx4N), cp.async double-buffered.
// ============================================================================
#define AST 20
#define BST 136
template<int ACT>
__global__ void __launch_bounds__(256, 2) mma_gemm_1x(
    const float* __restrict__ A, const float* __restrict__ W,
    const float* __restrict__ bias, float* __restrict__ C,
    int M, int N, int K)
{
    __shared__ float As[2][128][AST];
    __shared__ float Bs[2][16][BST];

    const int tid  = threadIdx.x;
    const int lane = tid & 31, warp = tid >> 5;
    const int wm = (warp & 1) * 64, wn = (warp >> 1) * 32;
    const int bm = blockIdx.y * 128, bn = blockIdx.x * 128;
    const int g = lane >> 2, tg = lane & 3;

    float acc[4][4][4];
    #pragma unroll
    for (int i = 0; i < 4; i++)
        #pragma unroll
        for (int j = 0; j < 4; j++)
            #pragma unroll
            for (int q = 0; q < 4; q++) acc[i][j][q] = 0.0f;

    const int ar = tid >> 1, ac = (tid & 1) * 8;
    const int br = tid >> 4, bc = (tid & 15) * 8;
    const float* Ap = A + (size_t)(bm + ar) * K + ac;
    const float* Bp = W + (size_t)br * N + bn + bc;

    const int ntiles = K >> 4;

    #define COPY_TILE(kt, buf) do { \
        const float* ap = Ap + (size_t)(kt) * 16; \
        cpasync16(&As[buf][ar][ac],   ap); \
        cpasync16(&As[buf][ar][ac+4], ap + 4); \
        const float* bp = Bp + (size_t)(kt) * 16 * N; \
        cpasync16(&Bs[buf][br][bc],   bp); \
        cpasync16(&Bs[buf][br][bc+4], bp + 4); \
        cpasync_commit(); \
    } while (0)

    COPY_TILE(0, 0);

    for (int i = 0; i < ntiles; i++){
        int buf = i & 1;
        if (i + 1 < ntiles){
            COPY_TILE(i + 1, buf ^ 1);
            cpasync_wait<1>();
        } else {
            cpasync_wait<0>();
        }
        __syncthreads();

        #pragma unroll
        for (int ks = 0; ks < 16; ks += 8){
            uint32_t a[4][4];
            #pragma unroll
            for (int mt = 0; mt < 4; mt++){
                int m = wm + mt*16 + g;
                a[mt][0] = __float_as_uint(As[buf][m  ][ks+tg]);
                a[mt][1] = __float_as_uint(As[buf][m+8][ks+tg]);
                a[mt][2] = __float_as_uint(As[buf][m  ][ks+tg+4]);
                a[mt][3] = __float_as_uint(As[buf][m+8][ks+tg+4]);
            }
            #pragma unroll
            for (int nt = 0; nt < 4; nt++){
                int n = wn + nt*8 + g;
                uint32_t b[2] = { __float_as_uint(Bs[buf][ks+tg  ][n]),
                                  __float_as_uint(Bs[buf][ks+tg+4][n]) };
                #pragma unroll
                for (int mt = 0; mt < 4; mt++) mma8(acc[mt][nt], a[mt], b);
            }
        }
        __syncthreads();
    }
    #undef COPY_TILE

    // epilogue: bias + activation, 64-bit stores
    #pragma unroll
    for (int mt = 0; mt < 4; mt++){
        #pragma unroll
        for (int nt = 0; nt < 4; nt++){
            int row = bm + wm + mt*16 + g;
            int col = bn + wn + nt*8 + 2*tg;
            float bs0 = bias[col], bs1 = bias[col+1];
            float2 o0, o1;
            o0.x = apply_act<ACT>(acc[mt][nt][0] + bs0, col);
            o0.y = apply_act<ACT>(acc[mt][nt][1] + bs1, col+1);
            o1.x = apply_act<ACT>(acc[mt][nt][2] + bs0, col);
            o1.y = apply_act<ACT>(acc[mt][nt][3] + bs1, col+1);
            *(float2*)&C[(size_t)row*N + col]     = o0;
            *(float2*)&C[(size_t)(row+8)*N + col] = o1;
        }
    }
}

// ============================================================================
// split-3x GEMM v2 (encoder): cp.async double-buffered pipeline.
// A staged RAW fp32 in smem [m][k] (stride 20, conflict-free), split
// in-register at fragment load; B pre-split float2.
// Numerically identical to previous split-3x (same split values, same
// MMA order).
// ============================================================================
template<int ACT>
__global__ void __launch_bounds__(256, 2) mma_gemm_sb2(
    const float* __restrict__ A, const float2* __restrict__ B2,
    const float* __restrict__ bias, float* __restrict__ C,
    int M, int N, int K)
{
    __shared__ float  As[2][128][AST];          // raw fp32
    __shared__ float2 Bs[2][16][128+SPAD];      // pre-split (hi,lo)

    const int tid  = threadIdx.x;
    const int lane = tid & 31, warp = tid >> 5;
    const int wm = (warp & 1) * 64, wn = (warp >> 1) * 32;
    const int bm = blockIdx.y * 128, bn = blockIdx.x * 128;
    const int g = lane >> 2, tg = lane & 3;

    float acc[4][4][4];
    #pragma unroll
    for (int i = 0; i < 4; i++)
        #pragma unroll
        for (int j = 0; j < 4; j++)
            #pragma unroll
            for (int q = 0; q < 4; q++) acc[i][j][q] = 0.0f;

    const int ar = tid >> 1, ac = (tid & 1) * 8;
    const int br = tid >> 4, bcf2 = (tid & 15) * 8;   // 8 float2 per thread
    const float*  Ap = A  + (size_t)(bm + ar) * K + ac;
    const float2* Bp = B2 + (size_t)br * N + bn + bcf2;

    const int ntiles = K >> 4;

    #define COPY_SB(kt, buf) do { \
        const float* ap = Ap + (size_t)(kt) * 16; \
        cpasync16(&As[buf][ar][ac],   ap); \
        cpasync16(&As[buf][ar][ac+4], ap + 4); \
        const float2* bp = Bp + (size_t)(kt) * 16 * N; \
        cpasync16(&Bs[buf][br][bcf2+0], bp); \
        cpasync16(&Bs[buf][br][bcf2+2], bp + 2); \
        cpasync16(&Bs[buf][br][bcf2+4], bp + 4); \
        cpasync16(&Bs[buf][br][bcf2+6], bp + 6); \
        cpasync_commit(); \
    } while (0)

    COPY_SB(0, 0);

    for (int i = 0; i < ntiles; i++){
        int buf = i & 1;
        if (i + 1 < ntiles){
            COPY_SB(i + 1, buf ^ 1);
            cpasync_wait<1>();
        } else {
            cpasync_wait<0>();
        }
        __syncthreads();

        #pragma unroll
        for (int ks = 0; ks < 16; ks += 8){
            uint32_t ah[4][4], al[4][4];
            #pragma unroll
            for (int mt = 0; mt < 4; mt++){
                int m = wm + mt*16 + g;
                float a0 = As[buf][m  ][ks+tg];
                float a1 = As[buf][m+8][ks+tg];
                float a2 = As[buf][m  ][ks+tg+4];
                float a3 = As[buf][m+8][ks+tg+4];
                split_u(a0, ah[mt][0], al[mt][0]);
                split_u(a1, ah[mt][1], al[mt][1]);
                split_u(a2, ah[mt][2], al[mt][2]);
                split_u(a3, ah[mt][3], al[mt][3]);
            }
            #pragma unroll
            for (int nt = 0; nt < 4; nt++){
                int n = wn + nt*8 + g;
                float2 w0 = Bs[buf][ks+tg  ][n];
                float2 w1 = Bs[buf][ks+tg+4][n];
                uint32_t bh[2] = { __float_as_uint(w0.x), __float_as_uint(w1.x) };
                uint32_t bl[2] = { __float_as_uint(w0.y), __float_as_uint(w1.y) };
                #pragma unroll
                for (int mt = 0; mt < 4; mt++) mma8(acc[mt][nt], ah[mt], bh);
                #pragma unroll
                for (int mt = 0; mt < 4; mt++) mma8(acc[mt][nt], al[mt], bh);
                #pragma unroll
                for (int mt = 0; mt < 4; mt++) mma8(acc[mt][nt], ah[mt], bl);
            }
        }
        __syncthreads();
    }
    #undef COPY_SB

    // epilogue: bias + activation, 64-bit stores
    #pragma unroll
    for (int mt = 0; mt < 4; mt++){
        #pragma unroll
        for (int nt = 0; nt < 4; nt++){
            int row = bm + wm + mt*16 + g;
            int col = bn + wn + nt*8 + 2*tg;
            float bs0 = bias[col], bs1 = bias[col+1];
            float2 o0, o1;
            o0.x = apply_act<ACT>(acc[mt][nt][0] + bs0, col);
            o0.y = apply_act<ACT>(acc[mt][nt][1] + bs1, col+1);
            o1.x = apply_act<ACT>(acc[mt][nt][2] + bs0, col);
            o1.y = apply_act<ACT>(acc[mt][nt][3] + bs1, col+1);
            *(float2*)&C[(size_t)row*N + col]     = o0;
            *(float2*)&C[(size_t)(row+8)*N + col] = o1;
        }
    }
}

// ---------------- small-N SGEMM: 64 rows x N(<=64) cols, BK=16, 4x4 microtile ----------------
template<int ACT>
__global__ void __launch_bounds__(256) sgemm_smallN(
    const float* __restrict__ A, const float* __restrict__ W,
    const float* __restrict__ bias, float* __restrict__ C,
    int M, int N, int K)
{
    __shared__ float As[16][64];
    __shared__ float Bs[16][64];
    const int tid = threadIdx.x;
    const int bm = blockIdx.x * 64;
    const int arow = tid >> 2,  acol = (tid & 3) * 4;
    const int bkr  = tid >> 4,  bcol = (tid & 15) * 4;
    const int ty = tid >> 4, tx = tid & 15;

    float acc[4][4];
    #pragma unroll
    for (int i = 0; i < 4; i++)
        #pragma unroll
        for (int j = 0; j < 4; j++) acc[i][j] = 0.0f;

    for (int k0 = 0; k0 < K; k0 += 16){
        float4 av = *(const float4*)(A + (size_t)(bm + arow) * K + k0 + acol);
        As[acol+0][arow] = av.x;
        As[acol+1][arow] = av.y;
        As[acol+2][arow] = av.z;
        As[acol+3][arow] = av.w;
        float4 bv = make_float4(0.f,0.f,0.f,0.f);
        if (bcol < N) bv = *(const float4*)(W + (size_t)(k0 + bkr) * N + bcol);
        *(float4*)&Bs[bkr][bcol] = bv;
        __syncthreads();
        #pragma unroll
        for (int kk = 0; kk < 16; kk++){
            float a[4], b[4];
            *(float4*)a = *(const float4*)&As[kk][ty*4];
            *(float4*)b = *(const float4*)&Bs[kk][tx*4];
            #pragma unroll
            for (int i = 0; i < 4; i++)
                #pragma unroll
                for (int j = 0; j < 4; j++)
                    acc[i][j] = fmaf(a[i], b[j], acc[i][j]);
        }
        __syncthreads();
    }

    if (tx*4 < N){
        float bsv[4];
        #pragma unroll
        for (int j = 0; j < 4; j++) bsv[j] = bias[tx*4 + j];
        #pragma unroll
        for (int i = 0; i < 4; i++){
            float4 v;
            v.x = apply_act<ACT>(acc[i][0] + bsv[0], tx*4+0);
            v.y = apply_act<ACT>(acc[i][1] + bsv[1], tx*4+1);
            v.z = apply_act<ACT>(acc[i][2] + bsv[2], tx*4+2);
            v.w = apply_act<ACT>(acc[i][3] + bsv[3], tx*4+3);
            *(float4*)(C + (size_t)(bm + ty*4 + i) * N + tx*4) = v;
        }
    }
}

// ---------------- codebook norms ----------------
__global__ void enorm_kernel(const float* __restrict__ emb, float* __restrict__ enorm){
    int k = blockIdx.x * 256 + threadIdx.x;
    if (k >= KCODES) return;
    const float4* e = (const float4*)(emb + (size_t)k * DLAT);
    float s = 0.0f;
    #pragma unroll
    for (int q = 0; q < 16; q++){
        float4 v = e[q];
        s += v.x*v.x + v.y*v.y + v.z*v.z + v.w*v.w;
    }
    enorm[k] = s;
}

// ---------------- VQ argmin v2: pre-split transposed codebook + cp.async ----------------
__global__ void __launch_bounds__(256) vq_argmin_mma(
    const float* __restrict__ z, const float2* __restrict__ embT,
    const float* __restrict__ enorm, int* __restrict__ idx_out)
{
    extern __shared__ float2 sm2[];
    float2 (*Zs)[ESTRIDE] = (float2 (*)[ESTRIDE])sm2;
    float2* EsBase = sm2 + 64*ESTRIDE;
    #define ES(buf,k,n) EsBase[(buf)*64*ESTRIDE + (k)*ESTRIDE + (n)]

    const int tid  = threadIdx.x;
    const int lane = tid & 31, warp = tid >> 5;
    const int wm = (warp & 1) * 64, wn = (warp >> 1) * 32;
    const int bm = blockIdx.x * 128;
    const int g = lane >> 2, tg = lane & 3;

    // load z tile: [k][m] split form (once per block)
    const int zr = tid >> 1, zc = (tid & 1) * 32;
    {
        const float* Zp = z + (size_t)(bm + zr) * DLAT + zc;
        #pragma unroll
        for (int q = 0; q < 8; q++){
            float4 v = *(const float4*)(Zp + q*4);
            Zs[zc+q*4+0][zr] = split2(v.x);
            Zs[zc+q*4+1][zr] = split2(v.y);
            Zs[zc+q*4+2][zr] = split2(v.z);
            Zs[zc+q*4+3][zr] = split2(v.w);
        }
    }

    #define COPY_ES(c0_, buf_) do { \
        _Pragma("unroll") \
        for (int j = 0; j < 16; j++){ \
            int unit = j*256 + tid; \
            int k_ = unit >> 6, u_ = unit & 63; \
            cpasync16(&ES(buf_, k_, u_*2), embT + (size_t)k_*KCODES + (c0_) + u_*2); \
        } \
        cpasync_commit(); \
    } while (0)

    float mv[8]; int mi[8];
    #pragma unroll
    for (int s = 0; s < 8; s++){ mv[s] = INFINITY; mi[s] = 0; }

    COPY_ES(0, 0);

    for (int ch = 0; ch < KCODES/128; ch++){
        int c0 = ch * 128;
        int buf = ch & 1;
        if (ch + 1 < KCODES/128){
            COPY_ES(c0 + 128, buf ^ 1);
            cpasync_wait<1>();
        } else {
            cpasync_wait<0>();
        }
        __syncthreads();

        float acc[4][4][4];
        #pragma unroll
        for (int i = 0; i < 4; i++)
            #pragma unroll
            for (int j = 0; j < 4; j++)
                #pragma unroll
                for (int q = 0; q < 4; q++) acc[i][j][q] = 0.0f;

        #pragma unroll
        for (int ks = 0; ks < DLAT; ks += 8){
            uint32_t ah[4][4], al[4][4];
            #pragma unroll
            for (int mt = 0; mt < 4; mt++){
                int m = wm + mt*16 + g;
                float2 v0 = Zs[ks+tg][m];
                float2 v1 = Zs[ks+tg][m+8];
                float2 v2 = Zs[ks+4+tg][m];
                float2 v3 = Zs[ks+4+tg][m+8];
                ah[mt][0] = __float_as_uint(v0.x);
                ah[mt][1] = __float_as_uint(v1.x);
                ah[mt][2] = __float_as_uint(v2.x);
                ah[mt][3] = __float_as_uint(v3.x);
                al[mt][0] = __float_as_uint(v0.y);
                al[mt][1] = __float_as_uint(v1.y);
                al[mt][2] = __float_as_uint(v2.y);
                al[mt][3] = __float_as_uint(v3.y);
            }
            #pragma unroll
            for (int nt = 0; nt < 4; nt++){
                int n = wn + nt*8 + g;
                float2 w0 = ES(buf, ks+tg,   n);
                float2 w1 = ES(buf, ks+4+tg, n);
                uint32_t bh[2] = { __float_as_uint(w0.x), __float_as_uint(w1.x) };
                uint32_t bl[2] = { __float_as_uint(w0.y), __float_as_uint(w1.y) };
                #pragma unroll
                for (int mt = 0; mt < 4; mt++) mma8(acc[mt][nt], ah[mt], bh);
                #pragma unroll
                for (int mt = 0; mt < 4; mt++) mma8(acc[mt][nt], al[mt], bh);
                #pragma unroll
                for (int mt = 0; mt < 4; mt++) mma8(acc[mt][nt], ah[mt], bl);
            }
        }

        // running argmin (ascending code order within thread; strict < keeps first min)
        #pragma unroll
        for (int nt = 0; nt < 4; nt++){
            int nc = wn + nt*8 + 2*tg;
            float e0 = __ldg(enorm + c0 + nc);
            float e1 = __ldg(enorm + c0 + nc + 1);
            int code = c0 + nc;
            #pragma unroll
            for (int mt = 0; mt < 4; mt++){
                float d00 = e0 - 2.0f*acc[mt][nt][0];
                float d01 = e1 - 2.0f*acc[mt][nt][1];
                float d10 = e0 - 2.0f*acc[mt][nt][2];
                float d11 = e1 - 2.0f*acc[mt][nt][3];
                int s0 = mt*2, s1 = mt*2 + 1;
                if (d00 < mv[s0]){ mv[s0] = d00; mi[s0] = code;   }
                if (d01 < mv[s0]){ mv[s0] = d01; mi[s0] = code+1; }
                if (d10 < mv[s1]){ mv[s1] = d10; mi[s1] = code;   }
                if (d11 < mv[s1]){ mv[s1] = d11; mi[s1] = code+1; }
            }
        }
        __syncthreads();
    }
    #undef COPY_ES

    float* rv = (float*)EsBase;           // 16 candidates x 128 rows
    int*   ri = ((int*)EsBase) + 16*128;
    int cand = (warp >> 1) * 4 + tg;      // 0..15
    #pragma unroll
    for (int s = 0; s < 8; s++){
        int r = wm + (s >> 1)*16 + g + (s & 1)*8;
        rv[cand*128 + r] = mv[s];
        ri[cand*128 + r] = mi[s];
    }
    __syncthreads();
    if (tid < 128){
        float bv = INFINITY; int bi = 0x7fffffff;
        #pragma unroll
        for (int t = 0; t < 16; t++){
            float v = rv[t*128 + tid];
            int c = ri[t*128 + tid];
            if (v < bv || (v == bv && c < bi)){ bv = v; bi = c; }
        }
        idx_out[bm + tid] = bi;
    }
    #undef ES
}

// ---------------- gather z_q, idx-as-float, counts, commit-loss partial sums ----------------
__global__ void vq_post(const float* __restrict__ z, const float* __restrict__ emb,
                        const int* __restrict__ idx, float* __restrict__ zq,
                        float* __restrict__ counts, float* __restrict__ loss,
                        float* __restrict__ out_idx)
{
    int b = blockIdx.x * 256 + threadIdx.x;
    int k = idx[b];
    const float4* e  = (const float4*)(emb + (size_t)k * DLAT);
    const float4* zz = (const float4*)(z   + (size_t)b * DLAT);
    float4*       zo = (float4*)(zq + (size_t)b * DLAT);
    float s = 0.0f;
    #pragma unroll
    for (int q = 0; q < 16; q++){
        float4 ev = e[q], zv = zz[q];
        float dx = ev.x - zv.x, dy = ev.y - zv.y, dz = ev.z - zv.z, dw = ev.w - zv.w;
        s += dx*dx + dy*dy + dz*dz + dw*dw;
        zo[q] = ev;
    }
    out_idx[b] = (float)k;
    atomicAdd(&counts[k], 1.0f);

    __shared__ float red[256];
    red[threadIdx.x] = s;
    __syncthreads();
    for (int off = 128; off > 0; off >>= 1){
        if (threadIdx.x < off) red[threadIdx.x] += red[threadIdx.x + off];
        __syncthreads();
    }
    if (threadIdx.x == 0) atomicAdd(loss, red[0]);
}

// ---------------- perplexity + vq_loss scalars ----------------
__global__ void finalize_kernel(const float* __restrict__ counts, const float* __restrict__ loss,
                                float* __restrict__ out)
{
    __shared__ float red[256];
    float s = 0.0f;
    for (int k = threadIdx.x; k < KCODES; k += 256){
        float p = counts[k] * (1.0f / (float)BATCH);
        s += p * logf(p + 1e-10f);
    }
    red[threadIdx.x] = s;
    __syncthreads();
    for (int off = 128; off > 0; off >>= 1){
        if (threadIdx.x < off) red[threadIdx.x] += red[threadIdx.x + off];
        __syncthreads();
    }
    if (threadIdx.x == 0){
        out[PERP_OFF] = expf(-red[0]);
        out[LOSS_OFF] = loss[0] * (0.25f / ((float)BATCH * (float)DLAT));
    }
}

// ---------------- zero counts + loss ----------------
__global__ void zero_kernel(float* __restrict__ counts, float* __restrict__ loss){
    int i = blockIdx.x * 256 + threadIdx.x;
    if (i < KCODES) counts[i] = 0.0f;
    if (i == KCODES) loss[0] = 0.0f;
}

// ---------------- concat head weights [pW|wW|aW|0pad] -> [1024,128], biases -> [128] ----------------
__global__ void concat_head(const float* __restrict__ pW, const float* __restrict__ pb,
                            const float* __restrict__ wW, const float* __restrict__ wb,
                            const float* __restrict__ aW, const float* __restrict__ ab,
                            float* __restrict__ hw, float* __restrict__ hb)
{
    int i = blockIdx.x * 256 + threadIdx.x;
    int total = HIDDEN * 128;
    if (i < total){
        int k = i >> 7, col = i & 127;
        float v = 0.0f;
        if (col < 40)      v = pW[k*40 + col];
        else if (col < 42) v = wW[k*2 + (col-40)];
        else if (col < 44) v = aW[k*2 + (col-42)];
        hw[i] = v;
    }
    if (i < 128){
        float v = 0.0f;
        if (i < 40)      v = pb[i];
        else if (i < 42) v = wb[i-40];
        else if (i < 44) v = ab[i-42];
        hb[i] = v;
    }
}

// ---------------- pack outputs: points / control_points / widths / alphas ----------------
__global__ void pack_kernel(const float* __restrict__ ho, float* __restrict__ out){
    int gid = blockIdx.x * 256 + threadIdx.x;
    int b = gid / 92, e = gid % 92;
    if (b >= BATCH) return;
    const float* h = ho + (size_t)b * 128;
    if (e < 40){
        out[P_OFF + (size_t)b*40 + e] = h[e];
    } else if (e < 88){
        int e2 = e - 40;
        int c  = e2 & 1;
        int j  = (e2 >> 1) & 3;
        int sg = (e2 >> 3) % 3;
        int p  = e2 / 24;
        out[CP_OFF + (size_t)b*48 + e2] = h[p*20 + (3*sg + j)*2 + c];
    } else if (e < 90){
        int p = e - 88;
        out[W_OFF + (size_t)b*2 + p] = h[40 + p];
    } else {
        int p = e - 90;
        out[A_OFF + (size_t)b*2 + p] = h[42 + p];
    }
}

// ---------------- launch ----------------
extern "C" void kernel_launch(void* const* d_in, const int* in_sizes, int n_in,
                              void* d_out, int out_size)
{
    (void)in_sizes; (void)n_in; (void)out_size;
    const float* x   = (const float*)d_in[0];
    const float* W1  = (const float*)d_in[1];
    const float* b1  = (const float*)d_in[2];
    const float* W2  = (const float*)d_in[3];
    const float* b2  = (const float*)d_in[4];
    const float* W3  = (const float*)d_in[5];
    const float* b3  = (const float*)d_in[6];
    const float* emb = (const float*)d_in[7];
    const float* dW1 = (const float*)d_in[8];
    const float* db1 = (const float*)d_in[9];
    const float* dW2 = (const float*)d_in[10];
    const float* db2 = (const float*)d_in[11];
    const float* pW  = (const float*)d_in[12];
    const float* pb  = (const float*)d_in[13];
    const float* wW  = (const float*)d_in[14];
    const float* wb  = (const float*)d_in[15];
    const float* aW  = (const float*)d_in[16];
    const float* ab  = (const float*)d_in[17];
    float* out = (float*)d_out;

    float *h1, *h2, *z, *zq, *d1, *d2, *ho, *counts, *loss, *enorm, *hw, *hb;
    float2 *W12, *W22, *embT;
    int* idx;
    cudaGetSymbolAddress((void**)&h1, g_h1);
    cudaGetSymbolAddress((void**)&h2, g_h2);
    cudaGetSymbolAddress((void**)&z,  g_z);
    cudaGetSymbolAddress((void**)&zq, g_zq);
    cudaGetSymbolAddress((void**)&d1, g_d1);
    cudaGetSymbolAddress((void**)&d2, g_d2);
    cudaGetSymbolAddress((void**)&ho, g_ho);
    cudaGetSymbolAddress((void**)&idx, g_idx);
    cudaGetSymbolAddress((void**)&counts, g_counts);
    cudaGetSymbolAddress((void**)&loss, g_loss);
    cudaGetSymbolAddress((void**)&enorm, g_enorm);
    cudaGetSymbolAddress((void**)&hw, g_hw);
    cudaGetSymbolAddress((void**)&hb, g_hb);
    cudaGetSymbolAddress((void**)&W12, g_W12);
    cudaGetSymbolAddress((void**)&W22, g_W22);
    cudaGetSymbolAddress((void**)&embT, g_embT);

    const int VQ_SMEM = (int)(3*64*ESTRIDE*sizeof(float2));   // Zs + 2x Es
    cudaFuncSetAttribute(vq_argmin_mma, cudaFuncAttributeMaxDynamicSharedMemorySize, VQ_SMEM);

    // init scalars/counts + head-weight concat + codebook norms + pre-splits
    zero_kernel<<<(KCODES + 1 + 255)/256, 256>>>(counts, loss);
    concat_head<<<(HIDDEN*128 + 255)/256, 256>>>(pW, pb, wW, wb, aW, ab, hw, hb);
    enorm_kernel<<<(KCODES + 255)/256, 256>>>(emb, enorm);
    split_arr<<<(784*256/4 + 255)/256, 256>>>(W1, W12, 784*256/4);
    split_arr<<<(256*256/4 + 255)/256, 256>>>(W2, W22, 256*256/4);
    split_emb_T<<<(KCODES*DLAT + 255)/256, 256>>>(emb, embT);

    // encoder (split-3x tensor cores, pipelined, B pre-split)
    mma_gemm_sb2<ACT_LEAKY><<<dim3(2, BATCH/128), 256>>>(x,  W12, b1, h1, BATCH, 256, 784);
    mma_gemm_sb2<ACT_LEAKY><<<dim3(2, BATCH/128), 256>>>(h1, W22, b2, h2, BATCH, 256, 256);
    sgemm_smallN<ACT_NONE><<<BATCH/64, 256>>>(h2, W3, b3, z, BATCH, DLAT, 256);

    // VQ (split-3x, pre-split transposed codebook, cp.async double-buffered)
    vq_argmin_mma<<<BATCH/128, 256, VQ_SMEM>>>(z, embT, enorm, idx);
    vq_post<<<BATCH/256, 256>>>(z, emb, idx, zq, counts, loss, out + IDX_OFF);
    finalize_kernel<<<1, 256>>>(counts, loss, out);

    // decoder (tensor cores, 1x TF32 + cp.async pipeline)
    mma_gemm_1x<ACT_SELU><<<dim3(HIDDEN/128, BATCH/128), 256>>>(zq, dW1, db1, d1, BATCH, HIDDEN, DLAT);
    mma_gemm_1x<ACT_SELU><<<dim3(HIDDEN/128, BATCH/128), 256>>>(d1, dW2, db2, d2, BATCH, HIDDEN, HIDDEN);

    // head (1x TF32, N padded to 128)
    mma_gemm_1x<ACT_HEAD><<<dim3(1, BATCH/128), 256>>>(d2, hw, hb, ho, BATCH, 128, HIDDEN);

    // pack outputs
    pack_kernel<<<(BATCH*92 + 255)/256, 256>>>(ho, out);
}

// round 9
// speedup vs baseline: 1.3054x; 1.0317x over previous
#include <cuda_runtime.h>
#include <math.h>
#include <stdint.h>

// ---------------- problem constants ----------------
#define BATCH   32768
#define KCODES  4096
#define DLAT    64
#define HIDDEN  1024

// output layout (f32, reference return order, flattened+concat)
#define P_OFF    0
#define P_SIZE   (BATCH*40)
#define CP_OFF   (P_OFF + P_SIZE)
#define CP_SIZE  (BATCH*48)
#define W_OFF    (CP_OFF + CP_SIZE)
#define WA_SIZE  (BATCH*2)
#define A_OFF    (W_OFF + WA_SIZE)
#define LOSS_OFF (A_OFF + WA_SIZE)
#define IDX_OFF  (LOSS_OFF + 1)
#define PERP_OFF (IDX_OFF + BATCH)

#define SPAD 4
#define EF 136           // raw Es float stride (136%32=8 -> conflict-free)
#define ZST 68           // raw Zs float stride for K=64 resident tile (68%32=4 -> conflict-free)

// ---------------- scratch (__device__ globals; no allocation allowed) ----------------
__device__ float  g_h1[BATCH*256];
__device__ float  g_h2[BATCH*256];
__device__ float  g_z [BATCH*DLAT];
__device__ float  g_zq[BATCH*DLAT];
__device__ float  g_d1[BATCH*HIDDEN];
__device__ float  g_d2[BATCH*HIDDEN];
__device__ float  g_ho[BATCH*128];        // head out, stride 128 (padded)
__device__ int    g_idx[BATCH];
__device__ float  g_counts[KCODES];
__device__ float  g_loss;
__device__ float  g_enorm[KCODES];
__device__ float  g_hw[HIDDEN*128];       // padded head weights [1024,128]
__device__ float  g_hb[128];
__device__ float2 g_W12[784*256];         // pre-split W1
__device__ float2 g_W22[256*256];         // pre-split W2
__device__ float  g_embTf[DLAT*KCODES];   // raw transposed codebook [d][k]

// ---------------- activations ----------------
#define ACT_NONE 0
#define ACT_LEAKY 1
#define ACT_SELU 2
#define ACT_HEAD 3

__device__ __forceinline__ float sigmoidf_(float x){ return 1.0f/(1.0f+expf(-x)); }

template<int ACT>
__device__ __forceinline__ float apply_act(float v, int col){
    if (ACT == ACT_LEAKY) return v > 0.0f ? v : 0.2f*v;
    if (ACT == ACT_SELU){
        const float a = 1.6732632423543772f, s = 1.0507009873554805f;
        return v > 0.0f ? s*v : s*a*(expf(v)-1.0f);
    }
    if (ACT == ACT_HEAD){
        if (col < 40) return tanhf(v)*12.0f + 14.0f;
        if (col < 42) return sigmoidf_(v)*2.0f + 1.0f;
        return sigmoidf_(v);
    }
    return v;
}

// ---------------- TF32 split helpers ----------------
__device__ __forceinline__ uint32_t tf32_of(float x){
    uint32_t r; asm("cvt.rna.tf32.f32 %0, %1;" : "=r"(r) : "f"(x)); return r;
}
__device__ __forceinline__ float2 split2(float x){
    uint32_t h = tf32_of(x);
    float hf = __uint_as_float(h);
    float lof = __uint_as_float(tf32_of(x - hf));
    return make_float2(hf, lof);
}
// in-register split to uint32 pair
__device__ __forceinline__ void split_u(float x, uint32_t& hi, uint32_t& lo){
    hi = tf32_of(x);
    lo = tf32_of(x - __uint_as_float(hi));
}

// D += A*B, m16n8k8 tf32
__device__ __forceinline__ void mma8(float* c, const uint32_t* a, const uint32_t* b){
    asm volatile(
        "mma.sync.aligned.m16n8k8.row.col.f32.tf32.tf32.f32 "
        "{%0,%1,%2,%3}, {%4,%5,%6,%7}, {%8,%9}, {%0,%1,%2,%3};\n"
        : "+f"(c[0]), "+f"(c[1]), "+f"(c[2]), "+f"(c[3])
        : "r"(a[0]), "r"(a[1]), "r"(a[2]), "r"(a[3]), "r"(b[0]), "r"(b[1]));
}

// ---------------- cp.async helpers ----------------
__device__ __forceinline__ void cpasync16(void* dst_smem, const void* src){
    uint32_t s = (uint32_t)__cvta_generic_to_shared(dst_smem);
    asm volatile("cp.async.cg.shared.global [%0], [%1], 16;\n" :: "r"(s), "l"(src));
}
__device__ __forceinline__ void cpasync_commit(){ asm volatile("cp.async.commit_group;\n"); }
template<int NN>
__device__ __forceinline__ void cpasync_wait(){ asm volatile("cp.async.wait_group %0;\n" :: "n"(NN)); }

// ---------------- elementwise split kernels ----------------
__global__ void split_arr(const float* __restrict__ src, float2* __restrict__ dst, int n4){
    int i = blockIdx.x * 256 + threadIdx.x;
    if (i >= n4) return;
    float4 v = ((const float4*)src)[i];
    float2 s0 = split2(v.x), s1 = split2(v.y), s2 = split2(v.z), s3 = split2(v.w);
    float4* d = (float4*)(dst + (size_t)i*4);
    d[0] = make_float4(s0.x, s0.y, s1.x, s1.y);
    d[1] = make_float4(s2.x, s2.y, s3.x, s3.y);
}

// emb [K][D] -> embTf [D][K] raw transpose
__global__ void emb_T_raw(const float* __restrict__ emb, float* __restrict__ embTf){
    int i = blockIdx.x * 256 + threadIdx.x;   // i = k*64 + d (coalesced read)
    if (i >= KCODES*DLAT) return;
    int k = i >> 6, d = i & 63;
    embTf[(size_t)d*KCODES + k] = emb[i];
}

// ============================================================================
// 1x-TF32 GEMM (decoder + head): C = act(A[M,K] @ W[K,N] + bias)
// 128x128 tile, BK=16, 8 warps (2Mx4N), cp.async double-buffered.
// ============================================================================
#define AST 20
#define BST 136
template<int ACT>
__global__ void __launch_bounds__(256, 2) mma_gemm_1x(
    const float* __restrict__ A, const float* __restrict__ W,
    const float* __restrict__ bias, float* __restrict__ C,
    int M, int N, int K)
{
    __shared__ float As[2][128][AST];
    __shared__ float Bs[2][16][BST];

    const int tid  = threadIdx.x;
    const int lane = tid & 31, warp = tid >> 5;
    const int wm = (warp & 1) * 64, wn = (warp >> 1) * 32;
    const int bm = blockIdx.y * 128, bn = blockIdx.x * 128;
    const int g = lane >> 2, tg = lane & 3;

    float acc[4][4][4];
    #pragma unroll
    for (int i = 0; i < 4; i++)
        #pragma unroll
        for (int j = 0; j < 4; j++)
            #pragma unroll
            for (int q = 0; q < 4; q++) acc[i][j][q] = 0.0f;

    const int ar = tid >> 1, ac = (tid & 1) * 8;
    const int br = tid >> 4, bc = (tid & 15) * 8;
    const float* Ap = A + (size_t)(bm + ar) * K + ac;
    const float* Bp = W + (size_t)br * N + bn + bc;

    const int ntiles = K >> 4;

    #define COPY_TILE(kt, buf) do { \
        const float* ap = Ap + (size_t)(kt) * 16; \
        cpasync16(&As[buf][ar][ac],   ap); \
        cpasync16(&As[buf][ar][ac+4], ap + 4); \
        const float* bp = Bp + (size_t)(kt) * 16 * N; \
        cpasync16(&Bs[buf][br][bc],   bp); \
        cpasync16(&Bs[buf][br][bc+4], bp + 4); \
        cpasync_commit(); \
    } while (0)

    COPY_TILE(0, 0);

    for (int i = 0; i < ntiles; i++){
        int buf = i & 1;
        if (i + 1 < ntiles){
            COPY_TILE(i + 1, buf ^ 1);
            cpasync_wait<1>();
        } else {
            cpasync_wait<0>();
        }
        __syncthreads();

        #pragma unroll
        for (int ks = 0; ks < 16; ks += 8){
            uint32_t a[4][4];
            #pragma unroll
            for (int mt = 0; mt < 4; mt++){
                int m = wm + mt*16 + g;
                a[mt][0] = __float_as_uint(As[buf][m  ][ks+tg]);
                a[mt][1] = __float_as_uint(As[buf][m+8][ks+tg]);
                a[mt][2] = __float_as_uint(As[buf][m  ][ks+tg+4]);
                a[mt][3] = __float_as_uint(As[buf][m+8][ks+tg+4]);
            }
            #pragma unroll
            for (int nt = 0; nt < 4; nt++){
                int n = wn + nt*8 + g;
                uint32_t b[2] = { __float_as_uint(Bs[buf][ks+tg  ][n]),
                                  __float_as_uint(Bs[buf][ks+tg+4][n]) };
                #pragma unroll
                for (int mt = 0; mt < 4; mt++) mma8(acc[mt][nt], a[mt], b);
            }
        }
        __syncthreads();
    }
    #undef COPY_TILE

    // epilogue: bias + activation, 64-bit stores
    #pragma unroll
    for (int mt = 0; mt < 4; mt++){
        #pragma unroll
        for (int nt = 0; nt < 4; nt++){
            int row = bm + wm + mt*16 + g;
            int col = bn + wn + nt*8 + 2*tg;
            float bs0 = bias[col], bs1 = bias[col+1];
            float2 o0, o1;
            o0.x = apply_act<ACT>(acc[mt][nt][0] + bs0, col);
            o0.y = apply_act<ACT>(acc[mt][nt][1] + bs1, col+1);
            o1.x = apply_act<ACT>(acc[mt][nt][2] + bs0, col);
            o1.y = apply_act<ACT>(acc[mt][nt][3] + bs1, col+1);
            *(float2*)&C[(size_t)row*N + col]     = o0;
            *(float2*)&C[(size_t)(row+8)*N + col] = o1;
        }
    }
}

// ============================================================================
// split-3x GEMM v2 (encoder): cp.async double-buffered pipeline.
// A staged RAW fp32 in smem, split in-register; B pre-split float2.
// ============================================================================
template<int ACT>
__global__ void __launch_bounds__(256, 2) mma_gemm_sb2(
    const float* __restrict__ A, const float2* __restrict__ B2,
    const float* __restrict__ bias, float* __restrict__ C,
    int M, int N, int K)
{
    __shared__ float  As[2][128][AST];          // raw fp32
    __shared__ float2 Bs[2][16][128+SPAD];      // pre-split (hi,lo)

    const int tid  = threadIdx.x;
    const int lane = tid & 31, warp = tid >> 5;
    const int wm = (warp & 1) * 64, wn = (warp >> 1) * 32;
    const int bm = blockIdx.y * 128, bn = blockIdx.x * 128;
    const int g = lane >> 2, tg = lane & 3;

    float acc[4][4][4];
    #pragma unroll
    for (int i = 0; i < 4; i++)
        #pragma unroll
        for (int j = 0; j < 4; j++)
            #pragma unroll
            for (int q = 0; q < 4; q++) acc[i][j][q] = 0.0f;

    const int ar = tid >> 1, ac = (tid & 1) * 8;
    const int br = tid >> 4, bcf2 = (tid & 15) * 8;   // 8 float2 per thread
    const float*  Ap = A  + (size_t)(bm + ar) * K + ac;
    const float2* Bp = B2 + (size_t)br * N + bn + bcf2;

    const int ntiles = K >> 4;

    #define COPY_SB(kt, buf) do { \
        const float* ap = Ap + (size_t)(kt) * 16; \
        cpasync16(&As[buf][ar][ac],   ap); \
        cpasync16(&As[buf][ar][ac+4], ap + 4); \
        const float2* bp = Bp + (size_t)(kt) * 16 * N; \
        cpasync16(&Bs[buf][br][bcf2+0], bp); \
        cpasync16(&Bs[buf][br][bcf2+2], bp + 2); \
        cpasync16(&Bs[buf][br][bcf2+4], bp + 4); \
        cpasync16(&Bs[buf][br][bcf2+6], bp + 6); \
        cpasync_commit(); \
    } while (0)

    COPY_SB(0, 0);

    for (int i = 0; i < ntiles; i++){
        int buf = i & 1;
        if (i + 1 < ntiles){
            COPY_SB(i + 1, buf ^ 1);
            cpasync_wait<1>();
        } else {
            cpasync_wait<0>();
        }
        __syncthreads();

        #pragma unroll
        for (int ks = 0; ks < 16; ks += 8){
            uint32_t ah[4][4], al[4][4];
            #pragma unroll
            for (int mt = 0; mt < 4; mt++){
                int m = wm + mt*16 + g;
                float a0 = As[buf][m  ][ks+tg];
                float a1 = As[buf][m+8][ks+tg];
                float a2 = As[buf][m  ][ks+tg+4];
                float a3 = As[buf][m+8][ks+tg+4];
                split_u(a0, ah[mt][0], al[mt][0]);
                split_u(a1, ah[mt][1], al[mt][1]);
                split_u(a2, ah[mt][2], al[mt][2]);
                split_u(a3, ah[mt][3], al[mt][3]);
            }
            #pragma unroll
            for (int nt = 0; nt < 4; nt++){
                int n = wn + nt*8 + g;
                float2 w0 = Bs[buf][ks+tg  ][n];
                float2 w1 = Bs[buf][ks+tg+4][n];
                uint32_t bh[2] = { __float_as_uint(w0.x), __float_as_uint(w1.x) };
                uint32_t bl[2] = { __float_as_uint(w0.y), __float_as_uint(w1.y) };
                #pragma unroll
                for (int mt = 0; mt < 4; mt++) mma8(acc[mt][nt], ah[mt], bh);
                #pragma unroll
                for (int mt = 0; mt < 4; mt++) mma8(acc[mt][nt], al[mt], bh);
                #pragma unroll
                for (int mt = 0; mt < 4; mt++) mma8(acc[mt][nt], ah[mt], bl);
            }
        }
        __syncthreads();
    }
    #undef COPY_SB

    // epilogue: bias + activation, 64-bit stores
    #pragma unroll
    for (int mt = 0; mt < 4; mt++){
        #pragma unroll
        for (int nt = 0; nt < 4; nt++){
            int row = bm + wm + mt*16 + g;
            int col = bn + wn + nt*8 + 2*tg;
            float bs0 = bias[col], bs1 = bias[col+1];
            float2 o0, o1;
            o0.x = apply_act<ACT>(acc[mt][nt][0] + bs0, col);
            o0.y = apply_act<ACT>(acc[mt][nt][1] + bs1, col+1);
            o1.x = apply_act<ACT>(acc[mt][nt][2] + bs0, col);
            o1.y = apply_act<ACT>(acc[mt][nt][3] + bs1, col+1);
            *(float2*)&C[(size_t)row*N + col]     = o0;
            *(float2*)&C[(size_t)(row+8)*N + col] = o1;
        }
    }
}

// ---------------- small-N SGEMM: 64 rows x N(<=64) cols, BK=16, 4x4 microtile ----------------
template<int ACT>
__global__ void __launch_bounds__(256) sgemm_smallN(
    const float* __restrict__ A, const float* __restrict__ W,
    const float* __restrict__ bias, float* __restrict__ C,
    int M, int N, int K)
{
    __shared__ float As[16][64];
    __shared__ float Bs[16][64];
    const int tid = threadIdx.x;
    const int bm = blockIdx.x * 64;
    const int arow = tid >> 2,  acol = (tid & 3) * 4;
    const int bkr  = tid >> 4,  bcol = (tid & 15) * 4;
    const int ty = tid >> 4, tx = tid & 15;

    float acc[4][4];
    #pragma unroll
    for (int i = 0; i < 4; i++)
        #pragma unroll
        for (int j = 0; j < 4; j++) acc[i][j] = 0.0f;

    for (int k0 = 0; k0 < K; k0 += 16){
        float4 av = *(const float4*)(A + (size_t)(bm + arow) * K + k0 + acol);
        As[acol+0][arow] = av.x;
        As[acol+1][arow] = av.y;
        As[acol+2][arow] = av.z;
        As[acol+3][arow] = av.w;
        float4 bv = make_float4(0.f,0.f,0.f,0.f);
        if (bcol < N) bv = *(const float4*)(W + (size_t)(k0 + bkr) * N + bcol);
        *(float4*)&Bs[bkr][bcol] = bv;
        __syncthreads();
        #pragma unroll
        for (int kk = 0; kk < 16; kk++){
            float a[4], b[4];
            *(float4*)a = *(const float4*)&As[kk][ty*4];
            *(float4*)b = *(const float4*)&Bs[kk][tx*4];
            #pragma unroll
            for (int i = 0; i < 4; i++)
                #pragma unroll
                for (int j = 0; j < 4; j++)
                    acc[i][j] = fmaf(a[i], b[j], acc[i][j]);
        }
        __syncthreads();
    }

    if (tx*4 < N){
        float bsv[4];
        #pragma unroll
        for (int j = 0; j < 4; j++) bsv[j] = bias[tx*4 + j];
        #pragma unroll
        for (int i = 0; i < 4; i++){
            float4 v;
            v.x = apply_act<ACT>(acc[i][0] + bsv[0], tx*4+0);
            v.y = apply_act<ACT>(acc[i][1] + bsv[1], tx*4+1);
            v.z = apply_act<ACT>(acc[i][2] + bsv[2], tx*4+2);
            v.w = apply_act<ACT>(acc[i][3] + bsv[3], tx*4+3);
            *(float4*)(C + (size_t)(bm + ty*4 + i) * N + tx*4) = v;
        }
    }
}

// ---------------- codebook norms ----------------
__global__ void enorm_kernel(const float* __restrict__ emb, float* __restrict__ enorm){
    int k = blockIdx.x * 256 + threadIdx.x;
    if (k >= KCODES) return;
    const float4* e = (const float4*)(emb + (size_t)k * DLAT);
    float s = 0.0f;
    #pragma unroll
    for (int q = 0; q < 16; q++){
        float4 v = e[q];
        s += v.x*v.x + v.y*v.y + v.z*v.z + v.w*v.w;
    }
    enorm[k] = s;
}

// ---------------- VQ argmin v3: raw smem + in-register split, 2 CTAs/SM ----------------
// Zs raw [128][68] (34.8 KB), Es raw [2][64][136] (69.6 KB double-buffered).
__global__ void __launch_bounds__(256, 2) vq_argmin_mma(
    const float* __restrict__ z, const float* __restrict__ embTf,
    const float* __restrict__ enorm, int* __restrict__ idx_out)
{
    __shared__ float Zs[128][ZST];
    __shared__ float Es[2][64][EF];

    const int tid  = threadIdx.x;
    const int lane = tid & 31, warp = tid >> 5;
    const int wm = (warp & 1) * 64, wn = (warp >> 1) * 32;
    const int bm = blockIdx.x * 128;
    const int g = lane >> 2, tg = lane & 3;

    // load z tile raw [m][k] via cp.async
    const int zr = tid >> 1, zc = (tid & 1) * 32;
    {
        const float* Zp = z + (size_t)(bm + zr) * DLAT + zc;
        #pragma unroll
        for (int q = 0; q < 8; q++)
            cpasync16(&Zs[zr][zc + q*4], Zp + q*4);
        cpasync_commit();
    }

    // chunk copy: 64 rows x 128 floats = 2048 16B-units; 8 per thread
    #define COPY_ES(c0_, buf_) do { \
        _Pragma("unroll") \
        for (int j = 0; j < 8; j++){ \
            int unit = j*256 + tid; \
            int k_ = unit >> 5, u_ = unit & 31; \
            cpasync16(&Es[buf_][k_][u_*4], embTf + (size_t)k_*KCODES + (c0_) + u_*4); \
        } \
        cpasync_commit(); \
    } while (0)

    float mv[8]; int mi[8];
    #pragma unroll
    for (int s = 0; s < 8; s++){ mv[s] = INFINITY; mi[s] = 0; }

    COPY_ES(0, 0);

    for (int ch = 0; ch < KCODES/128; ch++){
        int c0 = ch * 128;
        int buf = ch & 1;
        if (ch + 1 < KCODES/128){
            COPY_ES(c0 + 128, buf ^ 1);
            cpasync_wait<1>();
        } else {
            cpasync_wait<0>();
        }
        __syncthreads();

        float acc[4][4][4];
        #pragma unroll
        for (int i = 0; i < 4; i++)
            #pragma unroll
            for (int j = 0; j < 4; j++)
                #pragma unroll
                for (int q = 0; q < 4; q++) acc[i][j][q] = 0.0f;

        #pragma unroll
        for (int ks = 0; ks < DLAT; ks += 8){
            uint32_t ah[4][4], al[4][4];
            #pragma unroll
            for (int mt = 0; mt < 4; mt++){
                int m = wm + mt*16 + g;
                float a0 = Zs[m  ][ks+tg];
                float a1 = Zs[m+8][ks+tg];
                float a2 = Zs[m  ][ks+tg+4];
                float a3 = Zs[m+8][ks+tg+4];
                split_u(a0, ah[mt][0], al[mt][0]);
                split_u(a1, ah[mt][1], al[mt][1]);
                split_u(a2, ah[mt][2], al[mt][2]);
                split_u(a3, ah[mt][3], al[mt][3]);
            }
            #pragma unroll
            for (int nt = 0; nt < 4; nt++){
                int n = wn + nt*8 + g;
                float w0 = Es[buf][ks+tg  ][n];
                float w1 = Es[buf][ks+tg+4][n];
                uint32_t bh[2], bl[2];
                split_u(w0, bh[0], bl[0]);
                split_u(w1, bh[1], bl[1]);
                #pragma unroll
                for (int mt = 0; mt < 4; mt++) mma8(acc[mt][nt], ah[mt], bh);
                #pragma unroll
                for (int mt = 0; mt < 4; mt++) mma8(acc[mt][nt], al[mt], bh);
                #pragma unroll
                for (int mt = 0; mt < 4; mt++) mma8(acc[mt][nt], ah[mt], bl);
            }
        }

        // running argmin (ascending code order within thread; strict < keeps first min)
        #pragma unroll
        for (int nt = 0; nt < 4; nt++){
            int nc = wn + nt*8 + 2*tg;
            float e0 = __ldg(enorm + c0 + nc);
            float e1 = __ldg(enorm + c0 + nc + 1);
            int code = c0 + nc;
            #pragma unroll
            for (int mt = 0; mt < 4; mt++){
                float d00 = e0 - 2.0f*acc[mt][nt][0];
                float d01 = e1 - 2.0f*acc[mt][nt][1];
                float d10 = e0 - 2.0f*acc[mt][nt][2];
                float d11 = e1 - 2.0f*acc[mt][nt][3];
                int s0 = mt*2, s1 = mt*2 + 1;
                if (d00 < mv[s0]){ mv[s0] = d00; mi[s0] = code;   }
                if (d01 < mv[s0]){ mv[s0] = d01; mi[s0] = code+1; }
                if (d10 < mv[s1]){ mv[s1] = d10; mi[s1] = code;   }
                if (d11 < mv[s1]){ mv[s1] = d11; mi[s1] = code+1; }
            }
        }
        __syncthreads();
    }
    #undef COPY_ES

    // final reduction: 16 candidates x 128 rows (reuse Es)
    float* rv = &Es[0][0][0];
    int*   ri = ((int*)rv) + 16*128;
    int cand = (warp >> 1) * 4 + tg;      // 0..15
    #pragma unroll
    for (int s = 0; s < 8; s++){
        int r = wm + (s >> 1)*16 + g + (s & 1)*8;
        rv[cand*128 + r] = mv[s];
        ri[cand*128 + r] = mi[s];
    }
    __syncthreads();
    if (tid < 128){
        float bv = INFINITY; int bi = 0x7fffffff;
        #pragma unroll
        for (int t = 0; t < 16; t++){
            float v = rv[t*128 + tid];
            int c = ri[t*128 + tid];
            if (v < bv || (v == bv && c < bi)){ bv = v; bi = c; }
        }
        idx_out[bm + tid] = bi;
    }
}

// ---------------- gather z_q, idx-as-float, counts, commit-loss partial sums ----------------
__global__ void vq_post(const float* __restrict__ z, const float* __restrict__ emb,
                        const int* __restrict__ idx, float* __restrict__ zq,
                        float* __restrict__ counts, float* __restrict__ loss,
                        float* __restrict__ out_idx)
{
    int b = blockIdx.x * 256 + threadIdx.x;
    int k = idx[b];
    const float4* e  = (const float4*)(emb + (size_t)k * DLAT);
    const float4* zz = (const float4*)(z   + (size_t)b * DLAT);
    float4*       zo = (float4*)(zq + (size_t)b * DLAT);
    float s = 0.0f;
    #pragma unroll
    for (int q = 0; q < 16; q++){
        float4 ev = e[q], zv = zz[q];
        float dx = ev.x - zv.x, dy = ev.y - zv.y, dz = ev.z - zv.z, dw = ev.w - zv.w;
        s += dx*dx + dy*dy + dz*dz + dw*dw;
        zo[q] = ev;
    }
    out_idx[b] = (float)k;
    atomicAdd(&counts[k], 1.0f);

    __shared__ float red[256];
    red[threadIdx.x] = s;
    __syncthreads();
    for (int off = 128; off > 0; off >>= 1){
        if (threadIdx.x < off) red[threadIdx.x] += red[threadIdx.x + off];
        __syncthreads();
    }
    if (threadIdx.x == 0) atomicAdd(loss, red[0]);
}

// ---------------- perplexity + vq_loss scalars ----------------
__global__ void finalize_kernel(const float* __restrict__ counts, const float* __restrict__ loss,
                                float* __restrict__ out)
{
    __shared__ float red[256];
    float s = 0.0f;
    for (int k = threadIdx.x; k < KCODES; k += 256){
        float p = counts[k] * (1.0f / (float)BATCH);
        s += p * logf(p + 1e-10f);
    }
    red[threadIdx.x] = s;
    __syncthreads();
    for (int off = 128; off > 0; off >>= 1){
        if (threadIdx.x < off) red[threadIdx.x] += red[threadIdx.x + off];
        __syncthreads();
    }
    if (threadIdx.x == 0){
        out[PERP_OFF] = expf(-red[0]);
        out[LOSS_OFF] = loss[0] * (0.25f / ((float)BATCH * (float)DLAT));
    }
}

// ---------------- zero counts + loss ----------------
__global__ void zero_kernel(float* __restrict__ counts, float* __restrict__ loss){
    int i = blockIdx.x * 256 + threadIdx.x;
    if (i < KCODES) counts[i] = 0.0f;
    if (i == KCODES) loss[0] = 0.0f;
}

// ---------------- concat head weights [pW|wW|aW|0pad] -> [1024,128], biases -> [128] ----------------
__global__ void concat_head(const float* __restrict__ pW, const float* __restrict__ pb,
                            const float* __restrict__ wW, const float* __restrict__ wb,
                            const float* __restrict__ aW, const float* __restrict__ ab,
                            float* __restrict__ hw, float* __restrict__ hb)
{
    int i = blockIdx.x * 256 + threadIdx.x;
    int total = HIDDEN * 128;
    if (i < total){
        int k = i >> 7, col = i & 127;
        float v = 0.0f;
        if (col < 40)      v = pW[k*40 + col];
        else if (col < 42) v = wW[k*2 + (col-40)];
        else if (col < 44) v = aW[k*2 + (col-42)];
        hw[i] = v;
    }
    if (i < 128){
        float v = 0.0f;
        if (i < 40)      v = pb[i];
        else if (i < 42) v = wb[i-40];
        else if (i < 44) v = ab[i-42];
        hb[i] = v;
    }
}

// ---------------- pack outputs: points / control_points / widths / alphas ----------------
__global__ void pack_kernel(const float* __restrict__ ho, float* __restrict__ out){
    int gid = blockIdx.x * 256 + threadIdx.x;
    int b = gid / 92, e = gid % 92;
    if (b >= BATCH) return;
    const float* h = ho + (size_t)b * 128;
    if (e < 40){
        out[P_OFF + (size_t)b*40 + e] = h[e];
    } else if (e < 88){
        int e2 = e - 40;
        int c  = e2 & 1;
        int j  = (e2 >> 1) & 3;
        int sg = (e2 >> 3) % 3;
        int p  = e2 / 24;
        out[CP_OFF + (size_t)b*48 + e2] = h[p*20 + (3*sg + j)*2 + c];
    } else if (e < 90){
        int p = e - 88;
        out[W_OFF + (size_t)b*2 + p] = h[40 + p];
    } else {
        int p = e - 90;
        out[A_OFF + (size_t)b*2 + p] = h[42 + p];
    }
}

// ---------------- launch ----------------
extern "C" void kernel_launch(void* const* d_in, const int* in_sizes, int n_in,
                              void* d_out, int out_size)
{
    (void)in_sizes; (void)n_in; (void)out_size;
    const float* x   = (const float*)d_in[0];
    const float* W1  = (const float*)d_in[1];
    const float* b1  = (const float*)d_in[2];
    const float* W2  = (const float*)d_in[3];
    const float* b2  = (const float*)d_in[4];
    const float* W3  = (const float*)d_in[5];
    const float* b3  = (const float*)d_in[6];
    const float* emb = (const float*)d_in[7];
    const float* dW1 = (const float*)d_in[8];
    const float* db1 = (const float*)d_in[9];
    const float* dW2 = (const float*)d_in[10];
    const float* db2 = (const float*)d_in[11];
    const float* pW  = (const float*)d_in[12];
    const float* pb  = (const float*)d_in[13];
    const float* wW  = (const float*)d_in[14];
    const float* wb  = (const float*)d_in[15];
    const float* aW  = (const float*)d_in[16];
    const float* ab  = (const float*)d_in[17];
    float* out = (float*)d_out;

    float *h1, *h2, *z, *zq, *d1, *d2, *ho, *counts, *loss, *enorm, *hw, *hb, *embTf;
    float2 *W12, *W22;
    int* idx;
    cudaGetSymbolAddress((void**)&h1, g_h1);
    cudaGetSymbolAddress((void**)&h2, g_h2);
    cudaGetSymbolAddress((void**)&z,  g_z);
    cudaGetSymbolAddress((void**)&zq, g_zq);
    cudaGetSymbolAddress((void**)&d1, g_d1);
    cudaGetSymbolAddress((void**)&d2, g_d2);
    cudaGetSymbolAddress((void**)&ho, g_ho);
    cudaGetSymbolAddress((void**)&idx, g_idx);
    cudaGetSymbolAddress((void**)&counts, g_counts);
    cudaGetSymbolAddress((void**)&loss, g_loss);
    cudaGetSymbolAddress((void**)&enorm, g_enorm);
    cudaGetSymbolAddress((void**)&hw, g_hw);
    cudaGetSymbolAddress((void**)&hb, g_hb);
    cudaGetSymbolAddress((void**)&W12, g_W12);
    cudaGetSymbolAddress((void**)&W22, g_W22);
    cudaGetSymbolAddress((void**)&embTf, g_embTf);

    // init scalars/counts + head-weight concat + codebook norms + pre-splits
    zero_kernel<<<(KCODES + 1 + 255)/256, 256>>>(counts, loss);
    concat_head<<<(HIDDEN*128 + 255)/256, 256>>>(pW, pb, wW, wb, aW, ab, hw, hb);
    enorm_kernel<<<(KCODES + 255)/256, 256>>>(emb, enorm);
    split_arr<<<(784*256/4 + 255)/256, 256>>>(W1, W12, 784*256/4);
    split_arr<<<(256*256/4 + 255)/256, 256>>>(W2, W22, 256*256/4);
    emb_T_raw<<<(KCODES*DLAT + 255)/256, 256>>>(emb, embTf);

    // encoder (split-3x tensor cores, pipelined, B pre-split)
    mma_gemm_sb2<ACT_LEAKY><<<dim3(2, BATCH/128), 256>>>(x,  W12, b1, h1, BATCH, 256, 784);
    mma_gemm_sb2<ACT_LEAKY><<<dim3(2, BATCH/128), 256>>>(h1, W22, b2, h2, BATCH, 256, 256);
    sgemm_smallN<ACT_NONE><<<BATCH/64, 256>>>(h2, W3, b3, z, BATCH, DLAT, 256);

    // VQ (split-3x, raw tiles + in-register split, 2 CTAs/SM, cp.async)
    vq_argmin_mma<<<BATCH/128, 256>>>(z, embTf, enorm, idx);
    vq_post<<<BATCH/256, 256>>>(z, emb, idx, zq, counts, loss, out + IDX_OFF);
    finalize_kernel<<<1, 256>>>(counts, loss, out);

    // decoder (tensor cores, 1x TF32 + cp.async pipeline)
    mma_gemm_1x<ACT_SELU><<<dim3(HIDDEN/128, BATCH/128), 256>>>(zq, dW1, db1, d1, BATCH, HIDDEN, DLAT);
    mma_gemm_1x<ACT_SELU><<<dim3(HIDDEN/128, BATCH/128), 256>>>(d1, dW2, db2, d2, BATCH, HIDDEN, HIDDEN);

    // head (1x TF32, N padded to 128)
    mma_gemm_1x<ACT_HEAD><<<dim3(1, BATCH/128), 256>>>(d2, hw, hb, ho, BATCH, 128, HIDDEN);

    // pack outputs
    pack_kernel<<<(BATCH*92 + 255)/256, 256>>>(ho, out);
}

// round 10
// speedup vs baseline: 1.4706x; 1.1266x over previous
#include <cuda_runtime.h>
#include <cuda_fp16.h>
#include <math.h>
#include <stdint.h>

// ---------------- problem constants ----------------
#define BATCH   32768
#define KCODES  4096
#define DLAT    64
#define HIDDEN  1024

// output layout (f32, reference return order, flattened+concat)
#define P_OFF    0
#define P_SIZE   (BATCH*40)
#define CP_OFF   (P_OFF + P_SIZE)
#define CP_SIZE  (BATCH*48)
#define W_OFF    (CP_OFF + CP_SIZE)
#define WA_SIZE  (BATCH*2)
#define A_OFF    (W_OFF + WA_SIZE)
#define LOSS_OFF (A_OFF + WA_SIZE)
#define IDX_OFF  (LOSS_OFF + 1)
#define PERP_OFF (IDX_OFF + BATCH)

#define SPAD 4
#define HS 136           // half2-word stride for VQ smem rows (bank = m + 8*tg, conflict-free)

// ---------------- scratch (__device__ globals; no allocation allowed) ----------------
__device__ float  g_h1[BATCH*256];
__device__ float  g_h2[BATCH*256];
__device__ float  g_z [BATCH*DLAT];
__device__ float  g_zq[BATCH*DLAT];
__device__ float  g_d1[BATCH*HIDDEN];
__device__ float  g_d2[BATCH*HIDDEN];
__device__ float  g_ho[BATCH*128];        // head out, stride 128 (padded)
__device__ int    g_idx[BATCH];
__device__ float  g_counts[KCODES];
__device__ float  g_loss;
__device__ float  g_enorm[KCODES];
__device__ float  g_hw[HIDDEN*128];       // padded head weights [1024,128]
__device__ float  g_hb[128];
__device__ float2 g_W12[784*256];         // pre-split W1 (tf32 pairs)
__device__ float2 g_W22[256*256];         // pre-split W2
__device__ uint32_t g_zHiT[32*BATCH];     // fp16 hi pairs, transposed [dp][b]
__device__ uint32_t g_zLoT[32*BATCH];     // fp16 lo pairs
__device__ uint32_t g_eHiT[32*KCODES];    // codebook fp16 hi pairs [dp][code]
__device__ uint32_t g_eLoT[32*KCODES];

// ---------------- activations ----------------
#define ACT_NONE 0
#define ACT_LEAKY 1
#define ACT_SELU 2
#define ACT_HEAD 3

__device__ __forceinline__ float sigmoidf_(float x){ return 1.0f/(1.0f+expf(-x)); }

template<int ACT>
__device__ __forceinline__ float apply_act(float v, int col){
    if (ACT == ACT_LEAKY) return v > 0.0f ? v : 0.2f*v;
    if (ACT == ACT_SELU){
        const float a = 1.6732632423543772f, s = 1.0507009873554805f;
        return v > 0.0f ? s*v : s*a*(expf(v)-1.0f);
    }
    if (ACT == ACT_HEAD){
        if (col < 40) return tanhf(v)*12.0f + 14.0f;
        if (col < 42) return sigmoidf_(v)*2.0f + 1.0f;
        return sigmoidf_(v);
    }
    return v;
}

// ---------------- TF32 split helpers ----------------
__device__ __forceinline__ uint32_t tf32_of(float x){
    uint32_t r; asm("cvt.rna.tf32.f32 %0, %1;" : "=r"(r) : "f"(x)); return r;
}
__device__ __forceinline__ float2 split2(float x){
    uint32_t h = tf32_of(x);
    float hf = __uint_as_float(h);
    float lof = __uint_as_float(tf32_of(x - hf));
    return make_float2(hf, lof);
}
__device__ __forceinline__ void split_u(float x, uint32_t& hi, uint32_t& lo){
    hi = tf32_of(x);
    lo = tf32_of(x - __uint_as_float(hi));
}

// ---------------- fp16 split pack helper ----------------
__device__ __forceinline__ void fp16_split_pack(float x0, float x1,
                                                uint32_t& hi, uint32_t& lo){
    __half h0 = __float2half_rn(x0), h1 = __float2half_rn(x1);
    __half l0 = __float2half_rn(x0 - __half2float(h0));
    __half l1 = __float2half_rn(x1 - __half2float(h1));
    __half2 hh = __halves2half2(h0, h1);
    __half2 ll = __halves2half2(l0, l1);
    hi = *(uint32_t*)&hh;
    lo = *(uint32_t*)&ll;
}

// D += A*B, m16n8k8 tf32
__device__ __forceinline__ void mma8(float* c, const uint32_t* a, const uint32_t* b){
    asm volatile(
        "mma.sync.aligned.m16n8k8.row.col.f32.tf32.tf32.f32 "
        "{%0,%1,%2,%3}, {%4,%5,%6,%7}, {%8,%9}, {%0,%1,%2,%3};\n"
        : "+f"(c[0]), "+f"(c[1]), "+f"(c[2]), "+f"(c[3])
        : "r"(a[0]), "r"(a[1]), "r"(a[2]), "r"(a[3]), "r"(b[0]), "r"(b[1]));
}

// D += A*B, m16n8k16 fp16 (fp32 accum) — same reg shape, 2x K per instruction
__device__ __forceinline__ void mma16(float* c, const uint32_t* a, const uint32_t* b){
    asm volatile(
        "mma.sync.aligned.m16n8k16.row.col.f32.f16.f16.f32 "
        "{%0,%1,%2,%3}, {%4,%5,%6,%7}, {%8,%9}, {%0,%1,%2,%3};\n"
        : "+f"(c[0]), "+f"(c[1]), "+f"(c[2]), "+f"(c[3])
        : "r"(a[0]), "r"(a[1]), "r"(a[2]), "r"(a[3]), "r"(b[0]), "r"(b[1]));
}

// ---------------- cp.async helpers ----------------
__device__ __forceinline__ void cpasync16(void* dst_smem, const void* src){
    uint32_t s = (uint32_t)__cvta_generic_to_shared(dst_smem);
    asm volatile("cp.async.cg.shared.global [%0], [%1], 16;\n" :: "r"(s), "l"(src));
}
__device__ __forceinline__ void cpasync_commit(){ asm volatile("cp.async.commit_group;\n"); }
template<int NN>
__device__ __forceinline__ void cpasync_wait(){ asm volatile("cp.async.wait_group %0;\n" :: "n"(NN)); }

// ---------------- elementwise split/pack kernels ----------------
__global__ void split_arr(const float* __restrict__ src, float2* __restrict__ dst, int n4){
    int i = blockIdx.x * 256 + threadIdx.x;
    if (i >= n4) return;
    float4 v = ((const float4*)src)[i];
    float2 s0 = split2(v.x), s1 = split2(v.y), s2 = split2(v.z), s3 = split2(v.w);
    float4* d = (float4*)(dst + (size_t)i*4);
    d[0] = make_float4(s0.x, s0.y, s1.x, s1.y);
    d[1] = make_float4(s2.x, s2.y, s3.x, s3.y);
}

// emb [K][64] -> packed fp16 hi/lo transposed [dp][code]
__global__ void pack_embT(const float* __restrict__ emb,
                          uint32_t* __restrict__ eHiT, uint32_t* __restrict__ eLoT){
    int i = blockIdx.x * 256 + threadIdx.x;   // i = dp*KCODES + code
    if (i >= 32*KCODES) return;
    int dp = i >> 12, c = i & (KCODES-1);
    float x0 = emb[(size_t)c*DLAT + 2*dp];
    float x1 = emb[(size_t)c*DLAT + 2*dp + 1];
    uint32_t hi, lo;
    fp16_split_pack(x0, x1, hi, lo);
    eHiT[i] = hi; eLoT[i] = lo;
}

// z [B][64] -> packed fp16 hi/lo transposed [dp][b]
__global__ void pack_zT(const float* __restrict__ z,
                        uint32_t* __restrict__ zHiT, uint32_t* __restrict__ zLoT){
    int i = blockIdx.x * 256 + threadIdx.x;   // i = dp*BATCH + b
    if (i >= 32*BATCH) return;
    int dp = i >> 15, b = i & (BATCH-1);
    float x0 = z[(size_t)b*DLAT + 2*dp];
    float x1 = z[(size_t)b*DLAT + 2*dp + 1];
    uint32_t hi, lo;
    fp16_split_pack(x0, x1, hi, lo);
    zHiT[i] = hi; zLoT[i] = lo;
}

// ============================================================================
// 1x-TF32 GEMM (decoder + head): C = act(A[M,K] @ W[K,N] + bias)
// ============================================================================
#define AST 20
#define BST 136
template<int ACT>
__global__ void __launch_bounds__(256, 2) mma_gemm_1x(
    const float* __restrict__ A, const float* __restrict__ W,
    const float* __restrict__ bias, float* __restrict__ C,
    int M, int N, int K)
{
    __shared__ float As[2][128][AST];
    __shared__ float Bs[2][16][BST];

    const int tid  = threadIdx.x;
    const int lane = tid & 31, warp = tid >> 5;
    const int wm = (warp & 1) * 64, wn = (warp >> 1) * 32;
    const int bm = blockIdx.y * 128, bn = blockIdx.x * 128;
    const int g = lane >> 2, tg = lane & 3;

    float acc[4][4][4];
    #pragma unroll
    for (int i = 0; i < 4; i++)
        #pragma unroll
        for (int j = 0; j < 4; j++)
            #pragma unroll
            for (int q = 0; q < 4; q++) acc[i][j][q] = 0.0f;

    const int ar = tid >> 1, ac = (tid & 1) * 8;
    const int br = tid >> 4, bc = (tid & 15) * 8;
    const float* Ap = A + (size_t)(bm + ar) * K + ac;
    const float* Bp = W + (size_t)br * N + bn + bc;

    const int ntiles = K >> 4;

    #define COPY_TILE(kt, buf) do { \
        const float* ap = Ap + (size_t)(kt) * 16; \
        cpasync16(&As[buf][ar][ac],   ap); \
        cpasync16(&As[buf][ar][ac+4], ap + 4); \
        const float* bp = Bp + (size_t)(kt) * 16 * N; \
        cpasync16(&Bs[buf][br][bc],   bp); \
        cpasync16(&Bs[buf][br][bc+4], bp + 4); \
        cpasync_commit(); \
    } while (0)

    COPY_TILE(0, 0);

    for (int i = 0; i < ntiles; i++){
        int buf = i & 1;
        if (i + 1 < ntiles){
            COPY_TILE(i + 1, buf ^ 1);
            cpasync_wait<1>();
        } else {
            cpasync_wait<0>();
        }
        __syncthreads();

        #pragma unroll
        for (int ks = 0; ks < 16; ks += 8){
            uint32_t a[4][4];
            #pragma unroll
            for (int mt = 0; mt < 4; mt++){
                int m = wm + mt*16 + g;
                a[mt][0] = __float_as_uint(As[buf][m  ][ks+tg]);
                a[mt][1] = __float_as_uint(As[buf][m+8][ks+tg]);
                a[mt][2] = __float_as_uint(As[buf][m  ][ks+tg+4]);
                a[mt][3] = __float_as_uint(As[buf][m+8][ks+tg+4]);
            }
            #pragma unroll
            for (int nt = 0; nt < 4; nt++){
                int n = wn + nt*8 + g;
                uint32_t b[2] = { __float_as_uint(Bs[buf][ks+tg  ][n]),
                                  __float_as_uint(Bs[buf][ks+tg+4][n]) };
                #pragma unroll
                for (int mt = 0; mt < 4; mt++) mma8(acc[mt][nt], a[mt], b);
            }
        }
        __syncthreads();
    }
    #undef COPY_TILE

    #pragma unroll
    for (int mt = 0; mt < 4; mt++){
        #pragma unroll
        for (int nt = 0; nt < 4; nt++){
            int row = bm + wm + mt*16 + g;
            int col = bn + wn + nt*8 + 2*tg;
            float bs0 = bias[col], bs1 = bias[col+1];
            float2 o0, o1;
            o0.x = apply_act<ACT>(acc[mt][nt][0] + bs0, col);
            o0.y = apply_act<ACT>(acc[mt][nt][1] + bs1, col+1);
            o1.x = apply_act<ACT>(acc[mt][nt][2] + bs0, col);
            o1.y = apply_act<ACT>(acc[mt][nt][3] + bs1, col+1);
            *(float2*)&C[(size_t)row*N + col]     = o0;
            *(float2*)&C[(size_t)(row+8)*N + col] = o1;
        }
    }
}

// ============================================================================
// split-3x GEMM v2 (encoder): cp.async double-buffered; A raw+in-reg split,
// B pre-split float2.
// ============================================================================
template<int ACT>
__global__ void __launch_bounds__(256, 2) mma_gemm_sb2(
    const float* __restrict__ A, const float2* __restrict__ B2,
    const float* __restrict__ bias, float* __restrict__ C,
    int M, int N, int K)
{
    __shared__ float  As[2][128][AST];
    __shared__ float2 Bs[2][16][128+SPAD];

    const int tid  = threadIdx.x;
    const int lane = tid & 31, warp = tid >> 5;
    const int wm = (warp & 1) * 64, wn = (warp >> 1) * 32;
    const int bm = blockIdx.y * 128, bn = blockIdx.x * 128;
    const int g = lane >> 2, tg = lane & 3;

    float acc[4][4][4];
    #pragma unroll
    for (int i = 0; i < 4; i++)
        #pragma unroll
        for (int j = 0; j < 4; j++)
            #pragma unroll
            for (int q = 0; q < 4; q++) acc[i][j][q] = 0.0f;

    const int ar = tid >> 1, ac = (tid & 1) * 8;
    const int br = tid >> 4, bcf2 = (tid & 15) * 8;
    const float*  Ap = A  + (size_t)(bm + ar) * K + ac;
    const float2* Bp = B2 + (size_t)br * N + bn + bcf2;

    const int ntiles = K >> 4;

    #define COPY_SB(kt, buf) do { \
        const float* ap = Ap + (size_t)(kt) * 16; \
        cpasync16(&As[buf][ar][ac],   ap); \
        cpasync16(&As[buf][ar][ac+4], ap + 4); \
        const float2* bp = Bp + (size_t)(kt) * 16 * N; \
        cpasync16(&Bs[buf][br][bcf2+0], bp); \
        cpasync16(&Bs[buf][br][bcf2+2], bp + 2); \
        cpasync16(&Bs[buf][br][bcf2+4], bp + 4); \
        cpasync16(&Bs[buf][br][bcf2+6], bp + 6); \
        cpasync_commit(); \
    } while (0)

    COPY_SB(0, 0);

    for (int i = 0; i < ntiles; i++){
        int buf = i & 1;
        if (i + 1 < ntiles){
            COPY_SB(i + 1, buf ^ 1);
            cpasync_wait<1>();
        } else {
            cpasync_wait<0>();
        }
        __syncthreads();

        #pragma unroll
        for (int ks = 0; ks < 16; ks += 8){
            uint32_t ah[4][4], al[4][4];
            #pragma unroll
            for (int mt = 0; mt < 4; mt++){
                int m = wm + mt*16 + g;
                float a0 = As[buf][m  ][ks+tg];
                float a1 = As[buf][m+8][ks+tg];
                float a2 = As[buf][m  ][ks+tg+4];
                float a3 = As[buf][m+8][ks+tg+4];
                split_u(a0, ah[mt][0], al[mt][0]);
                split_u(a1, ah[mt][1], al[mt][1]);
                split_u(a2, ah[mt][2], al[mt][2]);
                split_u(a3, ah[mt][3], al[mt][3]);
            }
            #pragma unroll
            for (int nt = 0; nt < 4; nt++){
                int n = wn + nt*8 + g;
                float2 w0 = Bs[buf][ks+tg  ][n];
                float2 w1 = Bs[buf][ks+tg+4][n];
                uint32_t bh[2] = { __float_as_uint(w0.x), __float_as_uint(w1.x) };
                uint32_t bl[2] = { __float_as_uint(w0.y), __float_as_uint(w1.y) };
                #pragma unroll
                for (int mt = 0; mt < 4; mt++) mma8(acc[mt][nt], ah[mt], bh);
                #pragma unroll
                for (int mt = 0; mt < 4; mt++) mma8(acc[mt][nt], al[mt], bh);
                #pragma unroll
                for (int mt = 0; mt < 4; mt++) mma8(acc[mt][nt], ah[mt], bl);
            }
        }
        __syncthreads();
    }
    #undef COPY_SB

    #pragma unroll
    for (int mt = 0; mt < 4; mt++){
        #pragma unroll
        for (int nt = 0; nt < 4; nt++){
            int row = bm + wm + mt*16 + g;
            int col = bn + wn + nt*8 + 2*tg;
            float bs0 = bias[col], bs1 = bias[col+1];
            float2 o0, o1;
            o0.x = apply_act<ACT>(acc[mt][nt][0] + bs0, col);
            o0.y = apply_act<ACT>(acc[mt][nt][1] + bs1, col+1);
            o1.x = apply_act<ACT>(acc[mt][nt][2] + bs0, col);
            o1.y = apply_act<ACT>(acc[mt][nt][3] + bs1, col+1);
            *(float2*)&C[(size_t)row*N + col]     = o0;
            *(float2*)&C[(size_t)(row+8)*N + col] = o1;
        }
    }
}

// ---------------- small-N SGEMM: 64 rows x N(<=64) cols ----------------
template<int ACT>
__global__ void __launch_bounds__(256) sgemm_smallN(
    const float* __restrict__ A, const float* __restrict__ W,
    const float* __restrict__ bias, float* __restrict__ C,
    int M, int N, int K)
{
    __shared__ float As[16][64];
    __shared__ float Bs[16][64];
    const int tid = threadIdx.x;
    const int bm = blockIdx.x * 64;
    const int arow = tid >> 2,  acol = (tid & 3) * 4;
    const int bkr  = tid >> 4,  bcol = (tid & 15) * 4;
    const int ty = tid >> 4, tx = tid & 15;

    float acc[4][4];
    #pragma unroll
    for (int i = 0; i < 4; i++)
        #pragma unroll
        for (int j = 0; j < 4; j++) acc[i][j] = 0.0f;

    for (int k0 = 0; k0 < K; k0 += 16){
        float4 av = *(const float4*)(A + (size_t)(bm + arow) * K + k0 + acol);
        As[acol+0][arow] = av.x;
        As[acol+1][arow] = av.y;
        As[acol+2][arow] = av.z;
        As[acol+3][arow] = av.w;
        float4 bv = make_float4(0.f,0.f,0.f,0.f);
        if (bcol < N) bv = *(const float4*)(W + (size_t)(k0 + bkr) * N + bcol);
        *(float4*)&Bs[bkr][bcol] = bv;
        __syncthreads();
        #pragma unroll
        for (int kk = 0; kk < 16; kk++){
            float a[4], b[4];
            *(float4*)a = *(const float4*)&As[kk][ty*4];
            *(float4*)b = *(const float4*)&Bs[kk][tx*4];
            #pragma unroll
            for (int i = 0; i < 4; i++)
                #pragma unroll
                for (int j = 0; j < 4; j++)
                    acc[i][j] = fmaf(a[i], b[j], acc[i][j]);
        }
        __syncthreads();
    }

    if (tx*4 < N){
        float bsv[4];
        #pragma unroll
        for (int j = 0; j < 4; j++) bsv[j] = bias[tx*4 + j];
        #pragma unroll
        for (int i = 0; i < 4; i++){
            float4 v;
            v.x = apply_act<ACT>(acc[i][0] + bsv[0], tx*4+0);
            v.y = apply_act<ACT>(acc[i][1] + bsv[1], tx*4+1);
            v.z = apply_act<ACT>(acc[i][2] + bsv[2], tx*4+2);
            v.w = apply_act<ACT>(acc[i][3] + bsv[3], tx*4+3);
            *(float4*)(C + (size_t)(bm + ty*4 + i) * N + tx*4) = v;
        }
    }
}

// ---------------- codebook norms ----------------
__global__ void enorm_kernel(const float* __restrict__ emb, float* __restrict__ enorm){
    int k = blockIdx.x * 256 + threadIdx.x;
    if (k >= KCODES) return;
    const float4* e = (const float4*)(emb + (size_t)k * DLAT);
    float s = 0.0f;
    #pragma unroll
    for (int q = 0; q < 16; q++){
        float4 v = e[q];
        s += v.x*v.x + v.y*v.y + v.z*v.z + v.w*v.w;
    }
    enorm[k] = s;
}

// ---------------- VQ argmin v4: fp16-split m16n8k16, pre-packed operands ----------------
// Same 3-product hi/lo split precision as tf32 (both 10-bit mantissa).
// ZH/ZL: [dp][m] half2 words, EH/EL: [2][dp][n]. Stride HS=136 -> conflict-free.
__global__ void __launch_bounds__(256, 2) vq_argmin_f16(
    const uint32_t* __restrict__ zHiT, const uint32_t* __restrict__ zLoT,
    const uint32_t* __restrict__ eHiT, const uint32_t* __restrict__ eLoT,
    const float* __restrict__ enorm, int* __restrict__ idx_out)
{
    __shared__ uint32_t ZH[32][HS], ZL[32][HS];
    __shared__ uint32_t EH[2][32][HS], EL[2][32][HS];

    const int tid  = threadIdx.x;
    const int lane = tid & 31, warp = tid >> 5;
    const int wm = (warp & 1) * 64, wn = (warp >> 1) * 32;
    const int bm = blockIdx.x * 128;
    const int g = lane >> 2, tg = lane & 3;

    // z tile: 32 dp rows x 128 cols; 1024 16B-units per array
    {
        #pragma unroll
        for (int j = 0; j < 4; j++){
            int unit = j*256 + tid;
            int dp = unit >> 5, u = unit & 31;
            cpasync16(&ZH[dp][u*4], zHiT + (size_t)dp*BATCH + bm + u*4);
            cpasync16(&ZL[dp][u*4], zLoT + (size_t)dp*BATCH + bm + u*4);
        }
        cpasync_commit();
    }

    #define COPY_EP(c0_, buf_) do { \
        _Pragma("unroll") \
        for (int j = 0; j < 4; j++){ \
            int unit = j*256 + tid; \
            int dp_ = unit >> 5, u_ = unit & 31; \
            cpasync16(&EH[buf_][dp_][u_*4], eHiT + (size_t)dp_*KCODES + (c0_) + u_*4); \
            cpasync16(&EL[buf_][dp_][u_*4], eLoT + (size_t)dp_*KCODES + (c0_) + u_*4); \
        } \
        cpasync_commit(); \
    } while (0)

    float mv[8]; int mi[8];
    #pragma unroll
    for (int s = 0; s < 8; s++){ mv[s] = INFINITY; mi[s] = 0; }

    COPY_EP(0, 0);

    for (int ch = 0; ch < KCODES/128; ch++){
        int c0 = ch * 128;
        int buf = ch & 1;
        if (ch + 1 < KCODES/128){
            COPY_EP(c0 + 128, buf ^ 1);
            cpasync_wait<1>();
        } else {
            cpasync_wait<0>();
        }
        __syncthreads();

        float acc[4][4][4];
        #pragma unroll
        for (int i = 0; i < 4; i++)
            #pragma unroll
            for (int j = 0; j < 4; j++)
                #pragma unroll
                for (int q = 0; q < 4; q++) acc[i][j][q] = 0.0f;

        #pragma unroll
        for (int kb = 0; kb < 4; kb++){         // 4 x k16 covers K=64
            uint32_t ah[4][4], al[4][4];
            #pragma unroll
            for (int mt = 0; mt < 4; mt++){
                int m = wm + mt*16 + g;
                ah[mt][0] = ZH[kb*8+tg  ][m];
                ah[mt][1] = ZH[kb*8+tg  ][m+8];
                ah[mt][2] = ZH[kb*8+tg+4][m];
                ah[mt][3] = ZH[kb*8+tg+4][m+8];
                al[mt][0] = ZL[kb*8+tg  ][m];
                al[mt][1] = ZL[kb*8+tg  ][m+8];
                al[mt][2] = ZL[kb*8+tg+4][m];
                al[mt][3] = ZL[kb*8+tg+4][m+8];
            }
            #pragma unroll
            for (int nt = 0; nt < 4; nt++){
                int n = wn + nt*8 + g;
                uint32_t bh[2] = { EH[buf][kb*8+tg][n], EH[buf][kb*8+tg+4][n] };
                uint32_t bl[2] = { EL[buf][kb*8+tg][n], EL[buf][kb*8+tg+4][n] };
                #pragma unroll
                for (int mt = 0; mt < 4; mt++) mma16(acc[mt][nt], ah[mt], bh);
                #pragma unroll
                for (int mt = 0; mt < 4; mt++) mma16(acc[mt][nt], al[mt], bh);
                #pragma unroll
                for (int mt = 0; mt < 4; mt++) mma16(acc[mt][nt], ah[mt], bl);
            }
        }

        // running argmin (ascending code order within thread; strict < keeps first min)
        #pragma unroll
        for (int nt = 0; nt < 4; nt++){
            int nc = wn + nt*8 + 2*tg;
            float e0 = __ldg(enorm + c0 + nc);
            float e1 = __ldg(enorm + c0 + nc + 1);
            int code = c0 + nc;
            #pragma unroll
            for (int mt = 0; mt < 4; mt++){
                float d00 = e0 - 2.0f*acc[mt][nt][0];
                float d01 = e1 - 2.0f*acc[mt][nt][1];
                float d10 = e0 - 2.0f*acc[mt][nt][2];
                float d11 = e1 - 2.0f*acc[mt][nt][3];
                int s0 = mt*2, s1 = mt*2 + 1;
                if (d00 < mv[s0]){ mv[s0] = d00; mi[s0] = code;   }
                if (d01 < mv[s0]){ mv[s0] = d01; mi[s0] = code+1; }
                if (d10 < mv[s1]){ mv[s1] = d10; mi[s1] = code;   }
                if (d11 < mv[s1]){ mv[s1] = d11; mi[s1] = code+1; }
            }
        }
        __syncthreads();
    }
    #undef COPY_EP

    // final reduction: 16 candidates x 128 rows (reuse EH)
    float* rv = (float*)&EH[0][0][0];
    int*   ri = ((int*)rv) + 16*128;
    int cand = (warp >> 1) * 4 + tg;      // 0..15
    #pragma unroll
    for (int s = 0; s < 8; s++){
        int r = wm + (s >> 1)*16 + g + (s & 1)*8;
        rv[cand*128 + r] = mv[s];
        ri[cand*128 + r] = mi[s];
    }
    __syncthreads();
    if (tid < 128){
        float bv = INFINITY; int bi = 0x7fffffff;
        #pragma unroll
        for (int t = 0; t < 16; t++){
            float v = rv[t*128 + tid];
            int c = ri[t*128 + tid];
            if (v < bv || (v == bv && c < bi)){ bv = v; bi = c; }
        }
        idx_out[bm + tid] = bi;
    }
}

// ---------------- gather z_q, idx-as-float, counts, commit-loss ----------------
__global__ void vq_post(const float* __restrict__ z, const float* __restrict__ emb,
                        const int* __restrict__ idx, float* __restrict__ zq,
                        float* __restrict__ counts, float* __restrict__ loss,
                        float* __restrict__ out_idx)
{
    int b = blockIdx.x * 256 + threadIdx.x;
    int k = idx[b];
    const float4* e  = (const float4*)(emb + (size_t)k * DLAT);
    const float4* zz = (const float4*)(z   + (size_t)b * DLAT);
    float4*       zo = (float4*)(zq + (size_t)b * DLAT);
    float s = 0.0f;
    #pragma unroll
    for (int q = 0; q < 16; q++){
        float4 ev = e[q], zv = zz[q];
        float dx = ev.x - zv.x, dy = ev.y - zv.y, dz = ev.z - zv.z, dw = ev.w - zv.w;
        s += dx*dx + dy*dy + dz*dz + dw*dw;
        zo[q] = ev;
    }
    out_idx[b] = (float)k;
    atomicAdd(&counts[k], 1.0f);

    __shared__ float red[256];
    red[threadIdx.x] = s;
    __syncthreads();
    for (int off = 128; off > 0; off >>= 1){
        if (threadIdx.x < off) red[threadIdx.x] += red[threadIdx.x + off];
        __syncthreads();
    }
    if (threadIdx.x == 0) atomicAdd(loss, red[0]);
}

// ---------------- perplexity + vq_loss scalars ----------------
__global__ void finalize_kernel(const float* __restrict__ counts, const float* __restrict__ loss,
                                float* __restrict__ out)
{
    __shared__ float red[256];
    float s = 0.0f;
    for (int k = threadIdx.x; k < KCODES; k += 256){
        float p = counts[k] * (1.0f / (float)BATCH);
        s += p * logf(p + 1e-10f);
    }
    red[threadIdx.x] = s;
    __syncthreads();
    for (int off = 128; off > 0; off >>= 1){
        if (threadIdx.x < off) red[threadIdx.x] += red[threadIdx.x + off];
        __syncthreads();
    }
    if (threadIdx.x == 0){
        out[PERP_OFF] = expf(-red[0]);
        out[LOSS_OFF] = loss[0] * (0.25f / ((float)BATCH * (float)DLAT));
    }
}

// ---------------- zero counts + loss ----------------
__global__ void zero_kernel(float* __restrict__ counts, float* __restrict__ loss){
    int i = blockIdx.x * 256 + threadIdx.x;
    if (i < KCODES) counts[i] = 0.0f;
    if (i == KCODES) loss[0] = 0.0f;
}

// ---------------- concat head weights -> [1024,128], biases -> [128] ----------------
__global__ void concat_head(const float* __restrict__ pW, const float* __restrict__ pb,
                            const float* __restrict__ wW, const float* __restrict__ wb,
                            const float* __restrict__ aW, const float* __restrict__ ab,
                            float* __restrict__ hw, float* __restrict__ hb)
{
    int i = blockIdx.x * 256 + threadIdx.x;
    int total = HIDDEN * 128;
    if (i < total){
        int k = i >> 7, col = i & 127;
        float v = 0.0f;
        if (col < 40)      v = pW[k*40 + col];
        else if (col < 42) v = wW[k*2 + (col-40)];
        else if (col < 44) v = aW[k*2 + (col-42)];
        hw[i] = v;
    }
    if (i < 128){
        float v = 0.0f;
        if (i < 40)      v = pb[i];
        else if (i < 42) v = wb[i-40];
        else if (i < 44) v = ab[i-42];
        hb[i] = v;
    }
}

// ---------------- pack outputs ----------------
__global__ void pack_kernel(const float* __restrict__ ho, float* __restrict__ out){
    int gid = blockIdx.x * 256 + threadIdx.x;
    int b = gid / 92, e = gid % 92;
    if (b >= BATCH) return;
    const float* h = ho + (size_t)b * 128;
    if (e < 40){
        out[P_OFF + (size_t)b*40 + e] = h[e];
    } else if (e < 88){
        int e2 = e - 40;
        int c  = e2 & 1;
        int j  = (e2 >> 1) & 3;
        int sg = (e2 >> 3) % 3;
        int p  = e2 / 24;
        out[CP_OFF + (size_t)b*48 + e2] = h[p*20 + (3*sg + j)*2 + c];
    } else if (e < 90){
        int p = e - 88;
        out[W_OFF + (size_t)b*2 + p] = h[40 + p];
    } else {
        int p = e - 90;
        out[A_OFF + (size_t)b*2 + p] = h[42 + p];
    }
}

// ---------------- launch ----------------
extern "C" void kernel_launch(void* const* d_in, const int* in_sizes, int n_in,
                              void* d_out, int out_size)
{
    (void)in_sizes; (void)n_in; (void)out_size;
    const float* x   = (const float*)d_in[0];
    const float* W1  = (const float*)d_in[1];
    const float* b1  = (const float*)d_in[2];
    const float* W2  = (const float*)d_in[3];
    const float* b2  = (const float*)d_in[4];
    const float* W3  = (const float*)d_in[5];
    const float* b3  = (const float*)d_in[6];
    const float* emb = (const float*)d_in[7];
    const float* dW1 = (const float*)d_in[8];
    const float* db1 = (const float*)d_in[9];
    const float* dW2 = (const float*)d_in[10];
    const float* db2 = (const float*)d_in[11];
    const float* pW  = (const float*)d_in[12];
    const float* pb  = (const float*)d_in[13];
    const float* wW  = (const float*)d_in[14];
    const float* wb  = (const float*)d_in[15];
    const float* aW  = (const float*)d_in[16];
    const float* ab  = (const float*)d_in[17];
    float* out = (float*)d_out;

    float *h1, *h2, *z, *zq, *d1, *d2, *ho, *counts, *loss, *enorm, *hw, *hb;
    float2 *W12, *W22;
    uint32_t *zHiT, *zLoT, *eHiT, *eLoT;
    int* idx;
    cudaGetSymbolAddress((void**)&h1, g_h1);
    cudaGetSymbolAddress((void**)&h2, g_h2);
    cudaGetSymbolAddress((void**)&z,  g_z);
    cudaGetSymbolAddress((void**)&zq, g_zq);
    cudaGetSymbolAddress((void**)&d1, g_d1);
    cudaGetSymbolAddress((void**)&d2, g_d2);
    cudaGetSymbolAddress((void**)&ho, g_ho);
    cudaGetSymbolAddress((void**)&idx, g_idx);
    cudaGetSymbolAddress((void**)&counts, g_counts);
    cudaGetSymbolAddress((void**)&loss, g_loss);
    cudaGetSymbolAddress((void**)&enorm, g_enorm);
    cudaGetSymbolAddress((void**)&hw, g_hw);
    cudaGetSymbolAddress((void**)&hb, g_hb);
    cudaGetSymbolAddress((void**)&W12, g_W12);
    cudaGetSymbolAddress((void**)&W22, g_W22);
    cudaGetSymbolAddress((void**)&zHiT, g_zHiT);
    cudaGetSymbolAddress((void**)&zLoT, g_zLoT);
    cudaGetSymbolAddress((void**)&eHiT, g_eHiT);
    cudaGetSymbolAddress((void**)&eLoT, g_eLoT);

    // init scalars/counts + head-weight concat + codebook norms + pre-splits
    zero_kernel<<<(KCODES + 1 + 255)/256, 256>>>(counts, loss);
    concat_head<<<(HIDDEN*128 + 255)/256, 256>>>(pW, pb, wW, wb, aW, ab, hw, hb);
    enorm_kernel<<<(KCODES + 255)/256, 256>>>(emb, enorm);
    split_arr<<<(784*256/4 + 255)/256, 256>>>(W1, W12, 784*256/4);
    split_arr<<<(256*256/4 + 255)/256, 256>>>(W2, W22, 256*256/4);
    pack_embT<<<(32*KCODES + 255)/256, 256>>>(emb, eHiT, eLoT);

    // encoder (split-3x tensor cores, pipelined, B pre-split)
    mma_gemm_sb2<ACT_LEAKY><<<dim3(2, BATCH/128), 256>>>(x,  W12, b1, h1, BATCH, 256, 784);
    mma_gemm_sb2<ACT_LEAKY><<<dim3(2, BATCH/128), 256>>>(h1, W22, b2, h2, BATCH, 256, 256);
    sgemm_smallN<ACT_NONE><<<BATCH/64, 256>>>(h2, W3, b3, z, BATCH, DLAT, 256);

    // VQ: pack z, fp16-split argmin, post
    pack_zT<<<(32*BATCH + 255)/256, 256>>>(z, zHiT, zLoT);
    vq_argmin_f16<<<BATCH/128, 256>>>(zHiT, zLoT, eHiT, eLoT, enorm, idx);
    vq_post<<<BATCH/256, 256>>>(z, emb, idx, zq, counts, loss, out + IDX_OFF);
    finalize_kernel<<<1, 256>>>(counts, loss, out);

    // decoder (tensor cores, 1x TF32 + cp.async pipeline)
    mma_gemm_1x<ACT_SELU><<<dim3(HIDDEN/128, BATCH/128), 256>>>(zq, dW1, db1, d1, BATCH, HIDDEN, DLAT);
    mma_gemm_1x<ACT_SELU><<<dim3(HIDDEN/128, BATCH/128), 256>>>(d1, dW2, db2, d2, BATCH, HIDDEN, HIDDEN);

    // head (1x TF32, N padded to 128)
    mma_gemm_1x<ACT_HEAD><<<dim3(1, BATCH/128), 256>>>(d2, hw, hb, ho, BATCH, 128, HIDDEN);

    // pack outputs
    pack_kernel<<<(BATCH*92 + 255)/256, 256>>>(ho, out);
}

// round 11
// speedup vs baseline: 1.6976x; 1.1543x over previous
#include <cuda_runtime.h>
#include <cuda_fp16.h>
#include <math.h>
#include <stdint.h>

// ---------------- problem constants ----------------
#define BATCH   32768
#define KCODES  4096
#define DLAT    64
#define HIDDEN  1024

// output layout (f32, reference return order, flattened+concat)
#define P_OFF    0
#define P_SIZE   (BATCH*40)
#define CP_OFF   (P_OFF + P_SIZE)
#define CP_SIZE  (BATCH*48)
#define W_OFF    (CP_OFF + CP_SIZE)
#define WA_SIZE  (BATCH*2)
#define A_OFF    (W_OFF + WA_SIZE)
#define LOSS_OFF (A_OFF + WA_SIZE)
#define IDX_OFF  (LOSS_OFF + 1)
#define PERP_OFF (IDX_OFF + BATCH)

#define HS 136           // VQ smem word stride (conflict-free)
#define AKP 12           // encoder A smem word stride (8 used + 4 pad; (12g+tg)%32 all-distinct)
#define BNP 136          // encoder B smem word stride

// ---------------- scratch (__device__ globals; no allocation allowed) ----------------
__device__ float  g_h2 [BATCH*256];
__device__ float  g_z  [BATCH*DLAT];
__device__ float  g_zq [BATCH*DLAT];
__device__ float  g_d1 [BATCH*HIDDEN];
__device__ float  g_d2 [BATCH*HIDDEN];
__device__ float  g_ho [BATCH*128];       // head out, stride 128 (padded)
__device__ int    g_idx[BATCH];
__device__ float  g_counts[KCODES];
__device__ float  g_loss;
__device__ float  g_enorm[KCODES];
__device__ float  g_hw [HIDDEN*128];      // padded head weights [1024,128]
__device__ float  g_hb [128];
// fp16-split packed operands
__device__ uint32_t g_xH [BATCH*392];     // x   [m][kp], kp = 784/2
__device__ uint32_t g_xL [BATCH*392];
__device__ uint32_t g_w1H[392*256];       // W1  [kp][n]
__device__ uint32_t g_w1L[392*256];
__device__ uint32_t g_h1H[BATCH*128];     // h1  [m][kp], kp = 256/2
__device__ uint32_t g_h1L[BATCH*128];
__device__ uint32_t g_w2H[128*256];       // W2  [kp][n]
__device__ uint32_t g_w2L[128*256];
__device__ uint32_t g_zHiT[32*BATCH];     // z transposed [dp][b]
__device__ uint32_t g_zLoT[32*BATCH];
__device__ uint32_t g_eHiT[32*KCODES];    // codebook transposed [dp][code]
__device__ uint32_t g_eLoT[32*KCODES];

// ---------------- activations ----------------
#define ACT_NONE 0
#define ACT_LEAKY 1
#define ACT_SELU 2
#define ACT_HEAD 3

__device__ __forceinline__ float sigmoidf_(float x){ return 1.0f/(1.0f+expf(-x)); }

template<int ACT>
__device__ __forceinline__ float apply_act(float v, int col){
    if (ACT == ACT_LEAKY) return v > 0.0f ? v : 0.2f*v;
    if (ACT == ACT_SELU){
        const float a = 1.6732632423543772f, s = 1.0507009873554805f;
        return v > 0.0f ? s*v : s*a*(expf(v)-1.0f);
    }
    if (ACT == ACT_HEAD){
        if (col < 40) return tanhf(v)*12.0f + 14.0f;
        if (col < 42) return sigmoidf_(v)*2.0f + 1.0f;
        return sigmoidf_(v);
    }
    return v;
}

// ---------------- fp16 split pack helper ----------------
__device__ __forceinline__ void fp16_split_pack(float x0, float x1,
                                                uint32_t& hi, uint32_t& lo){
    __half h0 = __float2half_rn(x0), h1 = __float2half_rn(x1);
    __half l0 = __float2half_rn(x0 - __half2float(h0));
    __half l1 = __float2half_rn(x1 - __half2float(h1));
    __half2 hh = __halves2half2(h0, h1);
    __half2 ll = __halves2half2(l0, l1);
    hi = *(uint32_t*)&hh;
    lo = *(uint32_t*)&ll;
}

// D += A*B, m16n8k8 tf32 (decoder/head path, raw fp32 bits)
__device__ __forceinline__ void mma8(float* c, const uint32_t* a, const uint32_t* b){
    asm volatile(
        "mma.sync.aligned.m16n8k8.row.col.f32.tf32.tf32.f32 "
        "{%0,%1,%2,%3}, {%4,%5,%6,%7}, {%8,%9}, {%0,%1,%2,%3};\n"
        : "+f"(c[0]), "+f"(c[1]), "+f"(c[2]), "+f"(c[3])
        : "r"(a[0]), "r"(a[1]), "r"(a[2]), "r"(a[3]), "r"(b[0]), "r"(b[1]));
}

// D += A*B, m16n8k16 fp16 (fp32 accum)
__device__ __forceinline__ void mma16(float* c, const uint32_t* a, const uint32_t* b){
    asm volatile(
        "mma.sync.aligned.m16n8k16.row.col.f32.f16.f16.f32 "
        "{%0,%1,%2,%3}, {%4,%5,%6,%7}, {%8,%9}, {%0,%1,%2,%3};\n"
        : "+f"(c[0]), "+f"(c[1]), "+f"(c[2]), "+f"(c[3])
        : "r"(a[0]), "r"(a[1]), "r"(a[2]), "r"(a[3]), "r"(b[0]), "r"(b[1]));
}

// ---------------- cp.async helpers ----------------
__device__ __forceinline__ void cpasync16(void* dst_smem, const void* src){
    uint32_t s = (uint32_t)__cvta_generic_to_shared(dst_smem);
    asm volatile("cp.async.cg.shared.global [%0], [%1], 16;\n" :: "r"(s), "l"(src));
}
__device__ __forceinline__ void cpasync_commit(){ asm volatile("cp.async.commit_group;\n"); }
template<int NN>
__device__ __forceinline__ void cpasync_wait(){ asm volatile("cp.async.wait_group %0;\n" :: "n"(NN)); }

// ---------------- pack kernels ----------------
// row-major A pack: src [M][K] -> dst [M][K/2] hi/lo words
__global__ void pack_rowsA(const float* __restrict__ src,
                           uint32_t* __restrict__ hiA, uint32_t* __restrict__ loA,
                           int nwords){
    int i = blockIdx.x * 256 + threadIdx.x;
    if (i >= nwords) return;
    float2 v = ((const float2*)src)[i];
    uint32_t hi, lo;
    fp16_split_pack(v.x, v.y, hi, lo);
    hiA[i] = hi; loA[i] = lo;
}

// B pack: W [K][N] -> [K/2][N] words (pairs along k)
__global__ void pack_W(const float* __restrict__ W,
                       uint32_t* __restrict__ hiW, uint32_t* __restrict__ loW,
                       int KP, int N){
    int i = blockIdx.x * 256 + threadIdx.x;
    if (i >= KP*N) return;
    int kp = i / N, n = i % N;
    float x0 = W[(size_t)(2*kp)*N + n];
    float x1 = W[(size_t)(2*kp+1)*N + n];
    uint32_t hi, lo;
    fp16_split_pack(x0, x1, hi, lo);
    hiW[i] = hi; loW[i] = lo;
}

// emb [K][64] -> packed fp16 hi/lo transposed [dp][code]
__global__ void pack_embT(const float* __restrict__ emb,
                          uint32_t* __restrict__ eHiT, uint32_t* __restrict__ eLoT){
    int i = blockIdx.x * 256 + threadIdx.x;
    if (i >= 32*KCODES) return;
    int dp = i >> 12, c = i & (KCODES-1);
    float x0 = emb[(size_t)c*DLAT + 2*dp];
    float x1 = emb[(size_t)c*DLAT + 2*dp + 1];
    uint32_t hi, lo;
    fp16_split_pack(x0, x1, hi, lo);
    eHiT[i] = hi; eLoT[i] = lo;
}

// z [B][64] -> packed fp16 hi/lo transposed [dp][b]
__global__ void pack_zT(const float* __restrict__ z,
                        uint32_t* __restrict__ zHiT, uint32_t* __restrict__ zLoT){
    int i = blockIdx.x * 256 + threadIdx.x;
    if (i >= 32*BATCH) return;
    int dp = i >> 15, b = i & (BATCH-1);
    float x0 = z[(size_t)b*DLAT + 2*dp];
    float x1 = z[(size_t)b*DLAT + 2*dp + 1];
    uint32_t hi, lo;
    fp16_split_pack(x0, x1, hi, lo);
    zHiT[i] = hi; zLoT[i] = lo;
}

// ============================================================================
// fp16-split GEMM (encoder): C = act(A[M,K] @ B[K,N] + bias), 3-product hi/lo.
// A packed [m][kp] words, B packed [kp][n] words. 128x128 tile, BK=16 floats
// (8 kp = one k16 block per tile), cp.async double-buffered.
// OUTPACK=1: write C as packed hi/lo words (for chaining); else fp32 C.
// ============================================================================
template<int ACT, int OUTPACK>
__global__ void __launch_bounds__(256, 2) mma_gemm_f16(
    const uint32_t* __restrict__ AH, const uint32_t* __restrict__ AL,
    const uint32_t* __restrict__ BH, const uint32_t* __restrict__ BL,
    const float* __restrict__ bias, float* __restrict__ C,
    uint32_t* __restrict__ CH, uint32_t* __restrict__ CL,
    int M, int N, int K)
{
    __shared__ uint32_t AsH[2][128][AKP], AsL[2][128][AKP];
    __shared__ uint32_t BsH[2][8][BNP],   BsL[2][8][BNP];

    const int tid  = threadIdx.x;
    const int lane = tid & 31, warp = tid >> 5;
    const int wm = (warp & 1) * 64, wn = (warp >> 1) * 32;
    const int bm = blockIdx.y * 128, bn = blockIdx.x * 128;
    const int g = lane >> 2, tg = lane & 3;
    const int KP = K >> 1;

    float acc[4][4][4];
    #pragma unroll
    for (int i = 0; i < 4; i++)
        #pragma unroll
        for (int j = 0; j < 4; j++)
            #pragma unroll
            for (int q = 0; q < 4; q++) acc[i][j][q] = 0.0f;

    const int ar = tid >> 1, ac = (tid & 1) * 4;     // A: 128 rows x 8 words
    const int br = tid >> 5, bc = (lane) * 4;        // B: 8 rows x 128 words
    const uint32_t* AHp = AH + (size_t)(bm + ar) * KP + ac;
    const uint32_t* ALp = AL + (size_t)(bm + ar) * KP + ac;
    const uint32_t* BHp = BH + (size_t)br * N + bn + bc;
    const uint32_t* BLp = BL + (size_t)br * N + bn + bc;

    const int ntiles = K >> 4;   // 8 kp per tile

    #define COPY_F16(kt, buf) do { \
        cpasync16(&AsH[buf][ar][ac], AHp + (size_t)(kt)*8); \
        cpasync16(&AsL[buf][ar][ac], ALp + (size_t)(kt)*8); \
        cpasync16(&BsH[buf][br][bc], BHp + (size_t)(kt)*8*N); \
        cpasync16(&BsL[buf][br][bc], BLp + (size_t)(kt)*8*N); \
        cpasync_commit(); \
    } while (0)

    COPY_F16(0, 0);

    for (int i = 0; i < ntiles; i++){
        int buf = i & 1;
        if (i + 1 < ntiles){
            COPY_F16(i + 1, buf ^ 1);
            cpasync_wait<1>();
        } else {
            cpasync_wait<0>();
        }
        __syncthreads();

        uint32_t ah[4][4], al[4][4];
        #pragma unroll
        for (int mt = 0; mt < 4; mt++){
            int m = wm + mt*16 + g;
            ah[mt][0] = AsH[buf][m  ][tg];
            ah[mt][1] = AsH[buf][m+8][tg];
            ah[mt][2] = AsH[buf][m  ][tg+4];
            ah[mt][3] = AsH[buf][m+8][tg+4];
            al[mt][0] = AsL[buf][m  ][tg];
            al[mt][1] = AsL[buf][m+8][tg];
            al[mt][2] = AsL[buf][m  ][tg+4];
            al[mt][3] = AsL[buf][m+8][tg+4];
        }
        #pragma unroll
        for (int nt = 0; nt < 4; nt++){
            int n = wn + nt*8 + g;
            uint32_t bh[2] = { BsH[buf][tg][n], BsH[buf][tg+4][n] };
            uint32_t bl[2] = { BsL[buf][tg][n], BsL[buf][tg+4][n] };
            #pragma unroll
            for (int mt = 0; mt < 4; mt++) mma16(acc[mt][nt], ah[mt], bh);
            #pragma unroll
            for (int mt = 0; mt < 4; mt++) mma16(acc[mt][nt], al[mt], bh);
            #pragma unroll
            for (int mt = 0; mt < 4; mt++) mma16(acc[mt][nt], ah[mt], bl);
        }
        __syncthreads();
    }
    #undef COPY_F16

    // epilogue
    #pragma unroll
    for (int mt = 0; mt < 4; mt++){
        #pragma unroll
        for (int nt = 0; nt < 4; nt++){
            int row = bm + wm + mt*16 + g;
            int col = bn + wn + nt*8 + 2*tg;
            float bs0 = bias[col], bs1 = bias[col+1];
            float v00 = apply_act<ACT>(acc[mt][nt][0] + bs0, col);
            float v01 = apply_act<ACT>(acc[mt][nt][1] + bs1, col+1);
            float v10 = apply_act<ACT>(acc[mt][nt][2] + bs0, col);
            float v11 = apply_act<ACT>(acc[mt][nt][3] + bs1, col+1);
            if (OUTPACK){
                int w = col >> 1;
                int NP = N >> 1;
                uint32_t h0, l0, h1, l1;
                fp16_split_pack(v00, v01, h0, l0);
                fp16_split_pack(v10, v11, h1, l1);
                CH[(size_t)row*NP + w]     = h0;
                CL[(size_t)row*NP + w]     = l0;
                CH[(size_t)(row+8)*NP + w] = h1;
                CL[(size_t)(row+8)*NP + w] = l1;
            } else {
                *(float2*)&C[(size_t)row*N + col]     = make_float2(v00, v01);
                *(float2*)&C[(size_t)(row+8)*N + col] = make_float2(v10, v11);
            }
        }
    }
}

// ============================================================================
// 1x-TF32 GEMM (decoder + head): C = act(A[M,K] @ W[K,N] + bias)
// ============================================================================
#define AST 20
#define BST 136
template<int ACT>
__global__ void __launch_bounds__(256, 2) mma_gemm_1x(
    const float* __restrict__ A, const float* __restrict__ W,
    const float* __restrict__ bias, float* __restrict__ C,
    int M, int N, int K)
{
    __shared__ float As[2][128][AST];
    __shared__ float Bs[2][16][BST];

    const int tid  = threadIdx.x;
    const int lane = tid & 31, warp = tid >> 5;
    const int wm = (warp & 1) * 64, wn = (warp >> 1) * 32;
    const int bm = blockIdx.y * 128, bn = blockIdx.x * 128;
    const int g = lane >> 2, tg = lane & 3;

    float acc[4][4][4];
    #pragma unroll
    for (int i = 0; i < 4; i++)
        #pragma unroll
        for (int j = 0; j < 4; j++)
            #pragma unroll
            for (int q = 0; q < 4; q++) acc[i][j][q] = 0.0f;

    const int ar = tid >> 1, ac = (tid & 1) * 8;
    const int br = tid >> 4, bc = (tid & 15) * 8;
    const float* Ap = A + (size_t)(bm + ar) * K + ac;
    const float* Bp = W + (size_t)br * N + bn + bc;

    const int ntiles = K >> 4;

    #define COPY_TILE(kt, buf) do { \
        const float* ap = Ap + (size_t)(kt) * 16; \
        cpasync16(&As[buf][ar][ac],   ap); \
        cpasync16(&As[buf][ar][ac+4], ap + 4); \
        const float* bp = Bp + (size_t)(kt) * 16 * N; \
        cpasync16(&Bs[buf][br][bc],   bp); \
        cpasync16(&Bs[buf][br][bc+4], bp + 4); \
        cpasync_commit(); \
    } while (0)

    COPY_TILE(0, 0);

    for (int i = 0; i < ntiles; i++){
        int buf = i & 1;
        if (i + 1 < ntiles){
            COPY_TILE(i + 1, buf ^ 1);
            cpasync_wait<1>();
        } else {
            cpasync_wait<0>();
        }
        __syncthreads();

        #pragma unroll
        for (int ks = 0; ks < 16; ks += 8){
            uint32_t a[4][4];
            #pragma unroll
            for (int mt = 0; mt < 4; mt++){
                int m = wm + mt*16 + g;
                a[mt][0] = __float_as_uint(As[buf][m  ][ks+tg]);
                a[mt][1] = __float_as_uint(As[buf][m+8][ks+tg]);
                a[mt][2] = __float_as_uint(As[buf][m  ][ks+tg+4]);
                a[mt][3] = __float_as_uint(As[buf][m+8][ks+tg+4]);
            }
            #pragma unroll
            for (int nt = 0; nt < 4; nt++){
                int n = wn + nt*8 + g;
                uint32_t b[2] = { __float_as_uint(Bs[buf][ks+tg  ][n]),
                                  __float_as_uint(Bs[buf][ks+tg+4][n]) };
                #pragma unroll
                for (int mt = 0; mt < 4; mt++) mma8(acc[mt][nt], a[mt], b);
            }
        }
        __syncthreads();
    }
    #undef COPY_TILE

    #pragma unroll
    for (int mt = 0; mt < 4; mt++){
        #pragma unroll
        for (int nt = 0; nt < 4; nt++){
            int row = bm + wm + mt*16 + g;
            int col = bn + wn + nt*8 + 2*tg;
            float bs0 = bias[col], bs1 = bias[col+1];
            float2 o0, o1;
            o0.x = apply_act<ACT>(acc[mt][nt][0] + bs0, col);
            o0.y = apply_act<ACT>(acc[mt][nt][1] + bs1, col+1);
            o1.x = apply_act<ACT>(acc[mt][nt][2] + bs0, col);
            o1.y = apply_act<ACT>(acc[mt][nt][3] + bs1, col+1);
            *(float2*)&C[(size_t)row*N + col]     = o0;
            *(float2*)&C[(size_t)(row+8)*N + col] = o1;
        }
    }
}

// ---------------- small-N SGEMM: 64 rows x N(<=64) cols ----------------
template<int ACT>
__global__ void __launch_bounds__(256) sgemm_smallN(
    const float* __restrict__ A, const float* __restrict__ W,
    const float* __restrict__ bias, float* __restrict__ C,
    int M, int N, int K)
{
    __shared__ float As[16][64];
    __shared__ float Bs[16][64];
    const int tid = threadIdx.x;
    const int bm = blockIdx.x * 64;
    const int arow = tid >> 2,  acol = (tid & 3) * 4;
    const int bkr  = tid >> 4,  bcol = (tid & 15) * 4;
    const int ty = tid >> 4, tx = tid & 15;

    float acc[4][4];
    #pragma unroll
    for (int i = 0; i < 4; i++)
        #pragma unroll
        for (int j = 0; j < 4; j++) acc[i][j] = 0.0f;

    for (int k0 = 0; k0 < K; k0 += 16){
        float4 av = *(const float4*)(A + (size_t)(bm + arow) * K + k0 + acol);
        As[acol+0][arow] = av.x;
        As[acol+1][arow] = av.y;
        As[acol+2][arow] = av.z;
        As[acol+3][arow] = av.w;
        float4 bv = make_float4(0.f,0.f,0.f,0.f);
        if (bcol < N) bv = *(const float4*)(W + (size_t)(k0 + bkr) * N + bcol);
        *(float4*)&Bs[bkr][bcol] = bv;
        __syncthreads();
        #pragma unroll
        for (int kk = 0; kk < 16; kk++){
            float a[4], b[4];
            *(float4*)a = *(const float4*)&As[kk][ty*4];
            *(float4*)b = *(const float4*)&Bs[kk][tx*4];
            #pragma unroll
            for (int i = 0; i < 4; i++)
                #pragma unroll
                for (int j = 0; j < 4; j++)
                    acc[i][j] = fmaf(a[i], b[j], acc[i][j]);
        }
        __syncthreads();
    }

    if (tx*4 < N){
        float bsv[4];
        #pragma unroll
        for (int j = 0; j < 4; j++) bsv[j] = bias[tx*4 + j];
        #pragma unroll
        for (int i = 0; i < 4; i++){
            float4 v;
            v.x = apply_act<ACT>(acc[i][0] + bsv[0], tx*4+0);
            v.y = apply_act<ACT>(acc[i][1] + bsv[1], tx*4+1);
            v.z = apply_act<ACT>(acc[i][2] + bsv[2], tx*4+2);
            v.w = apply_act<ACT>(acc[i][3] + bsv[3], tx*4+3);
            *(float4*)(C + (size_t)(bm + ty*4 + i) * N + tx*4) = v;
        }
    }
}

// ---------------- codebook norms ----------------
__global__ void enorm_kernel(const float* __restrict__ emb, float* __restrict__ enorm){
    int k = blockIdx.x * 256 + threadIdx.x;
    if (k >= KCODES) return;
    const float4* e = (const float4*)(emb + (size_t)k * DLAT);
    float s = 0.0f;
    #pragma unroll
    for (int q = 0; q < 16; q++){
        float4 v = e[q];
        s += v.x*v.x + v.y*v.y + v.z*v.z + v.w*v.w;
    }
    enorm[k] = s;
}

// ---------------- VQ argmin: fp16-split m16n8k16, pre-packed operands ----------------
__global__ void __launch_bounds__(256, 2) vq_argmin_f16(
    const uint32_t* __restrict__ zHiT, const uint32_t* __restrict__ zLoT,
    const uint32_t* __restrict__ eHiT, const uint32_t* __restrict__ eLoT,
    const float* __restrict__ enorm, int* __restrict__ idx_out)
{
    __shared__ uint32_t ZH[32][HS], ZL[32][HS];
    __shared__ uint32_t EH[2][32][HS], EL[2][32][HS];

    const int tid  = threadIdx.x;
    const int lane = tid & 31, warp = tid >> 5;
    const int wm = (warp & 1) * 64, wn = (warp >> 1) * 32;
    const int bm = blockIdx.x * 128;
    const int g = lane >> 2, tg = lane & 3;

    {
        #pragma unroll
        for (int j = 0; j < 4; j++){
            int unit = j*256 + tid;
            int dp = unit >> 5, u = unit & 31;
            cpasync16(&ZH[dp][u*4], zHiT + (size_t)dp*BATCH + bm + u*4);
            cpasync16(&ZL[dp][u*4], zLoT + (size_t)dp*BATCH + bm + u*4);
        }
        cpasync_commit();
    }

    #define COPY_EP(c0_, buf_) do { \
        _Pragma("unroll") \
        for (int j = 0; j < 4; j++){ \
            int unit = j*256 + tid; \
            int dp_ = unit >> 5, u_ = unit & 31; \
            cpasync16(&EH[buf_][dp_][u_*4], eHiT + (size_t)dp_*KCODES + (c0_) + u_*4); \
            cpasync16(&EL[buf_][dp_][u_*4], eLoT + (size_t)dp_*KCODES + (c0_) + u_*4); \
        } \
        cpasync_commit(); \
    } while (0)

    float mv[8]; int mi[8];
    #pragma unroll
    for (int s = 0; s < 8; s++){ mv[s] = INFINITY; mi[s] = 0; }

    COPY_EP(0, 0);

    for (int ch = 0; ch < KCODES/128; ch++){
        int c0 = ch * 128;
        int buf = ch & 1;
        if (ch + 1 < KCODES/128){
            COPY_EP(c0 + 128, buf ^ 1);
            cpasync_wait<1>();
        } else {
            cpasync_wait<0>();
        }
        __syncthreads();

        float acc[4][4][4];
        #pragma unroll
        for (int i = 0; i < 4; i++)
            #pragma unroll
            for (int j = 0; j < 4; j++)
                #pragma unroll
                for (int q = 0; q < 4; q++) acc[i][j][q] = 0.0f;

        #pragma unroll
        for (int kb = 0; kb < 4; kb++){         // 4 x k16 covers K=64
            uint32_t ah[4][4], al[4][4];
            #pragma unroll
            for (int mt = 0; mt < 4; mt++){
                int m = wm + mt*16 + g;
                ah[mt][0] = ZH[kb*8+tg  ][m];
                ah[mt][1] = ZH[kb*8+tg  ][m+8];
                ah[mt][2] = ZH[kb*8+tg+4][m];
                ah[mt][3] = ZH[kb*8+tg+4][m+8];
                al[mt][0] = ZL[kb*8+tg  ][m];
                al[mt][1] = ZL[kb*8+tg  ][m+8];
                al[mt][2] = ZL[kb*8+tg+4][m];
                al[mt][3] = ZL[kb*8+tg+4][m+8];
            }
            #pragma unroll
            for (int nt = 0; nt < 4; nt++){
                int n = wn + nt*8 + g;
                uint32_t bh[2] = { EH[buf][kb*8+tg][n], EH[buf][kb*8+tg+4][n] };
                uint32_t bl[2] = { EL[buf][kb*8+tg][n], EL[buf][kb*8+tg+4][n] };
                #pragma unroll
                for (int mt = 0; mt < 4; mt++) mma16(acc[mt][nt], ah[mt], bh);
                #pragma unroll
                for (int mt = 0; mt < 4; mt++) mma16(acc[mt][nt], al[mt], bh);
                #pragma unroll
                for (int mt = 0; mt < 4; mt++) mma16(acc[mt][nt], ah[mt], bl);
            }
        }

        // running argmin (ascending code order within thread; strict < keeps first min)
        #pragma unroll
        for (int nt = 0; nt < 4; nt++){
            int nc = wn + nt*8 + 2*tg;
            float e0 = __ldg(enorm + c0 + nc);
            float e1 = __ldg(enorm + c0 + nc + 1);
            int code = c0 + nc;
            #pragma unroll
            for (int mt = 0; mt < 4; mt++){
                float d00 = e0 - 2.0f*acc[mt][nt][0];
                float d01 = e1 - 2.0f*acc[mt][nt][1];
                float d10 = e0 - 2.0f*acc[mt][nt][2];
                float d11 = e1 - 2.0f*acc[mt][nt][3];
                int s0 = mt*2, s1 = mt*2 + 1;
                if (d00 < mv[s0]){ mv[s0] = d00; mi[s0] = code;   }
                if (d01 < mv[s0]){ mv[s0] = d01; mi[s0] = code+1; }
                if (d10 < mv[s1]){ mv[s1] = d10; mi[s1] = code;   }
                if (d11 < mv[s1]){ mv[s1] = d11; mi[s1] = code+1; }
            }
        }
        __syncthreads();
    }
    #undef COPY_EP

    // final reduction: 16 candidates x 128 rows (reuse EH)
    float* rv = (float*)&EH[0][0][0];
    int*   ri = ((int*)rv) + 16*128;
    int cand = (warp >> 1) * 4 + tg;      // 0..15
    #pragma unroll
    for (int s = 0; s < 8; s++){
        int r = wm + (s >> 1)*16 + g + (s & 1)*8;
        rv[cand*128 + r] = mv[s];
        ri[cand*128 + r] = mi[s];
    }
    __syncthreads();
    if (tid < 128){
        float bv = INFINITY; int bi = 0x7fffffff;
        #pragma unroll
        for (int t = 0; t < 16; t++){
            float v = rv[t*128 + tid];
            int c = ri[t*128 + tid];
            if (v < bv || (v == bv && c < bi)){ bv = v; bi = c; }
        }
        idx_out[bm + tid] = bi;
    }
}

// ---------------- gather z_q, idx-as-float, counts, commit-loss ----------------
__global__ void vq_post(const float* __restrict__ z, const float* __restrict__ emb,
                        const int* __restrict__ idx, float* __restrict__ zq,
                        float* __restrict__ counts, float* __restrict__ loss,
                        float* __restrict__ out_idx)
{
    int b = blockIdx.x * 256 + threadIdx.x;
    int k = idx[b];
    const float4* e  = (const float4*)(emb + (size_t)k * DLAT);
    const float4* zz = (const float4*)(z   + (size_t)b * DLAT);
    float4*       zo = (float4*)(zq + (size_t)b * DLAT);
    float s = 0.0f;
    #pragma unroll
    for (int q = 0; q < 16; q++){
        float4 ev = e[q], zv = zz[q];
        float dx = ev.x - zv.x, dy = ev.y - zv.y, dz = ev.z - zv.z, dw = ev.w - zv.w;
        s += dx*dx + dy*dy + dz*dz + dw*dw;
        zo[q] = ev;
    }
    out_idx[b] = (float)k;
    atomicAdd(&counts[k], 1.0f);

    __shared__ float red[256];
    red[threadIdx.x] = s;
    __syncthreads();
    for (int off = 128; off > 0; off >>= 1){
        if (threadIdx.x < off) red[threadIdx.x] += red[threadIdx.x + off];
        __syncthreads();
    }
    if (threadIdx.x == 0) atomicAdd(loss, red[0]);
}

// ---------------- perplexity + vq_loss scalars ----------------
__global__ void finalize_kernel(const float* __restrict__ counts, const float* __restrict__ loss,
                                float* __restrict__ out)
{
    __shared__ float red[256];
    float s = 0.0f;
    for (int k = threadIdx.x; k < KCODES; k += 256){
        float p = counts[k] * (1.0f / (float)BATCH);
        s += p * logf(p + 1e-10f);
    }
    red[threadIdx.x] = s;
    __syncthreads();
    for (int off = 128; off > 0; off >>= 1){
        if (threadIdx.x < off) red[threadIdx.x] += red[threadIdx.x + off];
        __syncthreads();
    }
    if (threadIdx.x == 0){
        out[PERP_OFF] = expf(-red[0]);
        out[LOSS_OFF] = loss[0] * (0.25f / ((float)BATCH * (float)DLAT));
    }
}

// ---------------- zero counts + loss ----------------
__global__ void zero_kernel(float* __restrict__ counts, float* __restrict__ loss){
    int i = blockIdx.x * 256 + threadIdx.x;
    if (i < KCODES) counts[i] = 0.0f;
    if (i == KCODES) loss[0] = 0.0f;
}

// ---------------- concat head weights -> [1024,128], biases -> [128] ----------------
__global__ void concat_head(const float* __restrict__ pW, const float* __restrict__ pb,
                            const float* __restrict__ wW, const float* __restrict__ wb,
                            const float* __restrict__ aW, const float* __restrict__ ab,
                            float* __restrict__ hw, float* __restrict__ hb)
{
    int i = blockIdx.x * 256 + threadIdx.x;
    int total = HIDDEN * 128;
    if (i < total){
        int k = i >> 7, col = i & 127;
        float v = 0.0f;
        if (col < 40)      v = pW[k*40 + col];
        else if (col < 42) v = wW[k*2 + (col-40)];
        else if (col < 44) v = aW[k*2 + (col-42)];
        hw[i] = v;
    }
    if (i < 128){
        float v = 0.0f;
        if (i < 40)      v = pb[i];
        else if (i < 42) v = wb[i-40];
        else if (i < 44) v = ab[i-42];
        hb[i] = v;
    }
}

// ---------------- pack outputs ----------------
__global__ void pack_kernel(const float* __restrict__ ho, float* __restrict__ out){
    int gid = blockIdx.x * 256 + threadIdx.x;
    int b = gid / 92, e = gid % 92;
    if (b >= BATCH) return;
    const float* h = ho + (size_t)b * 128;
    if (e < 40){
        out[P_OFF + (size_t)b*40 + e] = h[e];
    } else if (e < 88){
        int e2 = e - 40;
        int c  = e2 & 1;
        int j  = (e2 >> 1) & 3;
        int sg = (e2 >> 3) % 3;
        int p  = e2 / 24;
        out[CP_OFF + (size_t)b*48 + e2] = h[p*20 + (3*sg + j)*2 + c];
    } else if (e < 90){
        int p = e - 88;
        out[W_OFF + (size_t)b*2 + p] = h[40 + p];
    } else {
        int p = e - 90;
        out[A_OFF + (size_t)b*2 + p] = h[42 + p];
    }
}

// ---------------- launch ----------------
extern "C" void kernel_launch(void* const* d_in, const int* in_sizes, int n_in,
                              void* d_out, int out_size)
{
    (void)in_sizes; (void)n_in; (void)out_size;
    const float* x   = (const float*)d_in[0];
    const float* W1  = (const float*)d_in[1];
    const float* b1  = (const float*)d_in[2];
    const float* W2  = (const float*)d_in[3];
    const float* b2  = (const float*)d_in[4];
    const float* W3  = (const float*)d_in[5];
    const float* b3  = (const float*)d_in[6];
    const float* emb = (const float*)d_in[7];
    const float* dW1 = (const float*)d_in[8];
    const float* db1 = (const float*)d_in[9];
    const float* dW2 = (const float*)d_in[10];
    const float* db2 = (const float*)d_in[11];
    const float* pW  = (const float*)d_in[12];
    const float* pb  = (const float*)d_in[13];
    const float* wW  = (const float*)d_in[14];
    const float* wb  = (const float*)d_in[15];
    const float* aW  = (const float*)d_in[16];
    const float* ab  = (const float*)d_in[17];
    float* out = (float*)d_out;

    float *h2, *z, *zq, *d1, *d2, *ho, *counts, *loss, *enorm, *hw, *hb;
    uint32_t *xH, *xL, *w1H, *w1L, *h1H, *h1L, *w2H, *w2L;
    uint32_t *zHiT, *zLoT, *eHiT, *eLoT;
    int* idx;
    cudaGetSymbolAddress((void**)&h2, g_h2);
    cudaGetSymbolAddress((void**)&z,  g_z);
    cudaGetSymbolAddress((void**)&zq, g_zq);
    cudaGetSymbolAddress((void**)&d1, g_d1);
    cudaGetSymbolAddress((void**)&d2, g_d2);
    cudaGetSymbolAddress((void**)&ho, g_ho);
    cudaGetSymbolAddress((void**)&idx, g_idx);
    cudaGetSymbolAddress((void**)&counts, g_counts);
    cudaGetSymbolAddress((void**)&loss, g_loss);
    cudaGetSymbolAddress((void**)&enorm, g_enorm);
    cudaGetSymbolAddress((void**)&hw, g_hw);
    cudaGetSymbolAddress((void**)&hb, g_hb);
    cudaGetSymbolAddress((void**)&xH, g_xH);
    cudaGetSymbolAddress((void**)&xL, g_xL);
    cudaGetSymbolAddress((void**)&w1H, g_w1H);
    cudaGetSymbolAddress((void**)&w1L, g_w1L);
    cudaGetSymbolAddress((void**)&h1H, g_h1H);
    cudaGetSymbolAddress((void**)&h1L, g_h1L);
    cudaGetSymbolAddress((void**)&w2H, g_w2H);
    cudaGetSymbolAddress((void**)&w2L, g_w2L);
    cudaGetSymbolAddress((void**)&zHiT, g_zHiT);
    cudaGetSymbolAddress((void**)&zLoT, g_zLoT);
    cudaGetSymbolAddress((void**)&eHiT, g_eHiT);
    cudaGetSymbolAddress((void**)&eLoT, g_eLoT);

    // init scalars/counts + head-weight concat + codebook norms + packs
    zero_kernel<<<(KCODES + 1 + 255)/256, 256>>>(counts, loss);
    concat_head<<<(HIDDEN*128 + 255)/256, 256>>>(pW, pb, wW, wb, aW, ab, hw, hb);
    enorm_kernel<<<(KCODES + 255)/256, 256>>>(emb, enorm);
    pack_rowsA<<<(BATCH*392 + 255)/256, 256>>>(x, xH, xL, BATCH*392);
    pack_W<<<(392*256 + 255)/256, 256>>>(W1, w1H, w1L, 392, 256);
    pack_W<<<(128*256 + 255)/256, 256>>>(W2, w2H, w2L, 128, 256);
    pack_embT<<<(32*KCODES + 255)/256, 256>>>(emb, eHiT, eLoT);

    // encoder (fp16-split 3-product tensor cores, fully pipelined)
    mma_gemm_f16<ACT_LEAKY, 1><<<dim3(2, BATCH/128), 256>>>(
        xH, xL, w1H, w1L, b1, nullptr, h1H, h1L, BATCH, 256, 784);
    mma_gemm_f16<ACT_LEAKY, 0><<<dim3(2, BATCH/128), 256>>>(
        h1H, h1L, w2H, w2L, b2, h2, nullptr, nullptr, BATCH, 256, 256);
    sgemm_smallN<ACT_NONE><<<BATCH/64, 256>>>(h2, W3, b3, z, BATCH, DLAT, 256);

    // VQ: pack z, fp16-split argmin, post
    pack_zT<<<(32*BATCH + 255)/256, 256>>>(z, zHiT, zLoT);
    vq_argmin_f16<<<BATCH/128, 256>>>(zHiT, zLoT, eHiT, eLoT, enorm, idx);
    vq_post<<<BATCH/256, 256>>>(z, emb, idx, zq, counts, loss, out + IDX_OFF);
    finalize_kernel<<<1, 256>>>(counts, loss, out);

    // decoder (tensor cores, 1x TF32 + cp.async pipeline)
    mma_gemm_1x<ACT_SELU><<<dim3(HIDDEN/128, BATCH/128), 256>>>(zq, dW1, db1, d1, BATCH, HIDDEN, DLAT);
    mma_gemm_1x<ACT_SELU><<<dim3(HIDDEN/128, BATCH/128), 256>>>(d1, dW2, db2, d2, BATCH, HIDDEN, HIDDEN);

    // head (1x TF32, N padded to 128)
    mma_gemm_1x<ACT_HEAD><<<dim3(1, BATCH/128), 256>>>(d2, hw, hb, ho, BATCH, 128, HIDDEN);

    // pack outputs
    pack_kernel<<<(BATCH*92 + 255)/256, 256>>>(ho, out);
}

// round 12
// speedup vs baseline: 2.2315x; 1.3145x over previous
#include <cuda_runtime.h>
#include <cuda_fp16.h>
#include <math.h>
#include <stdint.h>

// ---------------- problem constants ----------------
#define BATCH   32768
#define KCODES  4096
#define DLAT    64
#define HIDDEN  1024

// output layout (f32, reference return order, flattened+concat)
#define P_OFF    0
#define P_SIZE   (BATCH*40)
#define CP_OFF   (P_OFF + P_SIZE)
#define CP_SIZE  (BATCH*48)
#define W_OFF    (CP_OFF + CP_SIZE)
#define WA_SIZE  (BATCH*2)
#define A_OFF    (W_OFF + WA_SIZE)
#define LOSS_OFF (A_OFF + WA_SIZE)
#define IDX_OFF  (LOSS_OFF + 1)
#define PERP_OFF (IDX_OFF + BATCH)

#define HS 136           // VQ smem word stride (conflict-free)
#define AKP 12           // A smem word stride (8 used + 4 pad)
#define BNP 136          // B smem word stride

// ---------------- scratch (__device__ globals; no allocation allowed) ----------------
__device__ float  g_h2 [BATCH*256];
__device__ float  g_z  [BATCH*DLAT];
__device__ float  g_ho [BATCH*128];       // head out, stride 128 (padded)
__device__ int    g_idx[BATCH];
__device__ float  g_counts[KCODES];
__device__ float  g_loss;
__device__ float  g_enorm[KCODES];
__device__ float  g_hw [HIDDEN*128];      // padded head weights [1024,128]
__device__ float  g_hb [128];
// fp16-split packed operands (encoder + VQ)
__device__ uint32_t g_xH [BATCH*392];
__device__ uint32_t g_xL [BATCH*392];
__device__ uint32_t g_w1H[392*256];
__device__ uint32_t g_w1L[392*256];
__device__ uint32_t g_h1H[BATCH*128];
__device__ uint32_t g_h1L[BATCH*128];
__device__ uint32_t g_w2H[128*256];
__device__ uint32_t g_w2L[128*256];
__device__ uint32_t g_zHiT[32*BATCH];
__device__ uint32_t g_zLoT[32*BATCH];
__device__ uint32_t g_eHiT[32*KCODES];
__device__ uint32_t g_eLoT[32*KCODES];
// fp16 hi-only packed (decoder)
__device__ uint32_t g_zqH [BATCH*32];     // zq  [m][kp], kp = 64/2
__device__ uint32_t g_dW1H[32*HIDDEN];    // dW1 [kp][1024]
__device__ uint32_t g_d1H [BATCH*512];    // d1  [m][kp]
__device__ uint32_t g_dW2H[512*HIDDEN];   // dW2 [kp][1024]
__device__ uint32_t g_d2H [BATCH*512];    // d2  [m][kp]
__device__ uint32_t g_hwH [512*128];      // head W [kp][128]

// ---------------- activations ----------------
#define ACT_NONE 0
#define ACT_LEAKY 1
#define ACT_SELU 2
#define ACT_HEAD 3

__device__ __forceinline__ float sigmoidf_(float x){ return 1.0f/(1.0f+expf(-x)); }

template<int ACT>
__device__ __forceinline__ float apply_act(float v, int col){
    if (ACT == ACT_LEAKY) return v > 0.0f ? v : 0.2f*v;
    if (ACT == ACT_SELU){
        const float a = 1.6732632423543772f, s = 1.0507009873554805f;
        return v > 0.0f ? s*v : s*a*(expf(v)-1.0f);
    }
    if (ACT == ACT_HEAD){
        if (col < 40) return tanhf(v)*12.0f + 14.0f;
        if (col < 42) return sigmoidf_(v)*2.0f + 1.0f;
        return sigmoidf_(v);
    }
    return v;
}

// ---------------- fp16 pack helpers ----------------
__device__ __forceinline__ void fp16_split_pack(float x0, float x1,
                                                uint32_t& hi, uint32_t& lo){
    __half h0 = __float2half_rn(x0), h1 = __float2half_rn(x1);
    __half l0 = __float2half_rn(x0 - __half2float(h0));
    __half l1 = __float2half_rn(x1 - __half2float(h1));
    __half2 hh = __halves2half2(h0, h1);
    __half2 ll = __halves2half2(l0, l1);
    hi = *(uint32_t*)&hh;
    lo = *(uint32_t*)&ll;
}
__device__ __forceinline__ uint32_t fp16_pack_hi(float x0, float x1){
    __half2 hh = __halves2half2(__float2half_rn(x0), __float2half_rn(x1));
    return *(uint32_t*)&hh;
}

// D += A*B, m16n8k16 fp16 (fp32 accum)
__device__ __forceinline__ void mma16(float* c, const uint32_t* a, const uint32_t* b){
    asm volatile(
        "mma.sync.aligned.m16n8k16.row.col.f32.f16.f16.f32 "
        "{%0,%1,%2,%3}, {%4,%5,%6,%7}, {%8,%9}, {%0,%1,%2,%3};\n"
        : "+f"(c[0]), "+f"(c[1]), "+f"(c[2]), "+f"(c[3])
        : "r"(a[0]), "r"(a[1]), "r"(a[2]), "r"(a[3]), "r"(b[0]), "r"(b[1]));
}

// ---------------- cp.async helpers ----------------
__device__ __forceinline__ void cpasync16(void* dst_smem, const void* src){
    uint32_t s = (uint32_t)__cvta_generic_to_shared(dst_smem);
    asm volatile("cp.async.cg.shared.global [%0], [%1], 16;\n" :: "r"(s), "l"(src));
}
__device__ __forceinline__ void cpasync_commit(){ asm volatile("cp.async.commit_group;\n"); }
template<int NN>
__device__ __forceinline__ void cpasync_wait(){ asm volatile("cp.async.wait_group %0;\n" :: "n"(NN)); }

// ---------------- pack kernels ----------------
__global__ void pack_rowsA(const float* __restrict__ src,
                           uint32_t* __restrict__ hiA, uint32_t* __restrict__ loA,
                           int nwords){
    int i = blockIdx.x * 256 + threadIdx.x;
    if (i >= nwords) return;
    float2 v = ((const float2*)src)[i];
    uint32_t hi, lo;
    fp16_split_pack(v.x, v.y, hi, lo);
    hiA[i] = hi; loA[i] = lo;
}

__global__ void pack_W(const float* __restrict__ W,
                       uint32_t* __restrict__ hiW, uint32_t* __restrict__ loW,
                       int KP, int N){
    int i = blockIdx.x * 256 + threadIdx.x;
    if (i >= KP*N) return;
    int kp = i / N, n = i % N;
    float x0 = W[(size_t)(2*kp)*N + n];
    float x1 = W[(size_t)(2*kp+1)*N + n];
    uint32_t hi, lo;
    fp16_split_pack(x0, x1, hi, lo);
    hiW[i] = hi; loW[i] = lo;
}

// hi-only W pack (decoder path)
__global__ void pack_Wh(const float* __restrict__ W,
                        uint32_t* __restrict__ hiW, int KP, int N){
    int i = blockIdx.x * 256 + threadIdx.x;
    if (i >= KP*N) return;
    int kp = i / N, n = i % N;
    hiW[i] = fp16_pack_hi(W[(size_t)(2*kp)*N + n], W[(size_t)(2*kp+1)*N + n]);
}

__global__ void pack_embT(const float* __restrict__ emb,
                          uint32_t* __restrict__ eHiT, uint32_t* __restrict__ eLoT){
    int i = blockIdx.x * 256 + threadIdx.x;
    if (i >= 32*KCODES) return;
    int dp = i >> 12, c = i & (KCODES-1);
    float x0 = emb[(size_t)c*DLAT + 2*dp];
    float x1 = emb[(size_t)c*DLAT + 2*dp + 1];
    uint32_t hi, lo;
    fp16_split_pack(x0, x1, hi, lo);
    eHiT[i] = hi; eLoT[i] = lo;
}

__global__ void pack_zT(const float* __restrict__ z,
                        uint32_t* __restrict__ zHiT, uint32_t* __restrict__ zLoT){
    int i = blockIdx.x * 256 + threadIdx.x;
    if (i >= 32*BATCH) return;
    int dp = i >> 15, b = i & (BATCH-1);
    float x0 = z[(size_t)b*DLAT + 2*dp];
    float x1 = z[(size_t)b*DLAT + 2*dp + 1];
    uint32_t hi, lo;
    fp16_split_pack(x0, x1, hi, lo);
    zHiT[i] = hi; zLoT[i] = lo;
}

// ============================================================================
// fp16-split GEMM (encoder): 3-product hi/lo. A [m][kp], B [kp][n].
// ============================================================================
template<int ACT, int OUTPACK>
__global__ void __launch_bounds__(256, 2) mma_gemm_f16(
    const uint32_t* __restrict__ AH, const uint32_t* __restrict__ AL,
    const uint32_t* __restrict__ BH, const uint32_t* __restrict__ BL,
    const float* __restrict__ bias, float* __restrict__ C,
    uint32_t* __restrict__ CH, uint32_t* __restrict__ CL,
    int M, int N, int K)
{
    __shared__ uint32_t AsH[2][128][AKP], AsL[2][128][AKP];
    __shared__ uint32_t BsH[2][8][BNP],   BsL[2][8][BNP];

    const int tid  = threadIdx.x;
    const int lane = tid & 31, warp = tid >> 5;
    const int wm = (warp & 1) * 64, wn = (warp >> 1) * 32;
    const int bm = blockIdx.y * 128, bn = blockIdx.x * 128;
    const int g = lane >> 2, tg = lane & 3;
    const int KP = K >> 1;

    float acc[4][4][4];
    #pragma unroll
    for (int i = 0; i < 4; i++)
        #pragma unroll
        for (int j = 0; j < 4; j++)
            #pragma unroll
            for (int q = 0; q < 4; q++) acc[i][j][q] = 0.0f;

    const int ar = tid >> 1, ac = (tid & 1) * 4;
    const int br = tid >> 5, bc = lane * 4;
    const uint32_t* AHp = AH + (size_t)(bm + ar) * KP + ac;
    const uint32_t* ALp = AL + (size_t)(bm + ar) * KP + ac;
    const uint32_t* BHp = BH + (size_t)br * N + bn + bc;
    const uint32_t* BLp = BL + (size_t)br * N + bn + bc;

    const int ntiles = K >> 4;

    #define COPY_F16(kt, buf) do { \
        cpasync16(&AsH[buf][ar][ac], AHp + (size_t)(kt)*8); \
        cpasync16(&AsL[buf][ar][ac], ALp + (size_t)(kt)*8); \
        cpasync16(&BsH[buf][br][bc], BHp + (size_t)(kt)*8*N); \
        cpasync16(&BsL[buf][br][bc], BLp + (size_t)(kt)*8*N); \
        cpasync_commit(); \
    } while (0)

    COPY_F16(0, 0);

    for (int i = 0; i < ntiles; i++){
        int buf = i & 1;
        if (i + 1 < ntiles){
            COPY_F16(i + 1, buf ^ 1);
            cpasync_wait<1>();
        } else {
            cpasync_wait<0>();
        }
        __syncthreads();

        uint32_t ah[4][4], al[4][4];
        #pragma unroll
        for (int mt = 0; mt < 4; mt++){
            int m = wm + mt*16 + g;
            ah[mt][0] = AsH[buf][m  ][tg];
            ah[mt][1] = AsH[buf][m+8][tg];
            ah[mt][2] = AsH[buf][m  ][tg+4];
            ah[mt][3] = AsH[buf][m+8][tg+4];
            al[mt][0] = AsL[buf][m  ][tg];
            al[mt][1] = AsL[buf][m+8][tg];
            al[mt][2] = AsL[buf][m  ][tg+4];
            al[mt][3] = AsL[buf][m+8][tg+4];
        }
        #pragma unroll
        for (int nt = 0; nt < 4; nt++){
            int n = wn + nt*8 + g;
            uint32_t bh[2] = { BsH[buf][tg][n], BsH[buf][tg+4][n] };
            uint32_t bl[2] = { BsL[buf][tg][n], BsL[buf][tg+4][n] };
            #pragma unroll
            for (int mt = 0; mt < 4; mt++) mma16(acc[mt][nt], ah[mt], bh);
            #pragma unroll
            for (int mt = 0; mt < 4; mt++) mma16(acc[mt][nt], al[mt], bh);
            #pragma unroll
            for (int mt = 0; mt < 4; mt++) mma16(acc[mt][nt], ah[mt], bl);
        }
        __syncthreads();
    }
    #undef COPY_F16

    #pragma unroll
    for (int mt = 0; mt < 4; mt++){
        #pragma unroll
        for (int nt = 0; nt < 4; nt++){
            int row = bm + wm + mt*16 + g;
            int col = bn + wn + nt*8 + 2*tg;
            float bs0 = bias[col], bs1 = bias[col+1];
            float v00 = apply_act<ACT>(acc[mt][nt][0] + bs0, col);
            float v01 = apply_act<ACT>(acc[mt][nt][1] + bs1, col+1);
            float v10 = apply_act<ACT>(acc[mt][nt][2] + bs0, col);
            float v11 = apply_act<ACT>(acc[mt][nt][3] + bs1, col+1);
            if (OUTPACK){
                int w = col >> 1;
                int NP = N >> 1;
                uint32_t h0, l0, h1, l1;
                fp16_split_pack(v00, v01, h0, l0);
                fp16_split_pack(v10, v11, h1, l1);
                CH[(size_t)row*NP + w]     = h0;
                CL[(size_t)row*NP + w]     = l0;
                CH[(size_t)(row+8)*NP + w] = h1;
                CL[(size_t)(row+8)*NP + w] = l1;
            } else {
                *(float2*)&C[(size_t)row*N + col]     = make_float2(v00, v01);
                *(float2*)&C[(size_t)(row+8)*N + col] = make_float2(v10, v11);
            }
        }
    }
}

// ============================================================================
// fp16 hi-only GEMM (decoder + head): 1-product. A [m][kp], B [kp][n].
// OUTPACK=1: write C packed hi words for chaining; else fp32 C.
// ============================================================================
template<int ACT, int OUTPACK>
__global__ void __launch_bounds__(256, 2) mma_gemm_h16(
    const uint32_t* __restrict__ AH, const uint32_t* __restrict__ BH,
    const float* __restrict__ bias, float* __restrict__ C,
    uint32_t* __restrict__ CH,
    int M, int N, int K)
{
    __shared__ uint32_t AsH[2][128][AKP];
    __shared__ uint32_t BsH[2][8][BNP];

    const int tid  = threadIdx.x;
    const int lane = tid & 31, warp = tid >> 5;
    const int wm = (warp & 1) * 64, wn = (warp >> 1) * 32;
    const int bm = blockIdx.y * 128, bn = blockIdx.x * 128;
    const int g = lane >> 2, tg = lane & 3;
    const int KP = K >> 1;

    float acc[4][4][4];
    #pragma unroll
    for (int i = 0; i < 4; i++)
        #pragma unroll
        for (int j = 0; j < 4; j++)
            #pragma unroll
            for (int q = 0; q < 4; q++) acc[i][j][q] = 0.0f;

    const int ar = tid >> 1, ac = (tid & 1) * 4;
    const int br = tid >> 5, bc = lane * 4;
    const uint32_t* AHp = AH + (size_t)(bm + ar) * KP + ac;
    const uint32_t* BHp = BH + (size_t)br * N + bn + bc;

    const int ntiles = K >> 4;

    #define COPY_H16(kt, buf) do { \
        cpasync16(&AsH[buf][ar][ac], AHp + (size_t)(kt)*8); \
        cpasync16(&BsH[buf][br][bc], BHp + (size_t)(kt)*8*N); \
        cpasync_commit(); \
    } while (0)

    COPY_H16(0, 0);

    for (int i = 0; i < ntiles; i++){
        int buf = i & 1;
        if (i + 1 < ntiles){
            COPY_H16(i + 1, buf ^ 1);
            cpasync_wait<1>();
        } else {
            cpasync_wait<0>();
        }
        __syncthreads();

        uint32_t ah[4][4];
        #pragma unroll
        for (int mt = 0; mt < 4; mt++){
            int m = wm + mt*16 + g;
            ah[mt][0] = AsH[buf][m  ][tg];
            ah[mt][1] = AsH[buf][m+8][tg];
            ah[mt][2] = AsH[buf][m  ][tg+4];
            ah[mt][3] = AsH[buf][m+8][tg+4];
        }
        #pragma unroll
        for (int nt = 0; nt < 4; nt++){
            int n = wn + nt*8 + g;
            uint32_t bh[2] = { BsH[buf][tg][n], BsH[buf][tg+4][n] };
            #pragma unroll
            for (int mt = 0; mt < 4; mt++) mma16(acc[mt][nt], ah[mt], bh);
        }
        __syncthreads();
    }
    #undef COPY_H16

    #pragma unroll
    for (int mt = 0; mt < 4; mt++){
        #pragma unroll
        for (int nt = 0; nt < 4; nt++){
            int row = bm + wm + mt*16 + g;
            int col = bn + wn + nt*8 + 2*tg;
            float bs0 = bias[col], bs1 = bias[col+1];
            float v00 = apply_act<ACT>(acc[mt][nt][0] + bs0, col);
            float v01 = apply_act<ACT>(acc[mt][nt][1] + bs1, col+1);
            float v10 = apply_act<ACT>(acc[mt][nt][2] + bs0, col);
            float v11 = apply_act<ACT>(acc[mt][nt][3] + bs1, col+1);
            if (OUTPACK){
                int w = col >> 1;
                int NP = N >> 1;
                CH[(size_t)row*NP + w]     = fp16_pack_hi(v00, v01);
                CH[(size_t)(row+8)*NP + w] = fp16_pack_hi(v10, v11);
            } else {
                *(float2*)&C[(size_t)row*N + col]     = make_float2(v00, v01);
                *(float2*)&C[(size_t)(row+8)*N + col] = make_float2(v10, v11);
            }
        }
    }
}

// ---------------- small-N SGEMM: 64 rows x N(<=64) cols ----------------
template<int ACT>
__global__ void __launch_bounds__(256) sgemm_smallN(
    const float* __restrict__ A, const float* __restrict__ W,
    const float* __restrict__ bias, float* __restrict__ C,
    int M, int N, int K)
{
    __shared__ float As[16][64];
    __shared__ float Bs[16][64];
    const int tid = threadIdx.x;
    const int bm = blockIdx.x * 64;
    const int arow = tid >> 2,  acol = (tid & 3) * 4;
    const int bkr  = tid >> 4,  bcol = (tid & 15) * 4;
    const int ty = tid >> 4, tx = tid & 15;

    float acc[4][4];
    #pragma unroll
    for (int i = 0; i < 4; i++)
        #pragma unroll
        for (int j = 0; j < 4; j++) acc[i][j] = 0.0f;

    for (int k0 = 0; k0 < K; k0 += 16){
        float4 av = *(const float4*)(A + (size_t)(bm + arow) * K + k0 + acol);
        As[acol+0][arow] = av.x;
        As[acol+1][arow] = av.y;
        As[acol+2][arow] = av.z;
        As[acol+3][arow] = av.w;
        float4 bv = make_float4(0.f,0.f,0.f,0.f);
        if (bcol < N) bv = *(const float4*)(W + (size_t)(k0 + bkr) * N + bcol);
        *(float4*)&Bs[bkr][bcol] = bv;
        __syncthreads();
        #pragma unroll
        for (int kk = 0; kk < 16; kk++){
            float a[4], b[4];
            *(float4*)a = *(const float4*)&As[kk][ty*4];
            *(float4*)b = *(const float4*)&Bs[kk][tx*4];
            #pragma unroll
            for (int i = 0; i < 4; i++)
                #pragma unroll
                for (int j = 0; j < 4; j++)
                    acc[i][j] = fmaf(a[i], b[j], acc[i][j]);
        }
        __syncthreads();
    }

    if (tx*4 < N){
        float bsv[4];
        #pragma unroll
        for (int j = 0; j < 4; j++) bsv[j] = bias[tx*4 + j];
        #pragma unroll
        for (int i = 0; i < 4; i++){
            float4 v;
            v.x = apply_act<ACT>(acc[i][0] + bsv[0], tx*4+0);
            v.y = apply_act<ACT>(acc[i][1] + bsv[1], tx*4+1);
            v.z = apply_act<ACT>(acc[i][2] + bsv[2], tx*4+2);
            v.w = apply_act<ACT>(acc[i][3] + bsv[3], tx*4+3);
            *(float4*)(C + (size_t)(bm + ty*4 + i) * N + tx*4) = v;
        }
    }
}

// ---------------- codebook norms ----------------
__global__ void enorm_kernel(const float* __restrict__ emb, float* __restrict__ enorm){
    int k = blockIdx.x * 256 + threadIdx.x;
    if (k >= KCODES) return;
    const float4* e = (const float4*)(emb + (size_t)k * DLAT);
    float s = 0.0f;
    #pragma unroll
    for (int q = 0; q < 16; q++){
        float4 v = e[q];
        s += v.x*v.x + v.y*v.y + v.z*v.z + v.w*v.w;
    }
    enorm[k] = s;
}

// ---------------- VQ argmin: fp16-split m16n8k16, pre-packed operands ----------------
__global__ void __launch_bounds__(256, 2) vq_argmin_f16(
    const uint32_t* __restrict__ zHiT, const uint32_t* __restrict__ zLoT,
    const uint32_t* __restrict__ eHiT, const uint32_t* __restrict__ eLoT,
    const float* __restrict__ enorm, int* __restrict__ idx_out)
{
    __shared__ uint32_t ZH[32][HS], ZL[32][HS];
    __shared__ uint32_t EH[2][32][HS], EL[2][32][HS];

    const int tid  = threadIdx.x;
    const int lane = tid & 31, warp = tid >> 5;
    const int wm = (warp & 1) * 64, wn = (warp >> 1) * 32;
    const int bm = blockIdx.x * 128;
    const int g = lane >> 2, tg = lane & 3;

    {
        #pragma unroll
        for (int j = 0; j < 4; j++){
            int unit = j*256 + tid;
            int dp = unit >> 5, u = unit & 31;
            cpasync16(&ZH[dp][u*4], zHiT + (size_t)dp*BATCH + bm + u*4);
            cpasync16(&ZL[dp][u*4], zLoT + (size_t)dp*BATCH + bm + u*4);
        }
        cpasync_commit();
    }

    #define COPY_EP(c0_, buf_) do { \
        _Pragma("unroll") \
        for (int j = 0; j < 4; j++){ \
            int unit = j*256 + tid; \
            int dp_ = unit >> 5, u_ = unit & 31; \
            cpasync16(&EH[buf_][dp_][u_*4], eHiT + (size_t)dp_*KCODES + (c0_) + u_*4); \
            cpasync16(&EL[buf_][dp_][u_*4], eLoT + (size_t)dp_*KCODES + (c0_) + u_*4); \
        } \
        cpasync_commit(); \
    } while (0)

    float mv[8]; int mi[8];
    #pragma unroll
    for (int s = 0; s < 8; s++){ mv[s] = INFINITY; mi[s] = 0; }

    COPY_EP(0, 0);

    for (int ch = 0; ch < KCODES/128; ch++){
        int c0 = ch * 128;
        int buf = ch & 1;
        if (ch + 1 < KCODES/128){
            COPY_EP(c0 + 128, buf ^ 1);
            cpasync_wait<1>();
        } else {
            cpasync_wait<0>();
        }
        __syncthreads();

        float acc[4][4][4];
        #pragma unroll
        for (int i = 0; i < 4; i++)
            #pragma unroll
            for (int j = 0; j < 4; j++)
                #pragma unroll
                for (int q = 0; q < 4; q++) acc[i][j][q] = 0.0f;

        #pragma unroll
        for (int kb = 0; kb < 4; kb++){
            uint32_t ah[4][4], al[4][4];
            #pragma unroll
            for (int mt = 0; mt < 4; mt++){
                int m = wm + mt*16 + g;
                ah[mt][0] = ZH[kb*8+tg  ][m];
                ah[mt][1] = ZH[kb*8+tg  ][m+8];
                ah[mt][2] = ZH[kb*8+tg+4][m];
                ah[mt][3] = ZH[kb*8+tg+4][m+8];
                al[mt][0] = ZL[kb*8+tg  ][m];
                al[mt][1] = ZL[kb*8+tg  ][m+8];
                al[mt][2] = ZL[kb*8+tg+4][m];
                al[mt][3] = ZL[kb*8+tg+4][m+8];
            }
            #pragma unroll
            for (int nt = 0; nt < 4; nt++){
                int n = wn + nt*8 + g;
                uint32_t bh[2] = { EH[buf][kb*8+tg][n], EH[buf][kb*8+tg+4][n] };
                uint32_t bl[2] = { EL[buf][kb*8+tg][n], EL[buf][kb*8+tg+4][n] };
                #pragma unroll
                for (int mt = 0; mt < 4; mt++) mma16(acc[mt][nt], ah[mt], bh);
                #pragma unroll
                for (int mt = 0; mt < 4; mt++) mma16(acc[mt][nt], al[mt], bh);
                #pragma unroll
                for (int mt = 0; mt < 4; mt++) mma16(acc[mt][nt], ah[mt], bl);
            }
        }

        #pragma unroll
        for (int nt = 0; nt < 4; nt++){
            int nc = wn + nt*8 + 2*tg;
            float e0 = __ldg(enorm + c0 + nc);
            float e1 = __ldg(enorm + c0 + nc + 1);
            int code = c0 + nc;
            #pragma unroll
            for (int mt = 0; mt < 4; mt++){
                float d00 = e0 - 2.0f*acc[mt][nt][0];
                float d01 = e1 - 2.0f*acc[mt][nt][1];
                float d10 = e0 - 2.0f*acc[mt][nt][2];
                float d11 = e1 - 2.0f*acc[mt][nt][3];
                int s0 = mt*2, s1 = mt*2 + 1;
                if (d00 < mv[s0]){ mv[s0] = d00; mi[s0] = code;   }
                if (d01 < mv[s0]){ mv[s0] = d01; mi[s0] = code+1; }
                if (d10 < mv[s1]){ mv[s1] = d10; mi[s1] = code;   }
                if (d11 < mv[s1]){ mv[s1] = d11; mi[s1] = code+1; }
            }
        }
        __syncthreads();
    }
    #undef COPY_EP

    float* rv = (float*)&EH[0][0][0];
    int*   ri = ((int*)rv) + 16*128;
    int cand = (warp >> 1) * 4 + tg;
    #pragma unroll
    for (int s = 0; s < 8; s++){
        int r = wm + (s >> 1)*16 + g + (s & 1)*8;
        rv[cand*128 + r] = mv[s];
        ri[cand*128 + r] = mi[s];
    }
    __syncthreads();
    if (tid < 128){
        float bv = INFINITY; int bi = 0x7fffffff;
        #pragma unroll
        for (int t = 0; t < 16; t++){
            float v = rv[t*128 + tid];
            int c = ri[t*128 + tid];
            if (v < bv || (v == bv && c < bi)){ bv = v; bi = c; }
        }
        idx_out[bm + tid] = bi;
    }
}

// ---------------- gather: packed fp16 zq, idx-as-float, counts, commit-loss ----------------
__global__ void vq_post(const float* __restrict__ z, const float* __restrict__ emb,
                        const int* __restrict__ idx, uint32_t* __restrict__ zqH,
                        float* __restrict__ counts, float* __restrict__ loss,
                        float* __restrict__ out_idx)
{
    int b = blockIdx.x * 256 + threadIdx.x;
    int k = idx[b];
    const float4* e  = (const float4*)(emb + (size_t)k * DLAT);
    const float4* zz = (const float4*)(z   + (size_t)b * DLAT);
    uint32_t*     zo = zqH + (size_t)b * 32;
    float s = 0.0f;
    #pragma unroll
    for (int q = 0; q < 16; q++){
        float4 ev = e[q], zv = zz[q];
        float dx = ev.x - zv.x, dy = ev.y - zv.y, dz = ev.z - zv.z, dw = ev.w - zv.w;
        s += dx*dx + dy*dy + dz*dz + dw*dw;
        zo[q*2]   = fp16_pack_hi(ev.x, ev.y);
        zo[q*2+1] = fp16_pack_hi(ev.z, ev.w);
    }
    out_idx[b] = (float)k;
    atomicAdd(&counts[k], 1.0f);

    __shared__ float red[256];
    red[threadIdx.x] = s;
    __syncthreads();
    for (int off = 128; off > 0; off >>= 1){
        if (threadIdx.x < off) red[threadIdx.x] += red[threadIdx.x + off];
        __syncthreads();
    }
    if (threadIdx.x == 0) atomicAdd(loss, red[0]);
}

// ---------------- perplexity + vq_loss scalars ----------------
__global__ void finalize_kernel(const float* __restrict__ counts, const float* __restrict__ loss,
                                float* __restrict__ out)
{
    __shared__ float red[256];
    float s = 0.0f;
    for (int k = threadIdx.x; k < KCODES; k += 256){
        float p = counts[k] * (1.0f / (float)BATCH);
        s += p * logf(p + 1e-10f);
    }
    red[threadIdx.x] = s;
    __syncthreads();
    for (int off = 128; off > 0; off >>= 1){
        if (threadIdx.x < off) red[threadIdx.x] += red[threadIdx.x + off];
        __syncthreads();
    }
    if (threadIdx.x == 0){
        out[PERP_OFF] = expf(-red[0]);
        out[LOSS_OFF] = loss[0] * (0.25f / ((float)BATCH * (float)DLAT));
    }
}

// ---------------- zero counts + loss ----------------
__global__ void zero_kernel(float* __restrict__ counts, float* __restrict__ loss){
    int i = blockIdx.x * 256 + threadIdx.x;
    if (i < KCODES) counts[i] = 0.0f;
    if (i == KCODES) loss[0] = 0.0f;
}

// ---------------- concat head weights -> [1024,128], biases -> [128] ----------------
__global__ void concat_head(const float* __restrict__ pW, const float* __restrict__ pb,
                            const float* __restrict__ wW, const float* __restrict__ wb,
                            const float* __restrict__ aW, const float* __restrict__ ab,
                            float* __restrict__ hw, float* __restrict__ hb)
{
    int i = blockIdx.x * 256 + threadIdx.x;
    int total = HIDDEN * 128;
    if (i < total){
        int k = i >> 7, col = i & 127;
        float v = 0.0f;
        if (col < 40)      v = pW[k*40 + col];
        else if (col < 42) v = wW[k*2 + (col-40)];
        else if (col < 44) v = aW[k*2 + (col-42)];
        hw[i] = v;
    }
    if (i < 128){
        float v = 0.0f;
        if (i < 40)      v = pb[i];
        else if (i < 42) v = wb[i-40];
        else if (i < 44) v = ab[i-42];
        hb[i] = v;
    }
}

// ---------------- pack outputs ----------------
__global__ void pack_kernel(const float* __restrict__ ho, float* __restrict__ out){
    int gid = blockIdx.x * 256 + threadIdx.x;
    int b = gid / 92, e = gid % 92;
    if (b >= BATCH) return;
    const float* h = ho + (size_t)b * 128;
    if (e < 40){
        out[P_OFF + (size_t)b*40 + e] = h[e];
    } else if (e < 88){
        int e2 = e - 40;
        int c  = e2 & 1;
        int j  = (e2 >> 1) & 3;
        int sg = (e2 >> 3) % 3;
        int p  = e2 / 24;
        out[CP_OFF + (size_t)b*48 + e2] = h[p*20 + (3*sg + j)*2 + c];
    } else if (e < 90){
        int p = e - 88;
        out[W_OFF + (size_t)b*2 + p] = h[40 + p];
    } else {
        int p = e - 90;
        out[A_OFF + (size_t)b*2 + p] = h[42 + p];
    }
}

// ---------------- launch ----------------
extern "C" void kernel_launch(void* const* d_in, const int* in_sizes, int n_in,
                              void* d_out, int out_size)
{
    (void)in_sizes; (void)n_in; (void)out_size;
    const float* x   = (const float*)d_in[0];
    const float* W1  = (const float*)d_in[1];
    const float* b1  = (const float*)d_in[2];
    const float* W2  = (const float*)d_in[3];
    const float* b2  = (const float*)d_in[4];
    const float* W3  = (const float*)d_in[5];
    const float* b3  = (const float*)d_in[6];
    const float* emb = (const float*)d_in[7];
    const float* dW1 = (const float*)d_in[8];
    const float* db1 = (const float*)d_in[9];
    const float* dW2 = (const float*)d_in[10];
    const float* db2 = (const float*)d_in[11];
    const float* pW  = (const float*)d_in[12];
    const float* pb  = (const float*)d_in[13];
    const float* wW  = (const float*)d_in[14];
    const float* wb  = (const float*)d_in[15];
    const float* aW  = (const float*)d_in[16];
    const float* ab  = (const float*)d_in[17];
    float* out = (float*)d_out;

    float *h2, *z, *ho, *counts, *loss, *enorm, *hw, *hb;
    uint32_t *xH, *xL, *w1H, *w1L, *h1H, *h1L, *w2H, *w2L;
    uint32_t *zHiT, *zLoT, *eHiT, *eLoT;
    uint32_t *zqH, *dW1H, *d1H, *dW2H, *d2H, *hwH;
    int* idx;
    cudaGetSymbolAddress((void**)&h2, g_h2);
    cudaGetSymbolAddress((void**)&z,  g_z);
    cudaGetSymbolAddress((void**)&ho, g_ho);
    cudaGetSymbolAddress((void**)&idx, g_idx);
    cudaGetSymbolAddress((void**)&counts, g_counts);
    cudaGetSymbolAddress((void**)&loss, g_loss);
    cudaGetSymbolAddress((void**)&enorm, g_enorm);
    cudaGetSymbolAddress((void**)&hw, g_hw);
    cudaGetSymbolAddress((void**)&hb, g_hb);
    cudaGetSymbolAddress((void**)&xH, g_xH);
    cudaGetSymbolAddress((void**)&xL, g_xL);
    cudaGetSymbolAddress((void**)&w1H, g_w1H);
    cudaGetSymbolAddress((void**)&w1L, g_w1L);
    cudaGetSymbolAddress((void**)&h1H, g_h1H);
    cudaGetSymbolAddress((void**)&h1L, g_h1L);
    cudaGetSymbolAddress((void**)&w2H, g_w2H);
    cudaGetSymbolAddress((void**)&w2L, g_w2L);
    cudaGetSymbolAddress((void**)&zHiT, g_zHiT);
    cudaGetSymbolAddress((void**)&zLoT, g_zLoT);
    cudaGetSymbolAddress((void**)&eHiT, g_eHiT);
    cudaGetSymbolAddress((void**)&eLoT, g_eLoT);
    cudaGetSymbolAddress((void**)&zqH,  g_zqH);
    cudaGetSymbolAddress((void**)&dW1H, g_dW1H);
    cudaGetSymbolAddress((void**)&d1H,  g_d1H);
    cudaGetSymbolAddress((void**)&dW2H, g_dW2H);
    cudaGetSymbolAddress((void**)&d2H,  g_d2H);
    cudaGetSymbolAddress((void**)&hwH,  g_hwH);

    // init + packs
    zero_kernel<<<(KCODES + 1 + 255)/256, 256>>>(counts, loss);
    concat_head<<<(HIDDEN*128 + 255)/256, 256>>>(pW, pb, wW, wb, aW, ab, hw, hb);
    enorm_kernel<<<(KCODES + 255)/256, 256>>>(emb, enorm);
    pack_rowsA<<<(BATCH*392 + 255)/256, 256>>>(x, xH, xL, BATCH*392);
    pack_W<<<(392*256 + 255)/256, 256>>>(W1, w1H, w1L, 392, 256);
    pack_W<<<(128*256 + 255)/256, 256>>>(W2, w2H, w2L, 128, 256);
    pack_embT<<<(32*KCODES + 255)/256, 256>>>(emb, eHiT, eLoT);
    pack_Wh<<<(32*HIDDEN + 255)/256, 256>>>(dW1, dW1H, 32, HIDDEN);
    pack_Wh<<<(512*HIDDEN + 255)/256, 256>>>(dW2, dW2H, 512, HIDDEN);
    pack_Wh<<<(512*128 + 255)/256, 256>>>(hw, hwH, 512, 128);

    // encoder (fp16-split 3-product)
    mma_gemm_f16<ACT_LEAKY, 1><<<dim3(2, BATCH/128), 256>>>(
        xH, xL, w1H, w1L, b1, nullptr, h1H, h1L, BATCH, 256, 784);
    mma_gemm_f16<ACT_LEAKY, 0><<<dim3(2, BATCH/128), 256>>>(
        h1H, h1L, w2H, w2L, b2, h2, nullptr, nullptr, BATCH, 256, 256);
    sgemm_smallN<ACT_NONE><<<BATCH/64, 256>>>(h2, W3, b3, z, BATCH, DLAT, 256);

    // VQ
    pack_zT<<<(32*BATCH + 255)/256, 256>>>(z, zHiT, zLoT);
    vq_argmin_f16<<<BATCH/128, 256>>>(zHiT, zLoT, eHiT, eLoT, enorm, idx);
    vq_post<<<BATCH/256, 256>>>(z, emb, idx, zqH, counts, loss, out + IDX_OFF);
    finalize_kernel<<<1, 256>>>(counts, loss, out);

    // decoder (fp16 hi-only 1-product)
    mma_gemm_h16<ACT_SELU, 1><<<dim3(HIDDEN/128, BATCH/128), 256>>>(
        zqH, dW1H, db1, nullptr, d1H, BATCH, HIDDEN, DLAT);
    mma_gemm_h16<ACT_SELU, 1><<<dim3(HIDDEN/128, BATCH/128), 256>>>(
        d1H, dW2H, db2, nullptr, d2H, BATCH, HIDDEN, HIDDEN);

    // head (fp16 hi-only, N padded to 128)
    mma_gemm_h16<ACT_HEAD, 0><<<dim3(1, BATCH/128), 256>>>(
        d2H, hwH, hb, ho, nullptr, BATCH, 128, HIDDEN);

    // pack outputs
    pack_kernel<<<(BATCH*92 + 255)/256, 256>>>(ho, out);
}

// round 13
// speedup vs baseline: 2.2801x; 1.0218x over previous
#include <cuda_runtime.h>
#include <cuda_fp16.h>
#include <math.h>
#include <stdint.h>

// ---------------- problem constants ----------------
#define BATCH   32768
#define KCODES  4096
#define DLAT    64
#define HIDDEN  1024

// output layout (f32, reference return order, flattened+concat)
#define P_OFF    0
#define P_SIZE   (BATCH*40)
#define CP_OFF   (P_OFF + P_SIZE)
#define CP_SIZE  (BATCH*48)
#define W_OFF    (CP_OFF + CP_SIZE)
#define WA_SIZE  (BATCH*2)
#define A_OFF    (W_OFF + WA_SIZE)
#define LOSS_OFF (A_OFF + WA_SIZE)
#define IDX_OFF  (LOSS_OFF + 1)
#define PERP_OFF (IDX_OFF + BATCH)

#define HS 136           // VQ smem word stride (conflict-free)
#define AKP 12           // A smem word stride (8 used + 4 pad)
#define BNP 136          // B smem word stride

// ---------------- scratch (__device__ globals; no allocation allowed) ----------------
__device__ float  g_z  [BATCH*DLAT];
__device__ float  g_ho [BATCH*128];       // head out, stride 128 (padded)
__device__ int    g_idx[BATCH];
__device__ float  g_counts[KCODES];
__device__ float  g_loss;
__device__ float  g_enorm[KCODES];
__device__ float  g_hw [HIDDEN*128];      // padded head weights [1024,128]
__device__ float  g_hb [128];
__device__ float  g_b3p[128];             // padded b3
// fp16-split packed operands (encoder + VQ)
__device__ uint32_t g_xH [BATCH*392];
__device__ uint32_t g_xL [BATCH*392];
__device__ uint32_t g_w1H[392*256];
__device__ uint32_t g_w1L[392*256];
__device__ uint32_t g_h1H[BATCH*128];
__device__ uint32_t g_h1L[BATCH*128];
__device__ uint32_t g_w2H[128*256];
__device__ uint32_t g_w2L[128*256];
__device__ uint32_t g_h2H[BATCH*128];
__device__ uint32_t g_h2L[BATCH*128];
__device__ uint32_t g_w3H[128*128];       // W3 padded [kp=128][n=128]
__device__ uint32_t g_w3L[128*128];
__device__ uint32_t g_zHiT[32*BATCH];
__device__ uint32_t g_zLoT[32*BATCH];
__device__ uint32_t g_eHiT[32*KCODES];
__device__ uint32_t g_eLoT[32*KCODES];
// fp16 hi-only packed (decoder)
__device__ uint32_t g_zqH [BATCH*32];
__device__ uint32_t g_dW1H[32*HIDDEN];
__device__ uint32_t g_d1H [BATCH*512];
__device__ uint32_t g_dW2H[512*HIDDEN];
__device__ uint32_t g_d2H [BATCH*512];
__device__ uint32_t g_hwH [512*128];

// ---------------- activations ----------------
#define ACT_NONE 0
#define ACT_LEAKY 1
#define ACT_SELU 2
#define ACT_HEAD 3

__device__ __forceinline__ float sigmoidf_(float x){ return 1.0f/(1.0f+expf(-x)); }

template<int ACT>
__device__ __forceinline__ float apply_act(float v, int col){
    if (ACT == ACT_LEAKY) return v > 0.0f ? v : 0.2f*v;
    if (ACT == ACT_SELU){
        const float a = 1.6732632423543772f, s = 1.0507009873554805f;
        return v > 0.0f ? s*v : s*a*(expf(v)-1.0f);
    }
    if (ACT == ACT_HEAD){
        if (col < 40) return tanhf(v)*12.0f + 14.0f;
        if (col < 42) return sigmoidf_(v)*2.0f + 1.0f;
        return sigmoidf_(v);
    }
    return v;
}

// ---------------- fp16 pack helpers ----------------
__device__ __forceinline__ void fp16_split_pack(float x0, float x1,
                                                uint32_t& hi, uint32_t& lo){
    __half h0 = __float2half_rn(x0), h1 = __float2half_rn(x1);
    __half l0 = __float2half_rn(x0 - __half2float(h0));
    __half l1 = __float2half_rn(x1 - __half2float(h1));
    __half2 hh = __halves2half2(h0, h1);
    __half2 ll = __halves2half2(l0, l1);
    hi = *(uint32_t*)&hh;
    lo = *(uint32_t*)&ll;
}
__device__ __forceinline__ uint32_t fp16_pack_hi(float x0, float x1){
    __half2 hh = __halves2half2(__float2half_rn(x0), __float2half_rn(x1));
    return *(uint32_t*)&hh;
}

// D += A*B, m16n8k16 fp16 (fp32 accum)
__device__ __forceinline__ void mma16(float* c, const uint32_t* a, const uint32_t* b){
    asm volatile(
        "mma.sync.aligned.m16n8k16.row.col.f32.f16.f16.f32 "
        "{%0,%1,%2,%3}, {%4,%5,%6,%7}, {%8,%9}, {%0,%1,%2,%3};\n"
        : "+f"(c[0]), "+f"(c[1]), "+f"(c[2]), "+f"(c[3])
        : "r"(a[0]), "r"(a[1]), "r"(a[2]), "r"(a[3]), "r"(b[0]), "r"(b[1]));
}

// ---------------- cp.async helpers ----------------
__device__ __forceinline__ void cpasync16(void* dst_smem, const void* src){
    uint32_t s = (uint32_t)__cvta_generic_to_shared(dst_smem);
    asm volatile("cp.async.cg.shared.global [%0], [%1], 16;\n" :: "r"(s), "l"(src));
}
__device__ __forceinline__ void cpasync_commit(){ asm volatile("cp.async.commit_group;\n"); }
template<int NN>
__device__ __forceinline__ void cpasync_wait(){ asm volatile("cp.async.wait_group %0;\n" :: "n"(NN)); }

// ---------------- pack kernels ----------------
__global__ void pack_rowsA(const float* __restrict__ src,
                           uint32_t* __restrict__ hiA, uint32_t* __restrict__ loA,
                           int nwords){
    int i = blockIdx.x * 256 + threadIdx.x;
    if (i >= nwords) return;
    float2 v = ((const float2*)src)[i];
    uint32_t hi, lo;
    fp16_split_pack(v.x, v.y, hi, lo);
    hiA[i] = hi; loA[i] = lo;
}

__global__ void pack_W(const float* __restrict__ W,
                       uint32_t* __restrict__ hiW, uint32_t* __restrict__ loW,
                       int KP, int N){
    int i = blockIdx.x * 256 + threadIdx.x;
    if (i >= KP*N) return;
    int kp = i / N, n = i % N;
    float x0 = W[(size_t)(2*kp)*N + n];
    float x1 = W[(size_t)(2*kp+1)*N + n];
    uint32_t hi, lo;
    fp16_split_pack(x0, x1, hi, lo);
    hiW[i] = hi; loW[i] = lo;
}

// W3 [256][64] -> padded packed [128][128]; b3 -> padded [128]
__global__ void pack_W3(const float* __restrict__ W3, const float* __restrict__ b3,
                        uint32_t* __restrict__ hiW, uint32_t* __restrict__ loW,
                        float* __restrict__ b3p){
    int i = blockIdx.x * 256 + threadIdx.x;
    if (i >= 128*128) return;
    int kp = i >> 7, n = i & 127;
    float x0 = 0.0f, x1 = 0.0f;
    if (n < 64){
        x0 = W3[(size_t)(2*kp)*64 + n];
        x1 = W3[(size_t)(2*kp+1)*64 + n];
    }
    uint32_t hi, lo;
    fp16_split_pack(x0, x1, hi, lo);
    hiW[i] = hi; loW[i] = lo;
    if (i < 128) b3p[i] = (i < 64) ? b3[i] : 0.0f;
}

// hi-only W pack (decoder path)
__global__ void pack_Wh(const float* __restrict__ W,
                        uint32_t* __restrict__ hiW, int KP, int N){
    int i = blockIdx.x * 256 + threadIdx.x;
    if (i >= KP*N) return;
    int kp = i / N, n = i % N;
    hiW[i] = fp16_pack_hi(W[(size_t)(2*kp)*N + n], W[(size_t)(2*kp+1)*N + n]);
}

__global__ void pack_embT(const float* __restrict__ emb,
                          uint32_t* __restrict__ eHiT, uint32_t* __restrict__ eLoT){
    int i = blockIdx.x * 256 + threadIdx.x;
    if (i >= 32*KCODES) return;
    int dp = i >> 12, c = i & (KCODES-1);
    float x0 = emb[(size_t)c*DLAT + 2*dp];
    float x1 = emb[(size_t)c*DLAT + 2*dp + 1];
    uint32_t hi, lo;
    fp16_split_pack(x0, x1, hi, lo);
    eHiT[i] = hi; eLoT[i] = lo;
}

// ============================================================================
// fp16-split GEMM: 3-product hi/lo. A [m][kp], B [kp][n].
// OUTPACK: 0 = fp32 C; 1 = packed hi/lo C (chaining);
//          2 = fp32 z (cols<64) + transposed hi/lo packs zHiT/zLoT [dp][b]
// ============================================================================
template<int ACT, int OUTPACK>
__global__ void __launch_bounds__(256, 2) mma_gemm_f16(
    const uint32_t* __restrict__ AH, const uint32_t* __restrict__ AL,
    const uint32_t* __restrict__ BH, const uint32_t* __restrict__ BL,
    const float* __restrict__ bias, float* __restrict__ C,
    uint32_t* __restrict__ CH, uint32_t* __restrict__ CL,
    int M, int N, int K)
{
    __shared__ uint32_t AsH[2][128][AKP], AsL[2][128][AKP];
    __shared__ uint32_t BsH[2][8][BNP],   BsL[2][8][BNP];

    const int tid  = threadIdx.x;
    const int lane = tid & 31, warp = tid >> 5;
    const int wm = (warp & 1) * 64, wn = (warp >> 1) * 32;
    const int bm = blockIdx.y * 128, bn = blockIdx.x * 128;
    const int g = lane >> 2, tg = lane & 3;
    const int KP = K >> 1;

    float acc[4][4][4];
    #pragma unroll
    for (int i = 0; i < 4; i++)
        #pragma unroll
        for (int j = 0; j < 4; j++)
            #pragma unroll
            for (int q = 0; q < 4; q++) acc[i][j][q] = 0.0f;

    const int ar = tid >> 1, ac = (tid & 1) * 4;
    const int br = tid >> 5, bc = lane * 4;
    const uint32_t* AHp = AH + (size_t)(bm + ar) * KP + ac;
    const uint32_t* ALp = AL + (size_t)(bm + ar) * KP + ac;
    const uint32_t* BHp = BH + (size_t)br * N + bn + bc;
    const uint32_t* BLp = BL + (size_t)br * N + bn + bc;

    const int ntiles = K >> 4;

    #define COPY_F16(kt, buf) do { \
        cpasync16(&AsH[buf][ar][ac], AHp + (size_t)(kt)*8); \
        cpasync16(&AsL[buf][ar][ac], ALp + (size_t)(kt)*8); \
        cpasync16(&BsH[buf][br][bc], BHp + (size_t)(kt)*8*N); \
        cpasync16(&BsL[buf][br][bc], BLp + (size_t)(kt)*8*N); \
        cpasync_commit(); \
    } while (0)

    COPY_F16(0, 0);

    for (int i = 0; i < ntiles; i++){
        int buf = i & 1;
        if (i + 1 < ntiles){
            COPY_F16(i + 1, buf ^ 1);
            cpasync_wait<1>();
        } else {
            cpasync_wait<0>();
        }
        __syncthreads();

        uint32_t ah[4][4], al[4][4];
        #pragma unroll
        for (int mt = 0; mt < 4; mt++){
            int m = wm + mt*16 + g;
            ah[mt][0] = AsH[buf][m  ][tg];
            ah[mt][1] = AsH[buf][m+8][tg];
            ah[mt][2] = AsH[buf][m  ][tg+4];
            ah[mt][3] = AsH[buf][m+8][tg+4];
            al[mt][0] = AsL[buf][m  ][tg];
            al[mt][1] = AsL[buf][m+8][tg];
            al[mt][2] = AsL[buf][m  ][tg+4];
            al[mt][3] = AsL[buf][m+8][tg+4];
        }
        #pragma unroll
        for (int nt = 0; nt < 4; nt++){
            int n = wn + nt*8 + g;
            uint32_t bh[2] = { BsH[buf][tg][n], BsH[buf][tg+4][n] };
            uint32_t bl[2] = { BsL[buf][tg][n], BsL[buf][tg+4][n] };
            #pragma unroll
            for (int mt = 0; mt < 4; mt++) mma16(acc[mt][nt], ah[mt], bh);
            #pragma unroll
            for (int mt = 0; mt < 4; mt++) mma16(acc[mt][nt], al[mt], bh);
            #pragma unroll
            for (int mt = 0; mt < 4; mt++) mma16(acc[mt][nt], ah[mt], bl);
        }
        __syncthreads();
    }
    #undef COPY_F16

    #pragma unroll
    for (int mt = 0; mt < 4; mt++){
        #pragma unroll
        for (int nt = 0; nt < 4; nt++){
            int row = bm + wm + mt*16 + g;
            int col = bn + wn + nt*8 + 2*tg;
            float bs0 = bias[col], bs1 = bias[col+1];
            float v00 = apply_act<ACT>(acc[mt][nt][0] + bs0, col);
            float v01 = apply_act<ACT>(acc[mt][nt][1] + bs1, col+1);
            float v10 = apply_act<ACT>(acc[mt][nt][2] + bs0, col);
            float v11 = apply_act<ACT>(acc[mt][nt][3] + bs1, col+1);
            if (OUTPACK == 1){
                int w = col >> 1;
                int NP = N >> 1;
                uint32_t h0, l0, h1, l1;
                fp16_split_pack(v00, v01, h0, l0);
                fp16_split_pack(v10, v11, h1, l1);
                CH[(size_t)row*NP + w]     = h0;
                CL[(size_t)row*NP + w]     = l0;
                CH[(size_t)(row+8)*NP + w] = h1;
                CL[(size_t)(row+8)*NP + w] = l1;
            } else if (OUTPACK == 2){
                if (col < DLAT){
                    *(float2*)&C[(size_t)row*DLAT + col]     = make_float2(v00, v01);
                    *(float2*)&C[(size_t)(row+8)*DLAT + col] = make_float2(v10, v11);
                    int dp = col >> 1;
                    uint32_t h0, l0, h1, l1;
                    fp16_split_pack(v00, v01, h0, l0);
                    fp16_split_pack(v10, v11, h1, l1);
                    CH[(size_t)dp*BATCH + row]     = h0;
                    CL[(size_t)dp*BATCH + row]     = l0;
                    CH[(size_t)dp*BATCH + row + 8] = h1;
                    CL[(size_t)dp*BATCH + row + 8] = l1;
                }
            } else {
                *(float2*)&C[(size_t)row*N + col]     = make_float2(v00, v01);
                *(float2*)&C[(size_t)(row+8)*N + col] = make_float2(v10, v11);
            }
        }
    }
}

// ============================================================================
// fp16 hi-only GEMM (decoder + head): 1-product.
// ============================================================================
template<int ACT, int OUTPACK>
__global__ void __launch_bounds__(256, 2) mma_gemm_h16(
    const uint32_t* __restrict__ AH, const uint32_t* __restrict__ BH,
    const float* __restrict__ bias, float* __restrict__ C,
    uint32_t* __restrict__ CH,
    int M, int N, int K)
{
    __shared__ uint32_t AsH[2][128][AKP];
    __shared__ uint32_t BsH[2][8][BNP];

    const int tid  = threadIdx.x;
    const int lane = tid & 31, warp = tid >> 5;
    const int wm = (warp & 1) * 64, wn = (warp >> 1) * 32;
    const int bm = blockIdx.y * 128, bn = blockIdx.x * 128;
    const int g = lane >> 2, tg = lane & 3;
    const int KP = K >> 1;

    float acc[4][4][4];
    #pragma unroll
    for (int i = 0; i < 4; i++)
        #pragma unroll
        for (int j = 0; j < 4; j++)
            #pragma unroll
            for (int q = 0; q < 4; q++) acc[i][j][q] = 0.0f;

    const int ar = tid >> 1, ac = (tid & 1) * 4;
    const int br = tid >> 5, bc = lane * 4;
    const uint32_t* AHp = AH + (size_t)(bm + ar) * KP + ac;
    const uint32_t* BHp = BH + (size_t)br * N + bn + bc;

    const int ntiles = K >> 4;

    #define COPY_H16(kt, buf) do { \
        cpasync16(&AsH[buf][ar][ac], AHp + (size_t)(kt)*8); \
        cpasync16(&BsH[buf][br][bc], BHp + (size_t)(kt)*8*N); \
        cpasync_commit(); \
    } while (0)

    COPY_H16(0, 0);

    for (int i = 0; i < ntiles; i++){
        int buf = i & 1;
        if (i + 1 < ntiles){
            COPY_H16(i + 1, buf ^ 1);
            cpasync_wait<1>();
        } else {
            cpasync_wait<0>();
        }
        __syncthreads();

        uint32_t ah[4][4];
        #pragma unroll
        for (int mt = 0; mt < 4; mt++){
            int m = wm + mt*16 + g;
            ah[mt][0] = AsH[buf][m  ][tg];
            ah[mt][1] = AsH[buf][m+8][tg];
            ah[mt][2] = AsH[buf][m  ][tg+4];
            ah[mt][3] = AsH[buf][m+8][tg+4];
        }
        #pragma unroll
        for (int nt = 0; nt < 4; nt++){
            int n = wn + nt*8 + g;
            uint32_t bh[2] = { BsH[buf][tg][n], BsH[buf][tg+4][n] };
            #pragma unroll
            for (int mt = 0; mt < 4; mt++) mma16(acc[mt][nt], ah[mt], bh);
        }
        __syncthreads();
    }
    #undef COPY_H16

    #pragma unroll
    for (int mt = 0; mt < 4; mt++){
        #pragma unroll
        for (int nt = 0; nt < 4; nt++){
            int row = bm + wm + mt*16 + g;
            int col = bn + wn + nt*8 + 2*tg;
            float bs0 = bias[col], bs1 = bias[col+1];
            float v00 = apply_act<ACT>(acc[mt][nt][0] + bs0, col);
            float v01 = apply_act<ACT>(acc[mt][nt][1] + bs1, col+1);
            float v10 = apply_act<ACT>(acc[mt][nt][2] + bs0, col);
            float v11 = apply_act<ACT>(acc[mt][nt][3] + bs1, col+1);
            if (OUTPACK){
                int w = col >> 1;
                int NP = N >> 1;
                CH[(size_t)row*NP + w]     = fp16_pack_hi(v00, v01);
                CH[(size_t)(row+8)*NP + w] = fp16_pack_hi(v10, v11);
            } else {
                *(float2*)&C[(size_t)row*N + col]     = make_float2(v00, v01);
                *(float2*)&C[(size_t)(row+8)*N + col] = make_float2(v10, v11);
            }
        }
    }
}

// ---------------- codebook norms ----------------
__global__ void enorm_kernel(const float* __restrict__ emb, float* __restrict__ enorm){
    int k = blockIdx.x * 256 + threadIdx.x;
    if (k >= KCODES) return;
    const float4* e = (const float4*)(emb + (size_t)k * DLAT);
    float s = 0.0f;
    #pragma unroll
    for (int q = 0; q < 16; q++){
        float4 v = e[q];
        s += v.x*v.x + v.y*v.y + v.z*v.z + v.w*v.w;
    }
    enorm[k] = s;
}

// ---------------- VQ argmin: fp16-split m16n8k16, pre-packed operands ----------------
__global__ void __launch_bounds__(256, 2) vq_argmin_f16(
    const uint32_t* __restrict__ zHiT, const uint32_t* __restrict__ zLoT,
    const uint32_t* __restrict__ eHiT, const uint32_t* __restrict__ eLoT,
    const float* __restrict__ enorm, int* __restrict__ idx_out)
{
    __shared__ uint32_t ZH[32][HS], ZL[32][HS];
    __shared__ uint32_t EH[2][32][HS], EL[2][32][HS];

    const int tid  = threadIdx.x;
    const int lane = tid & 31, warp = tid >> 5;
    const int wm = (warp & 1) * 64, wn = (warp >> 1) * 32;
    const int bm = blockIdx.x * 128;
    const int g = lane >> 2, tg = lane & 3;

    {
        #pragma unroll
        for (int j = 0; j < 4; j++){
            int unit = j*256 + tid;
            int dp = unit >> 5, u = unit & 31;
            cpasync16(&ZH[dp][u*4], zHiT + (size_t)dp*BATCH + bm + u*4);
            cpasync16(&ZL[dp][u*4], zLoT + (size_t)dp*BATCH + bm + u*4);
        }
        cpasync_commit();
    }

    #define COPY_EP(c0_, buf_) do { \
        _Pragma("unroll") \
        for (int j = 0; j < 4; j++){ \
            int unit = j*256 + tid; \
            int dp_ = unit >> 5, u_ = unit & 31; \
            cpasync16(&EH[buf_][dp_][u_*4], eHiT + (size_t)dp_*KCODES + (c0_) + u_*4); \
            cpasync16(&EL[buf_][dp_][u_*4], eLoT + (size_t)dp_*KCODES + (c0_) + u_*4); \
        } \
        cpasync_commit(); \
    } while (0)

    float mv[8]; int mi[8];
    #pragma unroll
    for (int s = 0; s < 8; s++){ mv[s] = INFINITY; mi[s] = 0; }

    COPY_EP(0, 0);

    for (int ch = 0; ch < KCODES/128; ch++){
        int c0 = ch * 128;
        int buf = ch & 1;
        if (ch + 1 < KCODES/128){
            COPY_EP(c0 + 128, buf ^ 1);
            cpasync_wait<1>();
        } else {
            cpasync_wait<0>();
        }
        __syncthreads();

        float acc[4][4][4];
        #pragma unroll
        for (int i = 0; i < 4; i++)
            #pragma unroll
            for (int j = 0; j < 4; j++)
                #pragma unroll
                for (int q = 0; q < 4; q++) acc[i][j][q] = 0.0f;

        #pragma unroll
        for (int kb = 0; kb < 4; kb++){
            uint32_t ah[4][4], al[4][4];
            #pragma unroll
            for (int mt = 0; mt < 4; mt++){
                int m = wm + mt*16 + g;
                ah[mt][0] = ZH[kb*8+tg  ][m];
                ah[mt][1] = ZH[kb*8+tg  ][m+8];
                ah[mt][2] = ZH[kb*8+tg+4][m];
                ah[mt][3] = ZH[kb*8+tg+4][m+8];
                al[mt][0] = ZL[kb*8+tg  ][m];
                al[mt][1] = ZL[kb*8+tg  ][m+8];
                al[mt][2] = ZL[kb*8+tg+4][m];
                al[mt][3] = ZL[kb*8+tg+4][m+8];
            }
            #pragma unroll
            for (int nt = 0; nt < 4; nt++){
                int n = wn + nt*8 + g;
                uint32_t bh[2] = { EH[buf][kb*8+tg][n], EH[buf][kb*8+tg+4][n] };
                uint32_t bl[2] = { EL[buf][kb*8+tg][n], EL[buf][kb*8+tg+4][n] };
                #pragma unroll
                for (int mt = 0; mt < 4; mt++) mma16(acc[mt][nt], ah[mt], bh);
                #pragma unroll
                for (int mt = 0; mt < 4; mt++) mma16(acc[mt][nt], al[mt], bh);
                #pragma unroll
                for (int mt = 0; mt < 4; mt++) mma16(acc[mt][nt], ah[mt], bl);
            }
        }

        #pragma unroll
        for (int nt = 0; nt < 4; nt++){
            int nc = wn + nt*8 + 2*tg;
            float e0 = __ldg(enorm + c0 + nc);
            float e1 = __ldg(enorm + c0 + nc + 1);
            int code = c0 + nc;
            #pragma unroll
            for (int mt = 0; mt < 4; mt++){
                float d00 = e0 - 2.0f*acc[mt][nt][0];
                float d01 = e1 - 2.0f*acc[mt][nt][1];
                float d10 = e0 - 2.0f*acc[mt][nt][2];
                float d11 = e1 - 2.0f*acc[mt][nt][3];
                int s0 = mt*2, s1 = mt*2 + 1;
                if (d00 < mv[s0]){ mv[s0] = d00; mi[s0] = code;   }
                if (d01 < mv[s0]){ mv[s0] = d01; mi[s0] = code+1; }
                if (d10 < mv[s1]){ mv[s1] = d10; mi[s1] = code;   }
                if (d11 < mv[s1]){ mv[s1] = d11; mi[s1] = code+1; }
            }
        }
        __syncthreads();
    }
    #undef COPY_EP

    float* rv = (float*)&EH[0][0][0];
    int*   ri = ((int*)rv) + 16*128;
    int cand = (warp >> 1) * 4 + tg;
    #pragma unroll
    for (int s = 0; s < 8; s++){
        int r = wm + (s >> 1)*16 + g + (s & 1)*8;
        rv[cand*128 + r] = mv[s];
        ri[cand*128 + r] = mi[s];
    }
    __syncthreads();
    if (tid < 128){
        float bv = INFINITY; int bi = 0x7fffffff;
        #pragma unroll
        for (int t = 0; t < 16; t++){
            float v = rv[t*128 + tid];
            int c = ri[t*128 + tid];
            if (v < bv || (v == bv && c < bi)){ bv = v; bi = c; }
        }
        idx_out[bm + tid] = bi;
    }
}

// ---------------- gather: packed fp16 zq, idx-as-float, counts, commit-loss ----------------
__global__ void vq_post(const float* __restrict__ z, const float* __restrict__ emb,
                        const int* __restrict__ idx, uint32_t* __restrict__ zqH,
                        float* __restrict__ counts, float* __restrict__ loss,
                        float* __restrict__ out_idx)
{
    int b = blockIdx.x * 256 + threadIdx.x;
    int k = idx[b];
    const float4* e  = (const float4*)(emb + (size_t)k * DLAT);
    const float4* zz = (const float4*)(z   + (size_t)b * DLAT);
    uint32_t*     zo = zqH + (size_t)b * 32;
    float s = 0.0f;
    #pragma unroll
    for (int q = 0; q < 16; q++){
        float4 ev = e[q], zv = zz[q];
        float dx = ev.x - zv.x, dy = ev.y - zv.y, dz = ev.z - zv.z, dw = ev.w - zv.w;
        s += dx*dx + dy*dy + dz*dz + dw*dw;
        zo[q*2]   = fp16_pack_hi(ev.x, ev.y);
        zo[q*2+1] = fp16_pack_hi(ev.z, ev.w);
    }
    out_idx[b] = (float)k;
    atomicAdd(&counts[k], 1.0f);

    __shared__ float red[256];
    red[threadIdx.x] = s;
    __syncthreads();
    for (int off = 128; off > 0; off >>= 1){
        if (threadIdx.x < off) red[threadIdx.x] += red[threadIdx.x + off];
        __syncthreads();
    }
    if (threadIdx.x == 0) atomicAdd(loss, red[0]);
}

// ---------------- perplexity + vq_loss scalars ----------------
__global__ void finalize_kernel(const float* __restrict__ counts, const float* __restrict__ loss,
                                float* __restrict__ out)
{
    __shared__ float red[256];
    float s = 0.0f;
    for (int k = threadIdx.x; k < KCODES; k += 256){
        float p = counts[k] * (1.0f / (float)BATCH);
        s += p * logf(p + 1e-10f);
    }
    red[threadIdx.x] = s;
    __syncthreads();
    for (int off = 128; off > 0; off >>= 1){
        if (threadIdx.x < off) red[threadIdx.x] += red[threadIdx.x + off];
        __syncthreads();
    }
    if (threadIdx.x == 0){
        out[PERP_OFF] = expf(-red[0]);
        out[LOSS_OFF] = loss[0] * (0.25f / ((float)BATCH * (float)DLAT));
    }
}

// ---------------- zero counts + loss ----------------
__global__ void zero_kernel(float* __restrict__ counts, float* __restrict__ loss){
    int i = blockIdx.x * 256 + threadIdx.x;
    if (i < KCODES) counts[i] = 0.0f;
    if (i == KCODES) loss[0] = 0.0f;
}

// ---------------- concat head weights -> [1024,128], biases -> [128] ----------------
__global__ void concat_head(const float* __restrict__ pW, const float* __restrict__ pb,
                            const float* __restrict__ wW, const float* __restrict__ wb,
                            const float* __restrict__ aW, const float* __restrict__ ab,
                            float* __restrict__ hw, float* __restrict__ hb)
{
    int i = blockIdx.x * 256 + threadIdx.x;
    int total = HIDDEN * 128;
    if (i < total){
        int k = i >> 7, col = i & 127;
        float v = 0.0f;
        if (col < 40)      v = pW[k*40 + col];
        else if (col < 42) v = wW[k*2 + (col-40)];
        else if (col < 44) v = aW[k*2 + (col-42)];
        hw[i] = v;
    }
    if (i < 128){
        float v = 0.0f;
        if (i < 40)      v = pb[i];
        else if (i < 42) v = wb[i-40];
        else if (i < 44) v = ab[i-42];
        hb[i] = v;
    }
}

// ---------------- pack outputs ----------------
__global__ void pack_kernel(const float* __restrict__ ho, float* __restrict__ out){
    int gid = blockIdx.x * 256 + threadIdx.x;
    int b = gid / 92, e = gid % 92;
    if (b >= BATCH) return;
    const float* h = ho + (size_t)b * 128;
    if (e < 40){
        out[P_OFF + (size_t)b*40 + e] = h[e];
    } else if (e < 88){
        int e2 = e - 40;
        int c  = e2 & 1;
        int j  = (e2 >> 1) & 3;
        int sg = (e2 >> 3) % 3;
        int p  = e2 / 24;
        out[CP_OFF + (size_t)b*48 + e2] = h[p*20 + (3*sg + j)*2 + c];
    } else if (e < 90){
        int p = e - 88;
        out[W_OFF + (size_t)b*2 + p] = h[40 + p];
    } else {
        int p = e - 90;
        out[A_OFF + (size_t)b*2 + p] = h[42 + p];
    }
}

// ---------------- launch ----------------
extern "C" void kernel_launch(void* const* d_in, const int* in_sizes, int n_in,
                              void* d_out, int out_size)
{
    (void)in_sizes; (void)n_in; (void)out_size;
    const float* x   = (const float*)d_in[0];
    const float* W1  = (const float*)d_in[1];
    const float* b1  = (const float*)d_in[2];
    const float* W2  = (const float*)d_in[3];
    const float* b2  = (const float*)d_in[4];
    const float* W3  = (const float*)d_in[5];
    const float* b3  = (const float*)d_in[6];
    const float* emb = (const float*)d_in[7];
    const float* dW1 = (const float*)d_in[8];
    const float* db1 = (const float*)d_in[9];
    const float* dW2 = (const float*)d_in[10];
    const float* db2 = (const float*)d_in[11];
    const float* pW  = (const float*)d_in[12];
    const float* pb  = (const float*)d_in[13];
    const float* wW  = (const float*)d_in[14];
    const float* wb  = (const float*)d_in[15];
    const float* aW  = (const float*)d_in[16];
    const float* ab  = (const float*)d_in[17];
    float* out = (float*)d_out;

    float *z, *ho, *counts, *loss, *enorm, *hw, *hb, *b3p;
    uint32_t *xH, *xL, *w1H, *w1L, *h1H, *h1L, *w2H, *w2L, *h2H, *h2L, *w3H, *w3L;
    uint32_t *zHiT, *zLoT, *eHiT, *eLoT;
    uint32_t *zqH, *dW1H, *d1H, *dW2H, *d2H, *hwH;
    int* idx;
    cudaGetSymbolAddress((void**)&z,  g_z);
    cudaGetSymbolAddress((void**)&ho, g_ho);
    cudaGetSymbolAddress((void**)&idx, g_idx);
    cudaGetSymbolAddress((void**)&counts, g_counts);
    cudaGetSymbolAddress((void**)&loss, g_loss);
    cudaGetSymbolAddress((void**)&enorm, g_enorm);
    cudaGetSymbolAddress((void**)&hw, g_hw);
    cudaGetSymbolAddress((void**)&hb, g_hb);
    cudaGetSymbolAddress((void**)&b3p, g_b3p);
    cudaGetSymbolAddress((void**)&xH, g_xH);
    cudaGetSymbolAddress((void**)&xL, g_xL);
    cudaGetSymbolAddress((void**)&w1H, g_w1H);
    cudaGetSymbolAddress((void**)&w1L, g_w1L);
    cudaGetSymbolAddress((void**)&h1H, g_h1H);
    cudaGetSymbolAddress((void**)&h1L, g_h1L);
    cudaGetSymbolAddress((void**)&w2H, g_w2H);
    cudaGetSymbolAddress((void**)&w2L, g_w2L);
    cudaGetSymbolAddress((void**)&h2H, g_h2H);
    cudaGetSymbolAddress((void**)&h2L, g_h2L);
    cudaGetSymbolAddress((void**)&w3H, g_w3H);
    cudaGetSymbolAddress((void**)&w3L, g_w3L);
    cudaGetSymbolAddress((void**)&zHiT, g_zHiT);
    cudaGetSymbolAddress((void**)&zLoT, g_zLoT);
    cudaGetSymbolAddress((void**)&eHiT, g_eHiT);
    cudaGetSymbolAddress((void**)&eLoT, g_eLoT);
    cudaGetSymbolAddress((void**)&zqH,  g_zqH);
    cudaGetSymbolAddress((void**)&dW1H, g_dW1H);
    cudaGetSymbolAddress((void**)&d1H,  g_d1H);
    cudaGetSymbolAddress((void**)&dW2H, g_dW2H);
    cudaGetSymbolAddress((void**)&d2H,  g_d2H);
    cudaGetSymbolAddress((void**)&hwH,  g_hwH);

    // init + packs
    zero_kernel<<<(KCODES + 1 + 255)/256, 256>>>(counts, loss);
    concat_head<<<(HIDDEN*128 + 255)/256, 256>>>(pW, pb, wW, wb, aW, ab, hw, hb);
    enorm_kernel<<<(KCODES + 255)/256, 256>>>(emb, enorm);
    pack_rowsA<<<(BATCH*392 + 255)/256, 256>>>(x, xH, xL, BATCH*392);
    pack_W<<<(392*256 + 255)/256, 256>>>(W1, w1H, w1L, 392, 256);
    pack_W<<<(128*256 + 255)/256, 256>>>(W2, w2H, w2L, 128, 256);
    pack_W3<<<(128*128 + 255)/256, 256>>>(W3, b3, w3H, w3L, b3p);
    pack_embT<<<(32*KCODES + 255)/256, 256>>>(emb, eHiT, eLoT);
    pack_Wh<<<(32*HIDDEN + 255)/256, 256>>>(dW1, dW1H, 32, HIDDEN);
    pack_Wh<<<(512*HIDDEN + 255)/256, 256>>>(dW2, dW2H, 512, HIDDEN);
    pack_Wh<<<(512*128 + 255)/256, 256>>>(hw, hwH, 512, 128);

    // encoder (fp16-split 3-product)
    mma_gemm_f16<ACT_LEAKY, 1><<<dim3(2, BATCH/128), 256>>>(
        xH, xL, w1H, w1L, b1, nullptr, h1H, h1L, BATCH, 256, 784);
    mma_gemm_f16<ACT_LEAKY, 1><<<dim3(2, BATCH/128), 256>>>(
        h1H, h1L, w2H, w2L, b2, nullptr, h2H, h2L, BATCH, 256, 256);
    // z projection: fp16-split MMA, fused fp32 z + transposed hi/lo packs
    mma_gemm_f16<ACT_NONE, 2><<<dim3(1, BATCH/128), 256>>>(
        h2H, h2L, w3H, w3L, b3p, z, zHiT, zLoT, BATCH, 128, 256);

    // VQ
    vq_argmin_f16<<<BATCH/128, 256>>>(zHiT, zLoT, eHiT, eLoT, enorm, idx);
    vq_post<<<BATCH/256, 256>>>(z, emb, idx, zqH, counts, loss, out + IDX_OFF);
    finalize_kernel<<<1, 256>>>(counts, loss, out);

    // decoder (fp16 hi-only 1-product)
    mma_gemm_h16<ACT_SELU, 1><<<dim3(HIDDEN/128, BATCH/128), 256>>>(
        zqH, dW1H, db1, nullptr, d1H, BATCH, HIDDEN, DLAT);
    mma_gemm_h16<ACT_SELU, 1><<<dim3(HIDDEN/128, BATCH/128), 256>>>(
        d1H, dW2H, db2, nullptr, d2H, BATCH, HIDDEN, HIDDEN);

    // head (fp16 hi-only, N padded to 128)
    mma_gemm_h16<ACT_HEAD, 0><<<dim3(1, BATCH/128), 256>>>(
        d2H, hwH, hb, ho, nullptr, BATCH, 128, HIDDEN);

    // pack outputs
    pack_kernel<<<(BATCH*92 + 255)/256, 256>>>(ho, out);
}

// round 14
// speedup vs baseline: 2.3018x; 1.0095x over previous
#include <cuda_runtime.h>
#include <cuda_fp16.h>
#include <math.h>
#include <stdint.h>

// ---------------- problem constants ----------------
#define BATCH   32768
#define KCODES  4096
#define DLAT    64
#define HIDDEN  1024

// output layout (f32, reference return order, flattened+concat)
#define P_OFF    0
#define P_SIZE   (BATCH*40)
#define CP_OFF   (P_OFF + P_SIZE)
#define CP_SIZE  (BATCH*48)
#define W_OFF    (CP_OFF + CP_SIZE)
#define WA_SIZE  (BATCH*2)
#define A_OFF    (W_OFF + WA_SIZE)
#define LOSS_OFF (A_OFF + WA_SIZE)
#define IDX_OFF  (LOSS_OFF + 1)
#define PERP_OFF (IDX_OFF + BATCH)

#define HS 136           // VQ smem word stride (conflict-free)
#define AKP 12           // BK16 A smem word stride (8 used + 4 pad)
#define AKP2 20          // BK32 A smem word stride (16 used + 4 pad)
#define BNP 136          // B smem word stride

// ---------------- scratch (__device__ globals; no allocation allowed) ----------------
__device__ float  g_z  [BATCH*DLAT];
__device__ int    g_idx[BATCH];
__device__ float  g_counts[KCODES];
__device__ float  g_loss;
__device__ float  g_enorm[KCODES];
__device__ float  g_hw [HIDDEN*128];      // padded head weights [1024,128]
__device__ float  g_hb [128];
__device__ float  g_b3p[128];             // padded b3
// fp16-split packed operands (encoder + VQ)
__device__ uint32_t g_xH [BATCH*392];
__device__ uint32_t g_xL [BATCH*392];
__device__ uint32_t g_w1H[392*256];
__device__ uint32_t g_w1L[392*256];
__device__ uint32_t g_h1H[BATCH*128];
__device__ uint32_t g_h1L[BATCH*128];
__device__ uint32_t g_w2H[128*256];
__device__ uint32_t g_w2L[128*256];
__device__ uint32_t g_h2H[BATCH*128];
__device__ uint32_t g_h2L[BATCH*128];
__device__ uint32_t g_w3H[128*128];       // W3 padded [kp=128][n=128]
__device__ uint32_t g_w3L[128*128];
__device__ uint32_t g_zHiT[32*BATCH];
__device__ uint32_t g_zLoT[32*BATCH];
__device__ uint32_t g_eHiT[32*KCODES];
__device__ uint32_t g_eLoT[32*KCODES];
// fp16 hi-only packed (decoder)
__device__ uint32_t g_zqH [BATCH*32];
__device__ uint32_t g_dW1H[32*HIDDEN];
__device__ uint32_t g_d1H [BATCH*512];
__device__ uint32_t g_dW2H[512*HIDDEN];
__device__ uint32_t g_d2H [BATCH*512];
__device__ uint32_t g_hwH [512*128];

// ---------------- activations ----------------
#define ACT_NONE 0
#define ACT_LEAKY 1
#define ACT_SELU 2
#define ACT_HEAD 3

__device__ __forceinline__ float sigmoidf_(float x){ return 1.0f/(1.0f+expf(-x)); }

template<int ACT>
__device__ __forceinline__ float apply_act(float v, int col){
    if (ACT == ACT_LEAKY) return v > 0.0f ? v : 0.2f*v;
    if (ACT == ACT_SELU){
        const float a = 1.6732632423543772f, s = 1.0507009873554805f;
        return v > 0.0f ? s*v : s*a*(expf(v)-1.0f);
    }
    if (ACT == ACT_HEAD){
        if (col < 40) return tanhf(v)*12.0f + 14.0f;
        if (col < 42) return sigmoidf_(v)*2.0f + 1.0f;
        return sigmoidf_(v);
    }
    return v;
}

// ---------------- fp16 pack helpers ----------------
__device__ __forceinline__ void fp16_split_pack(float x0, float x1,
                                                uint32_t& hi, uint32_t& lo){
    __half h0 = __float2half_rn(x0), h1 = __float2half_rn(x1);
    __half l0 = __float2half_rn(x0 - __half2float(h0));
    __half l1 = __float2half_rn(x1 - __half2float(h1));
    __half2 hh = __halves2half2(h0, h1);
    __half2 ll = __halves2half2(l0, l1);
    hi = *(uint32_t*)&hh;
    lo = *(uint32_t*)&ll;
}
__device__ __forceinline__ uint32_t fp16_pack_hi(float x0, float x1){
    __half2 hh = __halves2half2(__float2half_rn(x0), __float2half_rn(x1));
    return *(uint32_t*)&hh;
}

// D += A*B, m16n8k16 fp16 (fp32 accum)
__device__ __forceinline__ void mma16(float* c, const uint32_t* a, const uint32_t* b){
    asm volatile(
        "mma.sync.aligned.m16n8k16.row.col.f32.f16.f16.f32 "
        "{%0,%1,%2,%3}, {%4,%5,%6,%7}, {%8,%9}, {%0,%1,%2,%3};\n"
        : "+f"(c[0]), "+f"(c[1]), "+f"(c[2]), "+f"(c[3])
        : "r"(a[0]), "r"(a[1]), "r"(a[2]), "r"(a[3]), "r"(b[0]), "r"(b[1]));
}

// ---------------- cp.async helpers ----------------
__device__ __forceinline__ void cpasync16(void* dst_smem, const void* src){
    uint32_t s = (uint32_t)__cvta_generic_to_shared(dst_smem);
    asm volatile("cp.async.cg.shared.global [%0], [%1], 16;\n" :: "r"(s), "l"(src));
}
__device__ __forceinline__ void cpasync_commit(){ asm volatile("cp.async.commit_group;\n"); }
template<int NN>
__device__ __forceinline__ void cpasync_wait(){ asm volatile("cp.async.wait_group %0;\n" :: "n"(NN)); }

// ---------------- pack kernels ----------------
__global__ void pack_rowsA(const float* __restrict__ src,
                           uint32_t* __restrict__ hiA, uint32_t* __restrict__ loA,
                           int nwords){
    int i = blockIdx.x * 256 + threadIdx.x;
    if (i >= nwords) return;
    float2 v = ((const float2*)src)[i];
    uint32_t hi, lo;
    fp16_split_pack(v.x, v.y, hi, lo);
    hiA[i] = hi; loA[i] = lo;
}

__global__ void pack_W(const float* __restrict__ W,
                       uint32_t* __restrict__ hiW, uint32_t* __restrict__ loW,
                       int KP, int N){
    int i = blockIdx.x * 256 + threadIdx.x;
    if (i >= KP*N) return;
    int kp = i / N, n = i % N;
    float x0 = W[(size_t)(2*kp)*N + n];
    float x1 = W[(size_t)(2*kp+1)*N + n];
    uint32_t hi, lo;
    fp16_split_pack(x0, x1, hi, lo);
    hiW[i] = hi; loW[i] = lo;
}

// W3 [256][64] -> padded packed [128][128]; b3 -> padded [128]
__global__ void pack_W3(const float* __restrict__ W3, const float* __restrict__ b3,
                        uint32_t* __restrict__ hiW, uint32_t* __restrict__ loW,
                        float* __restrict__ b3p){
    int i = blockIdx.x * 256 + threadIdx.x;
    if (i >= 128*128) return;
    int kp = i >> 7, n = i & 127;
    float x0 = 0.0f, x1 = 0.0f;
    if (n < 64){
        x0 = W3[(size_t)(2*kp)*64 + n];
        x1 = W3[(size_t)(2*kp+1)*64 + n];
    }
    uint32_t hi, lo;
    fp16_split_pack(x0, x1, hi, lo);
    hiW[i] = hi; loW[i] = lo;
    if (i < 128) b3p[i] = (i < 64) ? b3[i] : 0.0f;
}

// hi-only W pack (decoder path)
__global__ void pack_Wh(const float* __restrict__ W,
                        uint32_t* __restrict__ hiW, int KP, int N){
    int i = blockIdx.x * 256 + threadIdx.x;
    if (i >= KP*N) return;
    int kp = i / N, n = i % N;
    hiW[i] = fp16_pack_hi(W[(size_t)(2*kp)*N + n], W[(size_t)(2*kp+1)*N + n]);
}

__global__ void pack_embT(const float* __restrict__ emb,
                          uint32_t* __restrict__ eHiT, uint32_t* __restrict__ eLoT){
    int i = blockIdx.x * 256 + threadIdx.x;
    if (i >= 32*KCODES) return;
    int dp = i >> 12, c = i & (KCODES-1);
    float x0 = emb[(size_t)c*DLAT + 2*dp];
    float x1 = emb[(size_t)c*DLAT + 2*dp + 1];
    uint32_t hi, lo;
    fp16_split_pack(x0, x1, hi, lo);
    eHiT[i] = hi; eLoT[i] = lo;
}

// ============================================================================
// fp16-split GEMM: 3-product hi/lo. A [m][kp], B [kp][n]. BK=16.
// OUTPACK: 0 = fp32 C; 1 = packed hi/lo C;
//          2 = fp32 z (cols<64) + transposed hi/lo packs zHiT/zLoT [dp][b]
// ============================================================================
template<int ACT, int OUTPACK>
__global__ void __launch_bounds__(256, 2) mma_gemm_f16(
    const uint32_t* __restrict__ AH, const uint32_t* __restrict__ AL,
    const uint32_t* __restrict__ BH, const uint32_t* __restrict__ BL,
    const float* __restrict__ bias, float* __restrict__ C,
    uint32_t* __restrict__ CH, uint32_t* __restrict__ CL,
    int M, int N, int K)
{
    __shared__ uint32_t AsH[2][128][AKP], AsL[2][128][AKP];
    __shared__ uint32_t BsH[2][8][BNP],   BsL[2][8][BNP];

    const int tid  = threadIdx.x;
    const int lane = tid & 31, warp = tid >> 5;
    const int wm = (warp & 1) * 64, wn = (warp >> 1) * 32;
    const int bm = blockIdx.y * 128, bn = blockIdx.x * 128;
    const int g = lane >> 2, tg = lane & 3;
    const int KP = K >> 1;

    float acc[4][4][4];
    #pragma unroll
    for (int i = 0; i < 4; i++)
        #pragma unroll
        for (int j = 0; j < 4; j++)
            #pragma unroll
            for (int q = 0; q < 4; q++) acc[i][j][q] = 0.0f;

    const int ar = tid >> 1, ac = (tid & 1) * 4;
    const int br = tid >> 5, bc = lane * 4;
    const uint32_t* AHp = AH + (size_t)(bm + ar) * KP + ac;
    const uint32_t* ALp = AL + (size_t)(bm + ar) * KP + ac;
    const uint32_t* BHp = BH + (size_t)br * N + bn + bc;
    const uint32_t* BLp = BL + (size_t)br * N + bn + bc;

    const int ntiles = K >> 4;

    #define COPY_F16(kt, buf) do { \
        cpasync16(&AsH[buf][ar][ac], AHp + (size_t)(kt)*8); \
        cpasync16(&AsL[buf][ar][ac], ALp + (size_t)(kt)*8); \
        cpasync16(&BsH[buf][br][bc], BHp + (size_t)(kt)*8*N); \
        cpasync16(&BsL[buf][br][bc], BLp + (size_t)(kt)*8*N); \
        cpasync_commit(); \
    } while (0)

    COPY_F16(0, 0);

    for (int i = 0; i < ntiles; i++){
        int buf = i & 1;
        if (i + 1 < ntiles){
            COPY_F16(i + 1, buf ^ 1);
            cpasync_wait<1>();
        } else {
            cpasync_wait<0>();
        }
        __syncthreads();

        uint32_t ah[4][4], al[4][4];
        #pragma unroll
        for (int mt = 0; mt < 4; mt++){
            int m = wm + mt*16 + g;
            ah[mt][0] = AsH[buf][m  ][tg];
            ah[mt][1] = AsH[buf][m+8][tg];
            ah[mt][2] = AsH[buf][m  ][tg+4];
            ah[mt][3] = AsH[buf][m+8][tg+4];
            al[mt][0] = AsL[buf][m  ][tg];
            al[mt][1] = AsL[buf][m+8][tg];
            al[mt][2] = AsL[buf][m  ][tg+4];
            al[mt][3] = AsL[buf][m+8][tg+4];
        }
        #pragma unroll
        for (int nt = 0; nt < 4; nt++){
            int n = wn + nt*8 + g;
            uint32_t bh[2] = { BsH[buf][tg][n], BsH[buf][tg+4][n] };
            uint32_t bl[2] = { BsL[buf][tg][n], BsL[buf][tg+4][n] };
            #pragma unroll
            for (int mt = 0; mt < 4; mt++) mma16(acc[mt][nt], ah[mt], bh);
            #pragma unroll
            for (int mt = 0; mt < 4; mt++) mma16(acc[mt][nt], al[mt], bh);
            #pragma unroll
            for (int mt = 0; mt < 4; mt++) mma16(acc[mt][nt], ah[mt], bl);
        }
        __syncthreads();
    }
    #undef COPY_F16

    #pragma unroll
    for (int mt = 0; mt < 4; mt++){
        #pragma unroll
        for (int nt = 0; nt < 4; nt++){
            int row = bm + wm + mt*16 + g;
            int col = bn + wn + nt*8 + 2*tg;
            float bs0 = bias[col], bs1 = bias[col+1];
            float v00 = apply_act<ACT>(acc[mt][nt][0] + bs0, col);
            float v01 = apply_act<ACT>(acc[mt][nt][1] + bs1, col+1);
            float v10 = apply_act<ACT>(acc[mt][nt][2] + bs0, col);
            float v11 = apply_act<ACT>(acc[mt][nt][3] + bs1, col+1);
            if (OUTPACK == 1){
                int w = col >> 1;
                int NP = N >> 1;
                uint32_t h0, l0, h1, l1;
                fp16_split_pack(v00, v01, h0, l0);
                fp16_split_pack(v10, v11, h1, l1);
                CH[(size_t)row*NP + w]     = h0;
                CL[(size_t)row*NP + w]     = l0;
                CH[(size_t)(row+8)*NP + w] = h1;
                CL[(size_t)(row+8)*NP + w] = l1;
            } else if (OUTPACK == 2){
                if (col < DLAT){
                    *(float2*)&C[(size_t)row*DLAT + col]     = make_float2(v00, v01);
                    *(float2*)&C[(size_t)(row+8)*DLAT + col] = make_float2(v10, v11);
                    int dp = col >> 1;
                    uint32_t h0, l0, h1, l1;
                    fp16_split_pack(v00, v01, h0, l0);
                    fp16_split_pack(v10, v11, h1, l1);
                    CH[(size_t)dp*BATCH + row]     = h0;
                    CL[(size_t)dp*BATCH + row]     = l0;
                    CH[(size_t)dp*BATCH + row + 8] = h1;
                    CL[(size_t)dp*BATCH + row + 8] = l1;
                }
            } else {
                *(float2*)&C[(size_t)row*N + col]     = make_float2(v00, v01);
                *(float2*)&C[(size_t)(row+8)*N + col] = make_float2(v10, v11);
            }
        }
    }
}

// ============================================================================
// fp16 hi-only GEMM (decoder + head): 1-product, BK=32.
// OUTPACK: 0 = fp32 C; 1 = packed hi C; 3 = fused output packing (head)
// ============================================================================
template<int ACT, int OUTPACK>
__global__ void __launch_bounds__(256, 2) mma_gemm_h16(
    const uint32_t* __restrict__ AH, const uint32_t* __restrict__ BH,
    const float* __restrict__ bias, float* __restrict__ C,
    uint32_t* __restrict__ CH,
    int M, int N, int K)
{
    __shared__ uint32_t AsH[2][128][AKP2];
    __shared__ uint32_t BsH[2][16][BNP];

    const int tid  = threadIdx.x;
    const int lane = tid & 31, warp = tid >> 5;
    const int wm = (warp & 1) * 64, wn = (warp >> 1) * 32;
    const int bm = blockIdx.y * 128, bn = blockIdx.x * 128;
    const int g = lane >> 2, tg = lane & 3;
    const int KP = K >> 1;

    float acc[4][4][4];
    #pragma unroll
    for (int i = 0; i < 4; i++)
        #pragma unroll
        for (int j = 0; j < 4; j++)
            #pragma unroll
            for (int q = 0; q < 4; q++) acc[i][j][q] = 0.0f;

    const int ar = tid >> 1, ac = (tid & 1) * 8;
    const int br = tid >> 4, bc = (tid & 15) * 8;
    const uint32_t* AHp = AH + (size_t)(bm + ar) * KP + ac;
    const uint32_t* BHp = BH + (size_t)br * N + bn + bc;

    const int ntiles = K >> 5;   // 16 kp per tile

    #define COPY_H16(kt, buf) do { \
        cpasync16(&AsH[buf][ar][ac],   AHp + (size_t)(kt)*16); \
        cpasync16(&AsH[buf][ar][ac+4], AHp + (size_t)(kt)*16 + 4); \
        cpasync16(&BsH[buf][br][bc],   BHp + (size_t)(kt)*16*N); \
        cpasync16(&BsH[buf][br][bc+4], BHp + (size_t)(kt)*16*N + 4); \
        cpasync_commit(); \
    } while (0)

    COPY_H16(0, 0);

    for (int i = 0; i < ntiles; i++){
        int buf = i & 1;
        if (i + 1 < ntiles){
            COPY_H16(i + 1, buf ^ 1);
            cpasync_wait<1>();
        } else {
            cpasync_wait<0>();
        }
        __syncthreads();

        #pragma unroll
        for (int kb = 0; kb < 2; kb++){
            uint32_t ah[4][4];
            #pragma unroll
            for (int mt = 0; mt < 4; mt++){
                int m = wm + mt*16 + g;
                ah[mt][0] = AsH[buf][m  ][kb*8+tg];
                ah[mt][1] = AsH[buf][m+8][kb*8+tg];
                ah[mt][2] = AsH[buf][m  ][kb*8+tg+4];
                ah[mt][3] = AsH[buf][m+8][kb*8+tg+4];
            }
            #pragma unroll
            for (int nt = 0; nt < 4; nt++){
                int n = wn + nt*8 + g;
                uint32_t bh[2] = { BsH[buf][kb*8+tg][n], BsH[buf][kb*8+tg+4][n] };
                #pragma unroll
                for (int mt = 0; mt < 4; mt++) mma16(acc[mt][nt], ah[mt], bh);
            }
        }
        __syncthreads();
    }
    #undef COPY_H16

    #pragma unroll
    for (int mt = 0; mt < 4; mt++){
        #pragma unroll
        for (int nt = 0; nt < 4; nt++){
            int row = bm + wm + mt*16 + g;
            int col = bn + wn + nt*8 + 2*tg;
            float bs0 = bias[col], bs1 = bias[col+1];
            float v00 = apply_act<ACT>(acc[mt][nt][0] + bs0, col);
            float v01 = apply_act<ACT>(acc[mt][nt][1] + bs1, col+1);
            float v10 = apply_act<ACT>(acc[mt][nt][2] + bs0, col);
            float v11 = apply_act<ACT>(acc[mt][nt][3] + bs1, col+1);
            if (OUTPACK == 1){
                int w = col >> 1;
                int NP = N >> 1;
                CH[(size_t)row*NP + w]     = fp16_pack_hi(v00, v01);
                CH[(size_t)(row+8)*NP + w] = fp16_pack_hi(v10, v11);
            } else if (OUTPACK == 3){
                // fused output packing (head): col even, valid cols < 44
                if (col < 40){
                    int p = col / 20, rem = col - p*20;
                    int q = rem >> 1;
                    *(float2*)&C[P_OFF + (size_t)row*40 + col]     = make_float2(v00, v01);
                    *(float2*)&C[P_OFF + (size_t)(row+8)*40 + col] = make_float2(v10, v11);
                    #pragma unroll
                    for (int sg = 0; sg < 3; sg++){
                        int j = q - 3*sg;
                        if (j >= 0 && j < 4){
                            size_t o = (size_t)p*24 + sg*8 + j*2;
                            *(float2*)&C[CP_OFF + (size_t)row*48 + o]     = make_float2(v00, v01);
                            *(float2*)&C[CP_OFF + (size_t)(row+8)*48 + o] = make_float2(v10, v11);
                        }
                    }
                } else if (col == 40){
                    *(float2*)&C[W_OFF + (size_t)row*2]     = make_float2(v00, v01);
                    *(float2*)&C[W_OFF + (size_t)(row+8)*2] = make_float2(v10, v11);
                } else if (col == 42){
                    *(float2*)&C[A_OFF + (size_t)row*2]     = make_float2(v00, v01);
                    *(float2*)&C[A_OFF + (size_t)(row+8)*2] = make_float2(v10, v11);
                }
            } else {
                *(float2*)&C[(size_t)row*N + col]     = make_float2(v00, v01);
                *(float2*)&C[(size_t)(row+8)*N + col] = make_float2(v10, v11);
            }
        }
    }
}

// ---------------- codebook norms ----------------
__global__ void enorm_kernel(const float* __restrict__ emb, float* __restrict__ enorm){
    int k = blockIdx.x * 256 + threadIdx.x;
    if (k >= KCODES) return;
    const float4* e = (const float4*)(emb + (size_t)k * DLAT);
    float s = 0.0f;
    #pragma unroll
    for (int q = 0; q < 16; q++){
        float4 v = e[q];
        s += v.x*v.x + v.y*v.y + v.z*v.z + v.w*v.w;
    }
    enorm[k] = s;
}

// ---------------- VQ argmin: fp16-split m16n8k16, pre-packed operands ----------------
__global__ void __launch_bounds__(256, 2) vq_argmin_f16(
    const uint32_t* __restrict__ zHiT, const uint32_t* __restrict__ zLoT,
    const uint32_t* __restrict__ eHiT, const uint32_t* __restrict__ eLoT,
    const float* __restrict__ enorm, int* __restrict__ idx_out)
{
    __shared__ uint32_t ZH[32][HS], ZL[32][HS];
    __shared__ uint32_t EH[2][32][HS], EL[2][32][HS];

    const int tid  = threadIdx.x;
    const int lane = tid & 31, warp = tid >> 5;
    const int wm = (warp & 1) * 64, wn = (warp >> 1) * 32;
    const int bm = blockIdx.x * 128;
    const int g = lane >> 2, tg = lane & 3;

    {
        #pragma unroll
        for (int j = 0; j < 4; j++){
            int unit = j*256 + tid;
            int dp = unit >> 5, u = unit & 31;
            cpasync16(&ZH[dp][u*4], zHiT + (size_t)dp*BATCH + bm + u*4);
            cpasync16(&ZL[dp][u*4], zLoT + (size_t)dp*BATCH + bm + u*4);
        }
        cpasync_commit();
    }

    #define COPY_EP(c0_, buf_) do { \
        _Pragma("unroll") \
        for (int j = 0; j < 4; j++){ \
            int unit = j*256 + tid; \
            int dp_ = unit >> 5, u_ = unit & 31; \
            cpasync16(&EH[buf_][dp_][u_*4], eHiT + (size_t)dp_*KCODES + (c0_) + u_*4); \
            cpasync16(&EL[buf_][dp_][u_*4], eLoT + (size_t)dp_*KCODES + (c0_) + u_*4); \
        } \
        cpasync_commit(); \
    } while (0)

    float mv[8]; int mi[8];
    #pragma unroll
    for (int s = 0; s < 8; s++){ mv[s] = INFINITY; mi[s] = 0; }

    COPY_EP(0, 0);

    for (int ch = 0; ch < KCODES/128; ch++){
        int c0 = ch * 128;
        int buf = ch & 1;
        if (ch + 1 < KCODES/128){
            COPY_EP(c0 + 128, buf ^ 1);
            cpasync_wait<1>();
        } else {
            cpasync_wait<0>();
        }
        __syncthreads();

        float acc[4][4][4];
        #pragma unroll
        for (int i = 0; i < 4; i++)
            #pragma unroll
            for (int j = 0; j < 4; j++)
                #pragma unroll
                for (int q = 0; q < 4; q++) acc[i][j][q] = 0.0f;

        #pragma unroll
        for (int kb = 0; kb < 4; kb++){
            uint32_t ah[4][4], al[4][4];
            #pragma unroll
            for (int mt = 0; mt < 4; mt++){
                int m = wm + mt*16 + g;
                ah[mt][0] = ZH[kb*8+tg  ][m];
                ah[mt][1] = ZH[kb*8+tg  ][m+8];
                ah[mt][2] = ZH[kb*8+tg+4][m];
                ah[mt][3] = ZH[kb*8+tg+4][m+8];
                al[mt][0] = ZL[kb*8+tg  ][m];
                al[mt][1] = ZL[kb*8+tg  ][m+8];
                al[mt][2] = ZL[kb*8+tg+4][m];
                al[mt][3] = ZL[kb*8+tg+4][m+8];
            }
            #pragma unroll
            for (int nt = 0; nt < 4; nt++){
                int n = wn + nt*8 + g;
                uint32_t bh[2] = { EH[buf][kb*8+tg][n], EH[buf][kb*8+tg+4][n] };
                uint32_t bl[2] = { EL[buf][kb*8+tg][n], EL[buf][kb*8+tg+4][n] };
                #pragma unroll
                for (int mt = 0; mt < 4; mt++) mma16(acc[mt][nt], ah[mt], bh);
                #pragma unroll
                for (int mt = 0; mt < 4; mt++) mma16(acc[mt][nt], al[mt], bh);
                #pragma unroll
                for (int mt = 0; mt < 4; mt++) mma16(acc[mt][nt], ah[mt], bl);
            }
        }

        #pragma unroll
        for (int nt = 0; nt < 4; nt++){
            int nc = wn + nt*8 + 2*tg;
            float e0 = __ldg(enorm + c0 + nc);
            float e1 = __ldg(enorm + c0 + nc + 1);
            int code = c0 + nc;
            #pragma unroll
            for (int mt = 0; mt < 4; mt++){
                float d00 = e0 - 2.0f*acc[mt][nt][0];
                float d01 = e1 - 2.0f*acc[mt][nt][1];
                float d10 = e0 - 2.0f*acc[mt][nt][2];
                float d11 = e1 - 2.0f*acc[mt][nt][3];
                int s0 = mt*2, s1 = mt*2 + 1;
                if (d00 < mv[s0]){ mv[s0] = d00; mi[s0] = code;   }
                if (d01 < mv[s0]){ mv[s0] = d01; mi[s0] = code+1; }
                if (d10 < mv[s1]){ mv[s1] = d10; mi[s1] = code;   }
                if (d11 < mv[s1]){ mv[s1] = d11; mi[s1] = code+1; }
            }
        }
        __syncthreads();
    }
    #undef COPY_EP

    float* rv = (float*)&EH[0][0][0];
    int*   ri = ((int*)rv) + 16*128;
    int cand = (warp >> 1) * 4 + tg;
    #pragma unroll
    for (int s = 0; s < 8; s++){
        int r = wm + (s >> 1)*16 + g + (s & 1)*8;
        rv[cand*128 + r] = mv[s];
        ri[cand*128 + r] = mi[s];
    }
    __syncthreads();
    if (tid < 128){
        float bv = INFINITY; int bi = 0x7fffffff;
        #pragma unroll
        for (int t = 0; t < 16; t++){
            float v = rv[t*128 + tid];
            int c = ri[t*128 + tid];
            if (v < bv || (v == bv && c < bi)){ bv = v; bi = c; }
        }
        idx_out[bm + tid] = bi;
    }
}

// ---------------- gather: packed fp16 zq, idx-as-float, counts, commit-loss ----------------
__global__ void vq_post(const float* __restrict__ z, const float* __restrict__ emb,
                        const int* __restrict__ idx, uint32_t* __restrict__ zqH,
                        float* __restrict__ counts, float* __restrict__ loss,
                        float* __restrict__ out_idx)
{
    int b = blockIdx.x * 256 + threadIdx.x;
    int k = idx[b];
    const float4* e  = (const float4*)(emb + (size_t)k * DLAT);
    const float4* zz = (const float4*)(z   + (size_t)b * DLAT);
    uint32_t*     zo = zqH + (size_t)b * 32;
    float s = 0.0f;
    #pragma unroll
    for (int q = 0; q < 16; q++){
        float4 ev = e[q], zv = zz[q];
        float dx = ev.x - zv.x, dy = ev.y - zv.y, dz = ev.z - zv.z, dw = ev.w - zv.w;
        s += dx*dx + dy*dy + dz*dz + dw*dw;
        zo[q*2]   = fp16_pack_hi(ev.x, ev.y);
        zo[q*2+1] = fp16_pack_hi(ev.z, ev.w);
    }
    out_idx[b] = (float)k;
    atomicAdd(&counts[k], 1.0f);

    __shared__ float red[256];
    red[threadIdx.x] = s;
    __syncthreads();
    for (int off = 128; off > 0; off >>= 1){
        if (threadIdx.x < off) red[threadIdx.x] += red[threadIdx.x + off];
        __syncthreads();
    }
    if (threadIdx.x == 0) atomicAdd(loss, red[0]);
}

// ---------------- perplexity + vq_loss scalars ----------------
__global__ void finalize_kernel(const float* __restrict__ counts, const float* __restrict__ loss,
                                float* __restrict__ out)
{
    __shared__ float red[256];
    float s = 0.0f;
    for (int k = threadIdx.x; k < KCODES; k += 256){
        float p = counts[k] * (1.0f / (float)BATCH);
        s += p * logf(p + 1e-10f);
    }
    red[threadIdx.x] = s;
    __syncthreads();
    for (int off = 128; off > 0; off >>= 1){
        if (threadIdx.x < off) red[threadIdx.x] += red[threadIdx.x + off];
        __syncthreads();
    }
    if (threadIdx.x == 0){
        out[PERP_OFF] = expf(-red[0]);
        out[LOSS_OFF] = loss[0] * (0.25f / ((float)BATCH * (float)DLAT));
    }
}

// ---------------- zero counts + loss ----------------
__global__ void zero_kernel(float* __restrict__ counts, float* __restrict__ loss){
    int i = blockIdx.x * 256 + threadIdx.x;
    if (i < KCODES) counts[i] = 0.0f;
    if (i == KCODES) loss[0] = 0.0f;
}

// ---------------- concat head weights -> [1024,128], biases -> [128] ----------------
__global__ void concat_head(const float* __restrict__ pW, const float* __restrict__ pb,
                            const float* __restrict__ wW, const float* __restrict__ wb,
                            const float* __restrict__ aW, const float* __restrict__ ab,
                            float* __restrict__ hw, float* __restrict__ hb)
{
    int i = blockIdx.x * 256 + threadIdx.x;
    int total = HIDDEN * 128;
    if (i < total){
        int k = i >> 7, col = i & 127;
        float v = 0.0f;
        if (col < 40)      v = pW[k*40 + col];
        else if (col < 42) v = wW[k*2 + (col-40)];
        else if (col < 44) v = aW[k*2 + (col-42)];
        hw[i] = v;
    }
    if (i < 128){
        float v = 0.0f;
        if (i < 40)      v = pb[i];
        else if (i < 42) v = wb[i-40];
        else if (i < 44) v = ab[i-42];
        hb[i] = v;
    }
}

// ---------------- launch ----------------
extern "C" void kernel_launch(void* const* d_in, const int* in_sizes, int n_in,
                              void* d_out, int out_size)
{
    (void)in_sizes; (void)n_in; (void)out_size;
    const float* x   = (const float*)d_in[0];
    const float* W1  = (const float*)d_in[1];
    const float* b1  = (const float*)d_in[2];
    const float* W2  = (const float*)d_in[3];
    const float* b2  = (const float*)d_in[4];
    const float* W3  = (const float*)d_in[5];
    const float* b3  = (const float*)d_in[6];
    const float* emb = (const float*)d_in[7];
    const float* dW1 = (const float*)d_in[8];
    const float* db1 = (const float*)d_in[9];
    const float* dW2 = (const float*)d_in[10];
    const float* db2 = (const float*)d_in[11];
    const float* pW  = (const float*)d_in[12];
    const float* pb  = (const float*)d_in[13];
    const float* wW  = (const float*)d_in[14];
    const float* wb  = (const float*)d_in[15];
    const float* aW  = (const float*)d_in[16];
    const float* ab  = (const float*)d_in[17];
    float* out = (float*)d_out;

    float *z, *counts, *loss, *enorm, *hw, *hb, *b3p;
    uint32_t *xH, *xL, *w1H, *w1L, *h1H, *h1L, *w2H, *w2L, *h2H, *h2L, *w3H, *w3L;
    uint32_t *zHiT, *zLoT, *eHiT, *eLoT;
    uint32_t *zqH, *dW1H, *d1H, *dW2H, *d2H, *hwH;
    int* idx;
    cudaGetSymbolAddress((void**)&z,  g_z);
    cudaGetSymbolAddress((void**)&idx, g_idx);
    cudaGetSymbolAddress((void**)&counts, g_counts);
    cudaGetSymbolAddress((void**)&loss, g_loss);
    cudaGetSymbolAddress((void**)&enorm, g_enorm);
    cudaGetSymbolAddress((void**)&hw, g_hw);
    cudaGetSymbolAddress((void**)&hb, g_hb);
    cudaGetSymbolAddress((void**)&b3p, g_b3p);
    cudaGetSymbolAddress((void**)&xH, g_xH);
    cudaGetSymbolAddress((void**)&xL, g_xL);
    cudaGetSymbolAddress((void**)&w1H, g_w1H);
    cudaGetSymbolAddress((void**)&w1L, g_w1L);
    cudaGetSymbolAddress((void**)&h1H, g_h1H);
    cudaGetSymbolAddress((void**)&h1L, g_h1L);
    cudaGetSymbolAddress((void**)&w2H, g_w2H);
    cudaGetSymbolAddress((void**)&w2L, g_w2L);
    cudaGetSymbolAddress((void**)&h2H, g_h2H);
    cudaGetSymbolAddress((void**)&h2L, g_h2L);
    cudaGetSymbolAddress((void**)&w3H, g_w3H);
    cudaGetSymbolAddress((void**)&w3L, g_w3L);
    cudaGetSymbolAddress((void**)&zHiT, g_zHiT);
    cudaGetSymbolAddress((void**)&zLoT, g_zLoT);
    cudaGetSymbolAddress((void**)&eHiT, g_eHiT);
    cudaGetSymbolAddress((void**)&eLoT, g_eLoT);
    cudaGetSymbolAddress((void**)&zqH,  g_zqH);
    cudaGetSymbolAddress((void**)&dW1H, g_dW1H);
    cudaGetSymbolAddress((void**)&d1H,  g_d1H);
    cudaGetSymbolAddress((void**)&dW2H, g_dW2H);
    cudaGetSymbolAddress((void**)&d2H,  g_d2H);
    cudaGetSymbolAddress((void**)&hwH,  g_hwH);

    // init + packs
    zero_kernel<<<(KCODES + 1 + 255)/256, 256>>>(counts, loss);
    concat_head<<<(HIDDEN*128 + 255)/256, 256>>>(pW, pb, wW, wb, aW, ab, hw, hb);
    enorm_kernel<<<(KCODES + 255)/256, 256>>>(emb, enorm);
    pack_rowsA<<<(BATCH*392 + 255)/256, 256>>>(x, xH, xL, BATCH*392);
    pack_W<<<(392*256 + 255)/256, 256>>>(W1, w1H, w1L, 392, 256);
    pack_W<<<(128*256 + 255)/256, 256>>>(W2, w2H, w2L, 128, 256);
    pack_W3<<<(128*128 + 255)/256, 256>>>(W3, b3, w3H, w3L, b3p);
    pack_embT<<<(32*KCODES + 255)/256, 256>>>(emb, eHiT, eLoT);
    pack_Wh<<<(32*HIDDEN + 255)/256, 256>>>(dW1, dW1H, 32, HIDDEN);
    pack_Wh<<<(512*HIDDEN + 255)/256, 256>>>(dW2, dW2H, 512, HIDDEN);
    pack_Wh<<<(512*128 + 255)/256, 256>>>(hw, hwH, 512, 128);

    // encoder (fp16-split 3-product)
    mma_gemm_f16<ACT_LEAKY, 1><<<dim3(2, BATCH/128), 256>>>(
        xH, xL, w1H, w1L, b1, nullptr, h1H, h1L, BATCH, 256, 784);
    mma_gemm_f16<ACT_LEAKY, 1><<<dim3(2, BATCH/128), 256>>>(
        h1H, h1L, w2H, w2L, b2, nullptr, h2H, h2L, BATCH, 256, 256);
    // z projection: fp16-split MMA, fused fp32 z + transposed hi/lo packs
    mma_gemm_f16<ACT_NONE, 2><<<dim3(1, BATCH/128), 256>>>(
        h2H, h2L, w3H, w3L, b3p, z, zHiT, zLoT, BATCH, 128, 256);

    // VQ
    vq_argmin_f16<<<BATCH/128, 256>>>(zHiT, zLoT, eHiT, eLoT, enorm, idx);
    vq_post<<<BATCH/256, 256>>>(z, emb, idx, zqH, counts, loss, out + IDX_OFF);
    finalize_kernel<<<1, 256>>>(counts, loss, out);

    // decoder (fp16 hi-only 1-product, BK=32)
    mma_gemm_h16<ACT_SELU, 1><<<dim3(HIDDEN/128, BATCH/128), 256>>>(
        zqH, dW1H, db1, nullptr, d1H, BATCH, HIDDEN, DLAT);
    mma_gemm_h16<ACT_SELU, 1><<<dim3(HIDDEN/128, BATCH/128), 256>>>(
        d1H, dW2H, db2, nullptr, d2H, BATCH, HIDDEN, HIDDEN);

    // head (fp16 hi-only, fused output packing straight into out)
    mma_gemm_h16<ACT_HEAD, 3><<<dim3(1, BATCH/128), 256>>>(
        d2H, hwH, hb, out, nullptr, BATCH, 128, HIDDEN);
}

// round 15
// speedup vs baseline: 2.3849x; 1.0361x over previous
#include <cuda_runtime.h>
#include <cuda_fp16.h>
#include <math.h>
#include <stdint.h>

// ---------------- problem constants ----------------
#define BATCH   32768
#define KCODES  4096
#define DLAT    64
#define HIDDEN  1024

// output layout (f32, reference return order, flattened+concat)
#define P_OFF    0
#define P_SIZE   (BATCH*40)
#define CP_OFF   (P_OFF + P_SIZE)
#define CP_SIZE  (BATCH*48)
#define W_OFF    (CP_OFF + CP_SIZE)
#define WA_SIZE  (BATCH*2)
#define A_OFF    (W_OFF + WA_SIZE)
#define LOSS_OFF (A_OFF + WA_SIZE)
#define IDX_OFF  (LOSS_OFF + 1)
#define PERP_OFF (IDX_OFF + BATCH)

#define HS 136           // VQ smem word stride (conflict-free)
#define AKP 12           // BK16 A smem word stride (8 used + 4 pad)
#define AKP2 20          // BK32 A smem word stride (16 used + 4 pad)
#define BNP 136          // B smem word stride

// ---------------- scratch (__device__ globals; no allocation allowed) ----------------
__device__ float  g_z  [BATCH*DLAT];
__device__ int    g_idx[BATCH];
__device__ float  g_counts[KCODES];
__device__ float  g_loss;
__device__ float  g_enorm[KCODES];
__device__ float  g_hb [128];
__device__ float  g_b3p[128];             // padded b3
// fp16-split packed operands (encoder + VQ)
__device__ uint32_t g_xH [BATCH*392];
__device__ uint32_t g_xL [BATCH*392];
__device__ uint32_t g_w1H[392*256];
__device__ uint32_t g_w1L[392*256];
__device__ uint32_t g_h1H[BATCH*128];
__device__ uint32_t g_h1L[BATCH*128];
__device__ uint32_t g_w2H[128*256];
__device__ uint32_t g_w2L[128*256];
__device__ uint32_t g_h2H[BATCH*128];
__device__ uint32_t g_h2L[BATCH*128];
__device__ uint32_t g_w3H[128*128];       // W3 padded [kp=128][n=128]
__device__ uint32_t g_w3L[128*128];
__device__ uint32_t g_zHiT[32*BATCH];
__device__ uint32_t g_zLoT[32*BATCH];
__device__ uint32_t g_eHiT[32*KCODES];
__device__ uint32_t g_eLoT[32*KCODES];
// fp16 hi-only packed (decoder)
__device__ uint32_t g_zqH [BATCH*32];
__device__ uint32_t g_dW1H[32*HIDDEN];
__device__ uint32_t g_d1H [BATCH*512];
__device__ uint32_t g_dW2H[512*HIDDEN];
__device__ uint32_t g_d2H [BATCH*512];
__device__ uint32_t g_hwH [512*128];

// ---------------- activations ----------------
#define ACT_NONE 0
#define ACT_LEAKY 1
#define ACT_SELU 2
#define ACT_HEAD 3

__device__ __forceinline__ float sigmoidf_(float x){ return 1.0f/(1.0f+expf(-x)); }

template<int ACT>
__device__ __forceinline__ float apply_act(float v, int col){
    if (ACT == ACT_LEAKY) return v > 0.0f ? v : 0.2f*v;
    if (ACT == ACT_SELU){
        const float a = 1.6732632423543772f, s = 1.0507009873554805f;
        return v > 0.0f ? s*v : s*a*(expf(v)-1.0f);
    }
    if (ACT == ACT_HEAD){
        if (col < 40) return tanhf(v)*12.0f + 14.0f;
        if (col < 42) return sigmoidf_(v)*2.0f + 1.0f;
        return sigmoidf_(v);
    }
    return v;
}

// ---------------- fp16 pack helpers ----------------
__device__ __forceinline__ void fp16_split_pack(float x0, float x1,
                                                uint32_t& hi, uint32_t& lo){
    __half h0 = __float2half_rn(x0), h1 = __float2half_rn(x1);
    __half l0 = __float2half_rn(x0 - __half2float(h0));
    __half l1 = __float2half_rn(x1 - __half2float(h1));
    __half2 hh = __halves2half2(h0, h1);
    __half2 ll = __halves2half2(l0, l1);
    hi = *(uint32_t*)&hh;
    lo = *(uint32_t*)&ll;
}
__device__ __forceinline__ uint32_t fp16_pack_hi(float x0, float x1){
    __half2 hh = __halves2half2(__float2half_rn(x0), __float2half_rn(x1));
    return *(uint32_t*)&hh;
}

// D += A*B, m16n8k16 fp16 (fp32 accum)
__device__ __forceinline__ void mma16(float* c, const uint32_t* a, const uint32_t* b){
    asm volatile(
        "mma.sync.aligned.m16n8k16.row.col.f32.f16.f16.f32 "
        "{%0,%1,%2,%3}, {%4,%5,%6,%7}, {%8,%9}, {%0,%1,%2,%3};\n"
        : "+f"(c[0]), "+f"(c[1]), "+f"(c[2]), "+f"(c[3])
        : "r"(a[0]), "r"(a[1]), "r"(a[2]), "r"(a[3]), "r"(b[0]), "r"(b[1]));
}

// ---------------- cp.async helpers ----------------
__device__ __forceinline__ void cpasync16(void* dst_smem, const void* src){
    uint32_t s = (uint32_t)__cvta_generic_to_shared(dst_smem);
    asm volatile("cp.async.cg.shared.global [%0], [%1], 16;\n" :: "r"(s), "l"(src));
}
__device__ __forceinline__ void cpasync_commit(){ asm volatile("cp.async.commit_group;\n"); }
template<int NN>
__device__ __forceinline__ void cpasync_wait(){ asm volatile("cp.async.wait_group %0;\n" :: "n"(NN)); }

// ---------------- x pack (wide, float4/thread) ----------------
__global__ void pack_rowsA4(const float* __restrict__ src,
                            uint32_t* __restrict__ hiA, uint32_t* __restrict__ loA,
                            int nquads){
    int i = blockIdx.x * 256 + threadIdx.x;
    if (i >= nquads) return;
    float4 v = ((const float4*)src)[i];
    uint32_t h0, l0, h1, l1;
    fp16_split_pack(v.x, v.y, h0, l0);
    fp16_split_pack(v.z, v.w, h1, l1);
    ((uint2*)hiA)[i] = make_uint2(h0, h1);
    ((uint2*)loA)[i] = make_uint2(l0, l1);
}

// ---------------- mega setup: all weight packs + scalars in ONE launch ----------------
// segment sizes
#define S_ZERO   (KCODES + 1)                 // counts + loss
#define S_ENORM  KCODES
#define S_W1     (392*256)
#define S_W2     (128*256)
#define S_W3     (128*128)
#define S_EMBT   (32*KCODES)
#define S_DW1    (32*HIDDEN)
#define S_DW2    (512*HIDDEN)
#define S_HEAD   (512*128)
#define O_ENORM  S_ZERO
#define O_W1     (O_ENORM + S_ENORM)
#define O_W2     (O_W1 + S_W1)
#define O_W3     (O_W2 + S_W2)
#define O_EMBT   (O_W3 + S_W3)
#define O_DW1    (O_EMBT + S_EMBT)
#define O_DW2    (O_DW1 + S_DW1)
#define O_HEAD   (O_DW2 + S_DW2)
#define S_TOTAL  (O_HEAD + S_HEAD)

__device__ __forceinline__ float head_w(const float* pW, const float* wW,
                                        const float* aW, int k, int col){
    if (col < 40) return pW[k*40 + col];
    if (col < 42) return wW[k*2 + (col-40)];
    if (col < 44) return aW[k*2 + (col-42)];
    return 0.0f;
}

__global__ void mega_setup(
    const float* __restrict__ W1, const float* __restrict__ W2,
    const float* __restrict__ W3, const float* __restrict__ b3,
    const float* __restrict__ emb,
    const float* __restrict__ dW1, const float* __restrict__ dW2,
    const float* __restrict__ pW, const float* __restrict__ pb,
    const float* __restrict__ wW, const float* __restrict__ wb,
    const float* __restrict__ aW, const float* __restrict__ ab,
    float* __restrict__ counts, float* __restrict__ loss,
    float* __restrict__ enorm, float* __restrict__ b3p, float* __restrict__ hb,
    uint32_t* __restrict__ w1H, uint32_t* __restrict__ w1L,
    uint32_t* __restrict__ w2H, uint32_t* __restrict__ w2L,
    uint32_t* __restrict__ w3H, uint32_t* __restrict__ w3L,
    uint32_t* __restrict__ eHiT, uint32_t* __restrict__ eLoT,
    uint32_t* __restrict__ dW1H, uint32_t* __restrict__ dW2H,
    uint32_t* __restrict__ hwH)
{
    int gi = blockIdx.x * 256 + threadIdx.x;
    if (gi >= S_TOTAL) return;

    if (gi < S_ZERO){
        if (gi < KCODES) counts[gi] = 0.0f; else loss[0] = 0.0f;
    } else if (gi < O_W1){
        int k = gi - O_ENORM;
        const float4* e = (const float4*)(emb + (size_t)k * DLAT);
        float s = 0.0f;
        #pragma unroll
        for (int q = 0; q < 16; q++){
            float4 v = e[q];
            s += v.x*v.x + v.y*v.y + v.z*v.z + v.w*v.w;
        }
        enorm[k] = s;
    } else if (gi < O_W2){
        int i = gi - O_W1;                 // W1 pack [kp=392][n=256]
        int kp = i >> 8, n = i & 255;
        uint32_t hi, lo;
        fp16_split_pack(W1[(size_t)(2*kp)*256 + n], W1[(size_t)(2*kp+1)*256 + n], hi, lo);
        w1H[i] = hi; w1L[i] = lo;
    } else if (gi < O_W3){
        int i = gi - O_W2;                 // W2 pack [kp=128][n=256]
        int kp = i >> 8, n = i & 255;
        uint32_t hi, lo;
        fp16_split_pack(W2[(size_t)(2*kp)*256 + n], W2[(size_t)(2*kp+1)*256 + n], hi, lo);
        w2H[i] = hi; w2L[i] = lo;
    } else if (gi < O_EMBT){
        int i = gi - O_W3;                 // W3 padded pack [kp=128][n=128]
        int kp = i >> 7, n = i & 127;
        float x0 = 0.0f, x1 = 0.0f;
        if (n < 64){
            x0 = W3[(size_t)(2*kp)*64 + n];
            x1 = W3[(size_t)(2*kp+1)*64 + n];
        }
        uint32_t hi, lo;
        fp16_split_pack(x0, x1, hi, lo);
        w3H[i] = hi; w3L[i] = lo;
        if (i < 128) b3p[i] = (i < 64) ? b3[i] : 0.0f;
    } else if (gi < O_DW1){
        int i = gi - O_EMBT;               // embT pack [dp=32][code]
        int dp = i >> 12, c = i & (KCODES-1);
        uint32_t hi, lo;
        fp16_split_pack(emb[(size_t)c*DLAT + 2*dp], emb[(size_t)c*DLAT + 2*dp + 1], hi, lo);
        eHiT[i] = hi; eLoT[i] = lo;
    } else if (gi < O_DW2){
        int i = gi - O_DW1;                // dW1 hi pack [kp=32][n=1024]
        int kp = i >> 10, n = i & 1023;
        dW1H[i] = fp16_pack_hi(dW1[(size_t)(2*kp)*HIDDEN + n], dW1[(size_t)(2*kp+1)*HIDDEN + n]);
    } else if (gi < O_HEAD){
        int i = gi - O_DW2;                // dW2 hi pack [kp=512][n=1024]
        int kp = i >> 10, n = i & 1023;
        dW2H[i] = fp16_pack_hi(dW2[(size_t)(2*kp)*HIDDEN + n], dW2[(size_t)(2*kp+1)*HIDDEN + n]);
    } else {
        int i = gi - O_HEAD;               // head hi pack (direct) [kp=512][n=128]
        int kp = i >> 7, n = i & 127;
        float x0 = head_w(pW, wW, aW, 2*kp,   n);
        float x1 = head_w(pW, wW, aW, 2*kp+1, n);
        hwH[i] = fp16_pack_hi(x0, x1);
        if (i < 128){
            float v = 0.0f;
            if (i < 40)      v = pb[i];
            else if (i < 42) v = wb[i-40];
            else if (i < 44) v = ab[i-42];
            hb[i] = v;
        }
    }
}

// ============================================================================
// fp16-split GEMM: 3-product hi/lo. A [m][kp], B [kp][n]. BK=16.
// OUTPACK: 0 = fp32 C; 1 = packed hi/lo C;
//          2 = fp32 z (cols<64) + transposed hi/lo packs zHiT/zLoT [dp][b]
// ============================================================================
template<int ACT, int OUTPACK>
__global__ void __launch_bounds__(256, 2) mma_gemm_f16(
    const uint32_t* __restrict__ AH, const uint32_t* __restrict__ AL,
    const uint32_t* __restrict__ BH, const uint32_t* __restrict__ BL,
    const float* __restrict__ bias, float* __restrict__ C,
    uint32_t* __restrict__ CH, uint32_t* __restrict__ CL,
    int M, int N, int K)
{
    __shared__ uint32_t AsH[2][128][AKP], AsL[2][128][AKP];
    __shared__ uint32_t BsH[2][8][BNP],   BsL[2][8][BNP];

    const int tid  = threadIdx.x;
    const int lane = tid & 31, warp = tid >> 5;
    const int wm = (warp & 1) * 64, wn = (warp >> 1) * 32;
    const int bm = blockIdx.y * 128, bn = blockIdx.x * 128;
    const int g = lane >> 2, tg = lane & 3;
    const int KP = K >> 1;

    float acc[4][4][4];
    #pragma unroll
    for (int i = 0; i < 4; i++)
        #pragma unroll
        for (int j = 0; j < 4; j++)
            #pragma unroll
            for (int q = 0; q < 4; q++) acc[i][j][q] = 0.0f;

    const int ar = tid >> 1, ac = (tid & 1) * 4;
    const int br = tid >> 5, bc = lane * 4;
    const uint32_t* AHp = AH + (size_t)(bm + ar) * KP + ac;
    const uint32_t* ALp = AL + (size_t)(bm + ar) * KP + ac;
    const uint32_t* BHp = BH + (size_t)br * N + bn + bc;
    const uint32_t* BLp = BL + (size_t)br * N + bn + bc;

    const int ntiles = K >> 4;

    #define COPY_F16(kt, buf) do { \
        cpasync16(&AsH[buf][ar][ac], AHp + (size_t)(kt)*8); \
        cpasync16(&AsL[buf][ar][ac], ALp + (size_t)(kt)*8); \
        cpasync16(&BsH[buf][br][bc], BHp + (size_t)(kt)*8*N); \
        cpasync16(&BsL[buf][br][bc], BLp + (size_t)(kt)*8*N); \
        cpasync_commit(); \
    } while (0)

    COPY_F16(0, 0);

    for (int i = 0; i < ntiles; i++){
        int buf = i & 1;
        if (i + 1 < ntiles){
            COPY_F16(i + 1, buf ^ 1);
            cpasync_wait<1>();
        } else {
            cpasync_wait<0>();
        }
        __syncthreads();

        uint32_t ah[4][4], al[4][4];
        #pragma unroll
        for (int mt = 0; mt < 4; mt++){
            int m = wm + mt*16 + g;
            ah[mt][0] = AsH[buf][m  ][tg];
            ah[mt][1] = AsH[buf][m+8][tg];
            ah[mt][2] = AsH[buf][m  ][tg+4];
            ah[mt][3] = AsH[buf][m+8][tg+4];
            al[mt][0] = AsL[buf][m  ][tg];
            al[mt][1] = AsL[buf][m+8][tg];
            al[mt][2] = AsL[buf][m  ][tg+4];
            al[mt][3] = AsL[buf][m+8][tg+4];
        }
        #pragma unroll
        for (int nt = 0; nt < 4; nt++){
            int n = wn + nt*8 + g;
            uint32_t bh[2] = { BsH[buf][tg][n], BsH[buf][tg+4][n] };
            uint32_t bl[2] = { BsL[buf][tg][n], BsL[buf][tg+4][n] };
            #pragma unroll
            for (int mt = 0; mt < 4; mt++) mma16(acc[mt][nt], ah[mt], bh);
            #pragma unroll
            for (int mt = 0; mt < 4; mt++) mma16(acc[mt][nt], al[mt], bh);
            #pragma unroll
            for (int mt = 0; mt < 4; mt++) mma16(acc[mt][nt], ah[mt], bl);
        }
        __syncthreads();
    }
    #undef COPY_F16

    #pragma unroll
    for (int mt = 0; mt < 4; mt++){
        #pragma unroll
        for (int nt = 0; nt < 4; nt++){
            int row = bm + wm + mt*16 + g;
            int col = bn + wn + nt*8 + 2*tg;
            float bs0 = bias[col], bs1 = bias[col+1];
            float v00 = apply_act<ACT>(acc[mt][nt][0] + bs0, col);
            float v01 = apply_act<ACT>(acc[mt][nt][1] + bs1, col+1);
            float v10 = apply_act<ACT>(acc[mt][nt][2] + bs0, col);
            float v11 = apply_act<ACT>(acc[mt][nt][3] + bs1, col+1);
            if (OUTPACK == 1){
                int w = col >> 1;
                int NP = N >> 1;
                uint32_t h0, l0, h1, l1;
                fp16_split_pack(v00, v01, h0, l0);
                fp16_split_pack(v10, v11, h1, l1);
                CH[(size_t)row*NP + w]     = h0;
                CL[(size_t)row*NP + w]     = l0;
                CH[(size_t)(row+8)*NP + w] = h1;
                CL[(size_t)(row+8)*NP + w] = l1;
            } else if (OUTPACK == 2){
                if (col < DLAT){
                    *(float2*)&C[(size_t)row*DLAT + col]     = make_float2(v00, v01);
                    *(float2*)&C[(size_t)(row+8)*DLAT + col] = make_float2(v10, v11);
                    int dp = col >> 1;
                    uint32_t h0, l0, h1, l1;
                    fp16_split_pack(v00, v01, h0, l0);
                    fp16_split_pack(v10, v11, h1, l1);
                    CH[(size_t)dp*BATCH + row]     = h0;
                    CL[(size_t)dp*BATCH + row]     = l0;
                    CH[(size_t)dp*BATCH + row + 8] = h1;
                    CL[(size_t)dp*BATCH + row + 8] = l1;
                }
            } else {
                *(float2*)&C[(size_t)row*N + col]     = make_float2(v00, v01);
                *(float2*)&C[(size_t)(row+8)*N + col] = make_float2(v10, v11);
            }
        }
    }
}

// ============================================================================
// fp16 hi-only GEMM (decoder + head): 1-product, BK=32.
// OUTPACK: 0 = fp32 C; 1 = packed hi C; 3 = fused output packing (head)
// ============================================================================
template<int ACT, int OUTPACK>
__global__ void __launch_bounds__(256, 2) mma_gemm_h16(
    const uint32_t* __restrict__ AH, const uint32_t* __restrict__ BH,
    const float* __restrict__ bias, float* __restrict__ C,
    uint32_t* __restrict__ CH,
    int M, int N, int K)
{
    __shared__ uint32_t AsH[2][128][AKP2];
    __shared__ uint32_t BsH[2][16][BNP];

    const int tid  = threadIdx.x;
    const int lane = tid & 31, warp = tid >> 5;
    const int wm = (warp & 1) * 64, wn = (warp >> 1) * 32;
    const int bm = blockIdx.y * 128, bn = blockIdx.x * 128;
    const int g = lane >> 2, tg = lane & 3;
    const int KP = K >> 1;

    float acc[4][4][4];
    #pragma unroll
    for (int i = 0; i < 4; i++)
        #pragma unroll
        for (int j = 0; j < 4; j++)
            #pragma unroll
            for (int q = 0; q < 4; q++) acc[i][j][q] = 0.0f;

    const int ar = tid >> 1, ac = (tid & 1) * 8;
    const int br = tid >> 4, bc = (tid & 15) * 8;
    const uint32_t* AHp = AH + (size_t)(bm + ar) * KP + ac;
    const uint32_t* BHp = BH + (size_t)br * N + bn + bc;

    const int ntiles = K >> 5;   // 16 kp per tile

    #define COPY_H16(kt, buf) do { \
        cpasync16(&AsH[buf][ar][ac],   AHp + (size_t)(kt)*16); \
        cpasync16(&AsH[buf][ar][ac+4], AHp + (size_t)(kt)*16 + 4); \
        cpasync16(&BsH[buf][br][bc],   BHp + (size_t)(kt)*16*N); \
        cpasync16(&BsH[buf][br][bc+4], BHp + (size_t)(kt)*16*N + 4); \
        cpasync_commit(); \
    } while (0)

    COPY_H16(0, 0);

    for (int i = 0; i < ntiles; i++){
        int buf = i & 1;
        if (i + 1 < ntiles){
            COPY_H16(i + 1, buf ^ 1);
            cpasync_wait<1>();
        } else {
            cpasync_wait<0>();
        }
        __syncthreads();

        #pragma unroll
        for (int kb = 0; kb < 2; kb++){
            uint32_t ah[4][4];
            #pragma unroll
            for (int mt = 0; mt < 4; mt++){
                int m = wm + mt*16 + g;
                ah[mt][0] = AsH[buf][m  ][kb*8+tg];
                ah[mt][1] = AsH[buf][m+8][kb*8+tg];
                ah[mt][2] = AsH[buf][m  ][kb*8+tg+4];
                ah[mt][3] = AsH[buf][m+8][kb*8+tg+4];
            }
            #pragma unroll
            for (int nt = 0; nt < 4; nt++){
                int n = wn + nt*8 + g;
                uint32_t bh[2] = { BsH[buf][kb*8+tg][n], BsH[buf][kb*8+tg+4][n] };
                #pragma unroll
                for (int mt = 0; mt < 4; mt++) mma16(acc[mt][nt], ah[mt], bh);
            }
        }
        __syncthreads();
    }
    #undef COPY_H16

    #pragma unroll
    for (int mt = 0; mt < 4; mt++){
        #pragma unroll
        for (int nt = 0; nt < 4; nt++){
            int row = bm + wm + mt*16 + g;
            int col = bn + wn + nt*8 + 2*tg;
            float bs0 = bias[col], bs1 = bias[col+1];
            float v00 = apply_act<ACT>(acc[mt][nt][0] + bs0, col);
            float v01 = apply_act<ACT>(acc[mt][nt][1] + bs1, col+1);
            float v10 = apply_act<ACT>(acc[mt][nt][2] + bs0, col);
            float v11 = apply_act<ACT>(acc[mt][nt][3] + bs1, col+1);
            if (OUTPACK == 1){
                int w = col >> 1;
                int NP = N >> 1;
                CH[(size_t)row*NP + w]     = fp16_pack_hi(v00, v01);
                CH[(size_t)(row+8)*NP + w] = fp16_pack_hi(v10, v11);
            } else if (OUTPACK == 3){
                // fused output packing (head): col even, valid cols < 44
                if (col < 40){
                    int p = col / 20, rem = col - p*20;
                    int q = rem >> 1;
                    *(float2*)&C[P_OFF + (size_t)row*40 + col]     = make_float2(v00, v01);
                    *(float2*)&C[P_OFF + (size_t)(row+8)*40 + col] = make_float2(v10, v11);
                    #pragma unroll
                    for (int sg = 0; sg < 3; sg++){
                        int j = q - 3*sg;
                        if (j >= 0 && j < 4){
                            size_t o = (size_t)p*24 + sg*8 + j*2;
                            *(float2*)&C[CP_OFF + (size_t)row*48 + o]     = make_float2(v00, v01);
                            *(float2*)&C[CP_OFF + (size_t)(row+8)*48 + o] = make_float2(v10, v11);
                        }
                    }
                } else if (col == 40){
                    *(float2*)&C[W_OFF + (size_t)row*2]     = make_float2(v00, v01);
                    *(float2*)&C[W_OFF + (size_t)(row+8)*2] = make_float2(v10, v11);
                } else if (col == 42){
                    *(float2*)&C[A_OFF + (size_t)row*2]     = make_float2(v00, v01);
                    *(float2*)&C[A_OFF + (size_t)(row+8)*2] = make_float2(v10, v11);
                }
            } else {
                *(float2*)&C[(size_t)row*N + col]     = make_float2(v00, v01);
                *(float2*)&C[(size_t)(row+8)*N + col] = make_float2(v10, v11);
            }
        }
    }
}

// ---------------- VQ argmin: fp16-split m16n8k16, pre-packed operands ----------------
__global__ void __launch_bounds__(256, 2) vq_argmin_f16(
    const uint32_t* __restrict__ zHiT, const uint32_t* __restrict__ zLoT,
    const uint32_t* __restrict__ eHiT, const uint32_t* __restrict__ eLoT,
    const float* __restrict__ enorm, int* __restrict__ idx_out)
{
    __shared__ uint32_t ZH[32][HS], ZL[32][HS];
    __shared__ uint32_t EH[2][32][HS], EL[2][32][HS];

    const int tid  = threadIdx.x;
    const int lane = tid & 31, warp = tid >> 5;
    const int wm = (warp & 1) * 64, wn = (warp >> 1) * 32;
    const int bm = blockIdx.x * 128;
    const int g = lane >> 2, tg = lane & 3;

    {
        #pragma unroll
        for (int j = 0; j < 4; j++){
            int unit = j*256 + tid;
            int dp = unit >> 5, u = unit & 31;
            cpasync16(&ZH[dp][u*4], zHiT + (size_t)dp*BATCH + bm + u*4);
            cpasync16(&ZL[dp][u*4], zLoT + (size_t)dp*BATCH + bm + u*4);
        }
        cpasync_commit();
    }

    #define COPY_EP(c0_, buf_) do { \
        _Pragma("unroll") \
        for (int j = 0; j < 4; j++){ \
            int unit = j*256 + tid; \
            int dp_ = unit >> 5, u_ = unit & 31; \
            cpasync16(&EH[buf_][dp_][u_*4], eHiT + (size_t)dp_*KCODES + (c0_) + u_*4); \
            cpasync16(&EL[buf_][dp_][u_*4], eLoT + (size_t)dp_*KCODES + (c0_) + u_*4); \
        } \
        cpasync_commit(); \
    } while (0)

    float mv[8]; int mi[8];
    #pragma unroll
    for (int s = 0; s < 8; s++){ mv[s] = INFINITY; mi[s] = 0; }

    COPY_EP(0, 0);

    for (int ch = 0; ch < KCODES/128; ch++){
        int c0 = ch * 128;
        int buf = ch & 1;
        if (ch + 1 < KCODES/128){
            COPY_EP(c0 + 128, buf ^ 1);
            cpasync_wait<1>();
        } else {
            cpasync_wait<0>();
        }
        __syncthreads();

        float acc[4][4][4];
        #pragma unroll
        for (int i = 0; i < 4; i++)
            #pragma unroll
            for (int j = 0; j < 4; j++)
                #pragma unroll
                for (int q = 0; q < 4; q++) acc[i][j][q] = 0.0f;

        #pragma unroll
        for (int kb = 0; kb < 4; kb++){
            uint32_t ah[4][4], al[4][4];
            #pragma unroll
            for (int mt = 0; mt < 4; mt++){
                int m = wm + mt*16 + g;
                ah[mt][0] = ZH[kb*8+tg  ][m];
                ah[mt][1] = ZH[kb*8+tg  ][m+8];
                ah[mt][2] = ZH[kb*8+tg+4][m];
                ah[mt][3] = ZH[kb*8+tg+4][m+8];
                al[mt][0] = ZL[kb*8+tg  ][m];
                al[mt][1] = ZL[kb*8+tg  ][m+8];
                al[mt][2] = ZL[kb*8+tg+4][m];
                al[mt][3] = ZL[kb*8+tg+4][m+8];
            }
            #pragma unroll
            for (int nt = 0; nt < 4; nt++){
                int n = wn + nt*8 + g;
                uint32_t bh[2] = { EH[buf][kb*8+tg][n], EH[buf][kb*8+tg+4][n] };
                uint32_t bl[2] = { EL[buf][kb*8+tg][n], EL[buf][kb*8+tg+4][n] };
                #pragma unroll
                for (int mt = 0; mt < 4; mt++) mma16(acc[mt][nt], ah[mt], bh);
                #pragma unroll
                for (int mt = 0; mt < 4; mt++) mma16(acc[mt][nt], al[mt], bh);
                #pragma unroll
                for (int mt = 0; mt < 4; mt++) mma16(acc[mt][nt], ah[mt], bl);
            }
        }

        #pragma unroll
        for (int nt = 0; nt < 4; nt++){
            int nc = wn + nt*8 + 2*tg;
            float e0 = __ldg(enorm + c0 + nc);
            float e1 = __ldg(enorm + c0 + nc + 1);
            int code = c0 + nc;
            #pragma unroll
            for (int mt = 0; mt < 4; mt++){
                float d00 = e0 - 2.0f*acc[mt][nt][0];
                float d01 = e1 - 2.0f*acc[mt][nt][1];
                float d10 = e0 - 2.0f*acc[mt][nt][2];
                float d11 = e1 - 2.0f*acc[mt][nt][3];
                int s0 = mt*2, s1 = mt*2 + 1;
                if (d00 < mv[s0]){ mv[s0] = d00; mi[s0] = code;   }
                if (d01 < mv[s0]){ mv[s0] = d01; mi[s0] = code+1; }
                if (d10 < mv[s1]){ mv[s1] = d10; mi[s1] = code;   }
                if (d11 < mv[s1]){ mv[s1] = d11; mi[s1] = code+1; }
            }
        }
        __syncthreads();
    }
    #undef COPY_EP

    float* rv = (float*)&EH[0][0][0];
    int*   ri = ((int*)rv) + 16*128;
    int cand = (warp >> 1) * 4 + tg;
    #pragma unroll
    for (int s = 0; s < 8; s++){
        int r = wm + (s >> 1)*16 + g + (s & 1)*8;
        rv[cand*128 + r] = mv[s];
        ri[cand*128 + r] = mi[s];
    }
    __syncthreads();
    if (tid < 128){
        float bv = INFINITY; int bi = 0x7fffffff;
        #pragma unroll
        for (int t = 0; t < 16; t++){
            float v = rv[t*128 + tid];
            int c = ri[t*128 + tid];
            if (v < bv || (v == bv && c < bi)){ bv = v; bi = c; }
        }
        idx_out[bm + tid] = bi;
    }
}

// ---------------- gather: packed fp16 zq, idx-as-float, counts, commit-loss ----------------
__global__ void vq_post(const float* __restrict__ z, const float* __restrict__ emb,
                        const int* __restrict__ idx, uint32_t* __restrict__ zqH,
                        float* __restrict__ counts, float* __restrict__ loss,
                        float* __restrict__ out_idx)
{
    int b = blockIdx.x * 256 + threadIdx.x;
    int k = idx[b];
    const float4* e  = (const float4*)(emb + (size_t)k * DLAT);
    const float4* zz = (const float4*)(z   + (size_t)b * DLAT);
    uint32_t*     zo = zqH + (size_t)b * 32;
    float s = 0.0f;
    #pragma unroll
    for (int q = 0; q < 16; q++){
        float4 ev = e[q], zv = zz[q];
        float dx = ev.x - zv.x, dy = ev.y - zv.y, dz = ev.z - zv.z, dw = ev.w - zv.w;
        s += dx*dx + dy*dy + dz*dz + dw*dw;
        zo[q*2]   = fp16_pack_hi(ev.x, ev.y);
        zo[q*2+1] = fp16_pack_hi(ev.z, ev.w);
    }
    out_idx[b] = (float)k;
    atomicAdd(&counts[k], 1.0f);

    __shared__ float red[256];
    red[threadIdx.x] = s;
    __syncthreads();
    for (int off = 128; off > 0; off >>= 1){
        if (threadIdx.x < off) red[threadIdx.x] += red[threadIdx.x + off];
        __syncthreads();
    }
    if (threadIdx.x == 0) atomicAdd(loss, red[0]);
}

// ---------------- perplexity + vq_loss scalars ----------------
__global__ void finalize_kernel(const float* __restrict__ counts, const float* __restrict__ loss,
                                float* __restrict__ out)
{
    __shared__ float red[256];
    float s = 0.0f;
    for (int k = threadIdx.x; k < KCODES; k += 256){
        float p = counts[k] * (1.0f / (float)BATCH);
        s += p * logf(p + 1e-10f);
    }
    red[threadIdx.x] = s;
    __syncthreads();
    for (int off = 128; off > 0; off >>= 1){
        if (threadIdx.x < off) red[threadIdx.x] += red[threadIdx.x + off];
        __syncthreads();
    }
    if (threadIdx.x == 0){
        out[PERP_OFF] = expf(-red[0]);
        out[LOSS_OFF] = loss[0] * (0.25f / ((float)BATCH * (float)DLAT));
    }
}

// ---------------- launch ----------------
extern "C" void kernel_launch(void* const* d_in, const int* in_sizes, int n_in,
                              void* d_out, int out_size)
{
    (void)in_sizes; (void)n_in; (void)out_size;
    const float* x   = (const float*)d_in[0];
    const float* W1  = (const float*)d_in[1];
    const float* b1  = (const float*)d_in[2];
    const float* W2  = (const float*)d_in[3];
    const float* b2  = (const float*)d_in[4];
    const float* W3  = (const float*)d_in[5];
    const float* b3  = (const float*)d_in[6];
    const float* emb = (const float*)d_in[7];
    const float* dW1 = (const float*)d_in[8];
    const float* db1 = (const float*)d_in[9];
    const float* dW2 = (const float*)d_in[10];
    const float* db2 = (const float*)d_in[11];
    const float* pW  = (const float*)d_in[12];
    const float* pb  = (const float*)d_in[13];
    const float* wW  = (const float*)d_in[14];
    const float* wb  = (const float*)d_in[15];
    const float* aW  = (const float*)d_in[16];
    const float* ab  = (const float*)d_in[17];
    float* out = (float*)d_out;

    float *z, *counts, *loss, *enorm, *hb, *b3p;
    uint32_t *xH, *xL, *w1H, *w1L, *h1H, *h1L, *w2H, *w2L, *h2H, *h2L, *w3H, *w3L;
    uint32_t *zHiT, *zLoT, *eHiT, *eLoT;
    uint32_t *zqH, *dW1H, *d1H, *dW2H, *d2H, *hwH;
    int* idx;
    cudaGetSymbolAddress((void**)&z,  g_z);
    cudaGetSymbolAddress((void**)&idx, g_idx);
    cudaGetSymbolAddress((void**)&counts, g_counts);
    cudaGetSymbolAddress((void**)&loss, g_loss);
    cudaGetSymbolAddress((void**)&enorm, g_enorm);
    cudaGetSymbolAddress((void**)&hb, g_hb);
    cudaGetSymbolAddress((void**)&b3p, g_b3p);
    cudaGetSymbolAddress((void**)&xH, g_xH);
    cudaGetSymbolAddress((void**)&xL, g_xL);
    cudaGetSymbolAddress((void**)&w1H, g_w1H);
    cudaGetSymbolAddress((void**)&w1L, g_w1L);
    cudaGetSymbolAddress((void**)&h1H, g_h1H);
    cudaGetSymbolAddress((void**)&h1L, g_h1L);
    cudaGetSymbolAddress((void**)&w2H, g_w2H);
    cudaGetSymbolAddress((void**)&w2L, g_w2L);
    cudaGetSymbolAddress((void**)&h2H, g_h2H);
    cudaGetSymbolAddress((void**)&h2L, g_h2L);
    cudaGetSymbolAddress((void**)&w3H, g_w3H);
    cudaGetSymbolAddress((void**)&w3L, g_w3L);
    cudaGetSymbolAddress((void**)&zHiT, g_zHiT);
    cudaGetSymbolAddress((void**)&zLoT, g_zLoT);
    cudaGetSymbolAddress((void**)&eHiT, g_eHiT);
    cudaGetSymbolAddress((void**)&eLoT, g_eLoT);
    cudaGetSymbolAddress((void**)&zqH,  g_zqH);
    cudaGetSymbolAddress((void**)&dW1H, g_dW1H);
    cudaGetSymbolAddress((void**)&d1H,  g_d1H);
    cudaGetSymbolAddress((void**)&dW2H, g_dW2H);
    cudaGetSymbolAddress((void**)&d2H,  g_d2H);
    cudaGetSymbolAddress((void**)&hwH,  g_hwH);

    // setup: one mega kernel (all weight packs + scalars) + wide x pack
    mega_setup<<<(S_TOTAL + 255)/256, 256>>>(
        W1, W2, W3, b3, emb, dW1, dW2, pW, pb, wW, wb, aW, ab,
        counts, loss, enorm, b3p, hb,
        w1H, w1L, w2H, w2L, w3H, w3L, eHiT, eLoT, dW1H, dW2H, hwH);
    pack_rowsA4<<<(BATCH*196 + 255)/256, 256>>>(x, xH, xL, BATCH*196);

    // encoder (fp16-split 3-product)
    mma_gemm_f16<ACT_LEAKY, 1><<<dim3(2, BATCH/128), 256>>>(
        xH, xL, w1H, w1L, b1, nullptr, h1H, h1L, BATCH, 256, 784);
    mma_gemm_f16<ACT_LEAKY, 1><<<dim3(2, BATCH/128), 256>>>(
        h1H, h1L, w2H, w2L, b2, nullptr, h2H, h2L, BATCH, 256, 256);
    // z projection: fp16-split MMA, fused fp32 z + transposed hi/lo packs
    mma_gemm_f16<ACT_NONE, 2><<<dim3(1, BATCH/128), 256>>>(
        h2H, h2L, w3H, w3L, b3p, z, zHiT, zLoT, BATCH, 128, 256);

    // VQ
    vq_argmin_f16<<<BATCH/128, 256>>>(zHiT, zLoT, eHiT, eLoT, enorm, idx);
    vq_post<<<BATCH/256, 256>>>(z, emb, idx, zqH, counts, loss, out + IDX_OFF);
    finalize_kernel<<<1, 256>>>(counts, loss, out);

    // decoder (fp16 hi-only 1-product, BK=32)
    mma_gemm_h16<ACT_SELU, 1><<<dim3(HIDDEN/128, BATCH/128), 256>>>(
        zqH, dW1H, db1, nullptr, d1H, BATCH, HIDDEN, DLAT);
    mma_gemm_h16<ACT_SELU, 1><<<dim3(HIDDEN/128, BATCH/128), 256>>>(
        d1H, dW2H, db2, nullptr, d2H, BATCH, HIDDEN, HIDDEN);

    // head (fp16 hi-only, fused output packing straight into out)
    mma_gemm_h16<ACT_HEAD, 3><<<dim3(1, BATCH/128), 256>>>(
        d2H, hwH, hb, out, nullptr, BATCH, 128, HIDDEN);
}